// round 1
// baseline (speedup 1.0000x reference)
#include <cuda_runtime.h>
#include <math.h>

// Problem dims
#define B_      4
#define S_      1024
#define E_      1024
#define NHEADS  16
#define H_      64
#define NH_     1024      // NHEADS*H_
#define F_      4096
#define R_      2048      // 2*S_

// ---------------- scratch (static device globals; no allocation) ----------------
__device__ float g_q[4194304];        // [B,S,NH]   16MB
__device__ float g_k[4194304];        // [B,S,NH]   16MB
__device__ float g_v[4194304];        // [B,S,NH]   16MB
__device__ float g_r[8388608];        // [B,R,NH]   32MB
__device__ float g_scores[67108864];  // [B,N,S,S] 256MB
__device__ float g_attn[4194304];     // [B,S,NH]   16MB
__device__ float g_h1[4194304];       // [B,S,E]    16MB
__device__ float g_inner[16777216];   // [B,S,F]    64MB
__device__ float g_tmp[4194304];      // [B,S,E]    16MB

// ---------------- generic tiled SGEMM: C = A(MxK) * B(KxN) (+bias, relu) --------
// 128x128 tile, K-step 8, 256 threads, each thread 8x8.
// Batched via blockIdx.z: offset = (z/zdiv)*s1 + (z%zdiv)*s2 per operand.
__global__ __launch_bounds__(256) void sgemm_k(
    const float* __restrict__ A, const float* __restrict__ Bm, float* __restrict__ C,
    const float* __restrict__ bias,
    int M, int N, int K, int lda, int ldb, int ldc,
    int zdiv, long long As1, long long As2, long long Bs1, long long Bs2,
    long long Cs1, long long Cs2, int relu)
{
    int z = blockIdx.z;
    int zq = z / zdiv, zr = z % zdiv;
    A  += zq * As1 + zr * As2;
    Bm += zq * Bs1 + zr * Bs2;
    C  += zq * Cs1 + zr * Cs2;

    __shared__ float As[8][128];
    __shared__ float Bs[8][132];

    int bm = blockIdx.y * 128, bn = blockIdx.x * 128;
    int t = threadIdx.x;
    int tx = t & 15, ty = t >> 4;

    float acc[8][8];
#pragma unroll
    for (int i = 0; i < 8; i++)
#pragma unroll
        for (int j = 0; j < 8; j++) acc[i][j] = 0.f;

    int arow = t >> 1, akk = (t & 1) * 4;     // A tile: row in [0,128), k chunk
    int brow = t >> 5, bcol = (t & 31) * 4;   // B tile: k row in [0,8), col chunk

    for (int k0 = 0; k0 < K; k0 += 8) {
        float4 av = make_float4(0.f, 0.f, 0.f, 0.f);
        if (bm + arow < M)
            av = *(const float4*)(A + (long long)(bm + arow) * lda + k0 + akk);
        As[akk + 0][arow] = av.x;
        As[akk + 1][arow] = av.y;
        As[akk + 2][arow] = av.z;
        As[akk + 3][arow] = av.w;

        float4 bv = make_float4(0.f, 0.f, 0.f, 0.f);
        if (bn + bcol < N)
            bv = *(const float4*)(Bm + (long long)(k0 + brow) * ldb + bn + bcol);
        *(float4*)&Bs[brow][bcol] = bv;

        __syncthreads();
#pragma unroll
        for (int kk = 0; kk < 8; kk++) {
            float4 a0 = *(float4*)&As[kk][ty * 8];
            float4 a1 = *(float4*)&As[kk][ty * 8 + 4];
            float4 b0 = *(float4*)&Bs[kk][tx * 8];
            float4 b1 = *(float4*)&Bs[kk][tx * 8 + 4];
            float a[8] = {a0.x, a0.y, a0.z, a0.w, a1.x, a1.y, a1.z, a1.w};
            float b[8] = {b0.x, b0.y, b0.z, b0.w, b1.x, b1.y, b1.z, b1.w};
#pragma unroll
            for (int i = 0; i < 8; i++)
#pragma unroll
                for (int j = 0; j < 8; j++)
                    acc[i][j] = fmaf(a[i], b[j], acc[i][j]);
        }
        __syncthreads();
    }

#pragma unroll
    for (int i = 0; i < 8; i++) {
        int m = bm + ty * 8 + i;
        if (m >= M) continue;
#pragma unroll
        for (int j = 0; j < 8; j++) {
            int n = bn + tx * 8 + j;
            if (n >= N) continue;
            float vv = acc[i][j];
            if (bias) vv += bias[n];
            if (relu) vv = fmaxf(vv, 0.f);
            C[(long long)m * ldc + n] = vv;
        }
    }
}

// ---------------- fused content+position attention scores ----------------------
// scores[b,n,i,j] = ( sum_h K[j,h]*(Q[i,h]+cb) + sum_h Rr[S+j-i,h]*(Q[i,h]+pb) ) / 8
// 64x64 output tile per block; 256 threads, each 4x4.
#define SC_SMEM ((64 * 68 + 128 * 68) * 4)
__global__ __launch_bounds__(256) void scores_k(
    const float* __restrict__ q, const float* __restrict__ k,
    const float* __restrict__ r, const float* __restrict__ cb,
    const float* __restrict__ pb, float* __restrict__ sc)
{
    extern __shared__ float sm[];
    float* smQ = sm;             // [64][68]
    float* smB = sm + 64 * 68;   // [128][68]

    const int z = blockIdx.z;
    const int b = z >> 4, n = z & 15;
    const int i0 = blockIdx.y * 64, j0 = blockIdx.x * 64;

    const float* qb = q + (long long)b * S_ * NH_ + n * H_;
    const float* kb = k + (long long)b * S_ * NH_ + n * H_;
    const float* rb = r + (long long)b * R_ * NH_ + n * H_;

    int t = threadIdx.x;
    int tx = t & 15, ty = t >> 4;
    float acc[4][4];
#pragma unroll
    for (int i = 0; i < 4; i++)
#pragma unroll
        for (int j = 0; j < 4; j++) acc[i][j] = 0.f;

    // ---- pass 1: content ----
#pragma unroll
    for (int rep = 0; rep < 4; rep++) {
        int idx = t + rep * 256;
        int row = idx >> 4, c = (idx & 15) << 2;
        float4 cv = *(const float4*)(cb + n * H_ + c);
        float4 qv = *(const float4*)(qb + (long long)(i0 + row) * NH_ + c);
        smQ[row * 68 + c + 0] = qv.x + cv.x;
        smQ[row * 68 + c + 1] = qv.y + cv.y;
        smQ[row * 68 + c + 2] = qv.z + cv.z;
        smQ[row * 68 + c + 3] = qv.w + cv.w;
        float4 kv = *(const float4*)(kb + (long long)(j0 + row) * NH_ + c);
        *(float4*)&smB[row * 68 + c] = kv;
    }
    __syncthreads();
#pragma unroll 8
    for (int h = 0; h < 64; h++) {
        float a[4], bb[4];
#pragma unroll
        for (int i = 0; i < 4; i++) a[i] = smQ[(ty * 4 + i) * 68 + h];
#pragma unroll
        for (int j = 0; j < 4; j++) bb[j] = smB[(tx * 4 + j) * 68 + h];
#pragma unroll
        for (int i = 0; i < 4; i++)
#pragma unroll
            for (int j = 0; j < 4; j++)
                acc[i][j] = fmaf(a[i], bb[j], acc[i][j]);
    }
    __syncthreads();

    // ---- pass 2: position (rel-shift folded: r index = S + j - i) ----
#pragma unroll
    for (int rep = 0; rep < 4; rep++) {
        int idx = t + rep * 256;
        int row = idx >> 4, c = (idx & 15) << 2;
        float4 pv = *(const float4*)(pb + n * H_ + c);
        float4 qv = *(const float4*)(qb + (long long)(i0 + row) * NH_ + c);
        smQ[row * 68 + c + 0] = qv.x + pv.x;
        smQ[row * 68 + c + 1] = qv.y + pv.y;
        smQ[row * 68 + c + 2] = qv.z + pv.z;
        smQ[row * 68 + c + 3] = qv.w + pv.w;
    }
    int base = S_ + j0 - i0 - 63;  // band rows base; offset = 63 + jj - ii in [0,126]
#pragma unroll
    for (int rep = 0; rep < 8; rep++) {
        int idx = t + rep * 256;
        int row = idx >> 4, c = (idx & 15) << 2;
        int g = base + row;
        float4 rv = make_float4(0.f, 0.f, 0.f, 0.f);
        if (g >= 0 && g < R_)
            rv = *(const float4*)(rb + (long long)g * NH_ + c);
        *(float4*)&smB[row * 68 + c] = rv;
    }
    __syncthreads();
#pragma unroll 4
    for (int h = 0; h < 64; h++) {
        float a[4];
#pragma unroll
        for (int i = 0; i < 4; i++) a[i] = smQ[(ty * 4 + i) * 68 + h];
#pragma unroll
        for (int i = 0; i < 4; i++) {
            int ii = ty * 4 + i;
#pragma unroll
            for (int j = 0; j < 4; j++) {
                int jj = tx * 4 + j;
                acc[i][j] = fmaf(a[i], smB[(63 + jj - ii) * 68 + h], acc[i][j]);
            }
        }
    }

    float* o = sc + (long long)z * S_ * S_;
#pragma unroll
    for (int i = 0; i < 4; i++) {
        int gi = i0 + ty * 4 + i;
#pragma unroll
        for (int j = 0; j < 4; j++)
            o[(long long)gi * S_ + j0 + tx * 4 + j] = acc[i][j] * 0.125f;
    }
}

// ---------------- row softmax over 1024 (in place) ------------------------------
__global__ __launch_bounds__(256) void softmax_k(float* __restrict__ sc)
{
    __shared__ float red[8];
    long long row = blockIdx.x;
    float* p = sc + row * 1024;
    int t = threadIdx.x;
    float4 v = *((float4*)p + t);
    float m = fmaxf(fmaxf(v.x, v.y), fmaxf(v.z, v.w));
#pragma unroll
    for (int o = 16; o; o >>= 1) m = fmaxf(m, __shfl_xor_sync(0xffffffffu, m, o));
    if ((t & 31) == 0) red[t >> 5] = m;
    __syncthreads();
    if (t == 0) {
        float mm = red[0];
#pragma unroll
        for (int i = 1; i < 8; i++) mm = fmaxf(mm, red[i]);
        red[0] = mm;
    }
    __syncthreads();
    m = red[0];
    v.x = expf(v.x - m); v.y = expf(v.y - m);
    v.z = expf(v.z - m); v.w = expf(v.w - m);
    float s = v.x + v.y + v.z + v.w;
#pragma unroll
    for (int o = 16; o; o >>= 1) s += __shfl_xor_sync(0xffffffffu, s, o);
    __syncthreads();
    if ((t & 31) == 0) red[t >> 5] = s;
    __syncthreads();
    if (t == 0) {
        float ss = red[0];
#pragma unroll
        for (int i = 1; i < 8; i++) ss += red[i];
        red[0] = ss;
    }
    __syncthreads();
    float inv = 1.0f / red[0];
    v.x *= inv; v.y *= inv; v.z *= inv; v.w *= inv;
    *((float4*)p + t) = v;
}

// ---------------- fused residual-add + LayerNorm over E=1024 --------------------
__global__ __launch_bounds__(256) void ln_k(
    const float* __restrict__ a, const float* __restrict__ res,
    const float* __restrict__ g, const float* __restrict__ bt,
    float* __restrict__ o)
{
    __shared__ float red[16];
    long long row = blockIdx.x;
    int t = threadIdx.x;
    float4 va = *((const float4*)(a + row * 1024) + t);
    float4 vr = *((const float4*)(res + row * 1024) + t);
    float4 x;
    x.x = va.x + vr.x; x.y = va.y + vr.y; x.z = va.z + vr.z; x.w = va.w + vr.w;
    float s  = x.x + x.y + x.z + x.w;
    float q2 = x.x * x.x + x.y * x.y + x.z * x.z + x.w * x.w;
#pragma unroll
    for (int off = 16; off; off >>= 1) {
        s  += __shfl_xor_sync(0xffffffffu, s, off);
        q2 += __shfl_xor_sync(0xffffffffu, q2, off);
    }
    if ((t & 31) == 0) { red[t >> 5] = s; red[8 + (t >> 5)] = q2; }
    __syncthreads();
    if (t == 0) {
        float ss = red[0], qq = red[8];
#pragma unroll
        for (int i = 1; i < 8; i++) { ss += red[i]; qq += red[8 + i]; }
        red[0] = ss; red[8] = qq;
    }
    __syncthreads();
    float mu  = red[0] * (1.f / 1024.f);
    float var = red[8] * (1.f / 1024.f) - mu * mu;
    float rs = rsqrtf(var + 1e-12f);
    float4 gg = *((const float4*)g + t);
    float4 bb = *((const float4*)bt + t);
    float4 y;
    y.x = (x.x - mu) * rs * gg.x + bb.x;
    y.y = (x.y - mu) * rs * gg.y + bb.y;
    y.z = (x.z - mu) * rs * gg.z + bb.z;
    y.w = (x.w - mu) * rs * gg.w + bb.w;
    *((float4*)(o + row * 1024) + t) = y;
}

// ---------------- driver --------------------------------------------------------
extern "C" void kernel_launch(void* const* d_in, const int* in_sizes, int n_in,
                              void* d_out, int out_size)
{
    const float* x    = (const float*)d_in[0];
    const float* cb   = (const float*)d_in[1];
    const float* pb   = (const float*)d_in[2];
    const float* rpe  = (const float*)d_in[3];
    const float* Wq   = (const float*)d_in[4];
    const float* Wk   = (const float*)d_in[5];
    const float* Wv   = (const float*)d_in[6];
    const float* Wr   = (const float*)d_in[7];
    const float* Wo   = (const float*)d_in[8];
    const float* ln1g = (const float*)d_in[9];
    const float* ln1b = (const float*)d_in[10];
    const float* Wi   = (const float*)d_in[11];
    const float* bi   = (const float*)d_in[12];
    const float* Wout = (const float*)d_in[13];
    const float* bout = (const float*)d_in[14];
    const float* ln2g = (const float*)d_in[15];
    const float* ln2b = (const float*)d_in[16];
    float* out = (float*)d_out;

    float *q, *k, *v, *r, *sc, *attn, *h1, *inner, *tmp;
    cudaGetSymbolAddress((void**)&q,     g_q);
    cudaGetSymbolAddress((void**)&k,     g_k);
    cudaGetSymbolAddress((void**)&v,     g_v);
    cudaGetSymbolAddress((void**)&r,     g_r);
    cudaGetSymbolAddress((void**)&sc,    g_scores);
    cudaGetSymbolAddress((void**)&attn,  g_attn);
    cudaGetSymbolAddress((void**)&h1,    g_h1);
    cudaGetSymbolAddress((void**)&inner, g_inner);
    cudaGetSymbolAddress((void**)&tmp,   g_tmp);

    const int M = B_ * S_;  // 4096
    dim3 blk(256);

    // Q, K, V, R projections
    sgemm_k<<<dim3(8, 32, 1), blk>>>(x,   Wq, q, nullptr, M,    NH_, E_, E_, NH_, NH_,
                                     1, 0, 0, 0, 0, 0, 0, 0);
    sgemm_k<<<dim3(8, 32, 1), blk>>>(x,   Wk, k, nullptr, M,    NH_, E_, E_, NH_, NH_,
                                     1, 0, 0, 0, 0, 0, 0, 0);
    sgemm_k<<<dim3(8, 32, 1), blk>>>(x,   Wv, v, nullptr, M,    NH_, E_, E_, NH_, NH_,
                                     1, 0, 0, 0, 0, 0, 0, 0);
    sgemm_k<<<dim3(8, 64, 1), blk>>>(rpe, Wr, r, nullptr, B_ * R_, NH_, E_, E_, NH_, NH_,
                                     1, 0, 0, 0, 0, 0, 0, 0);

    // fused content+position scores (rel-shift folded into indexing)
    cudaFuncSetAttribute(scores_k, cudaFuncAttributeMaxDynamicSharedMemorySize, SC_SMEM);
    scores_k<<<dim3(16, 16, B_ * NHEADS), blk, SC_SMEM>>>(q, k, r, cb, pb, sc);

    // softmax rows
    softmax_k<<<B_ * NHEADS * S_, 256>>>(sc);

    // attn = P @ V, batched over (b, n)
    sgemm_k<<<dim3(1, 8, B_ * NHEADS), blk>>>(
        sc, v, attn, nullptr, S_, H_, S_, S_, NH_, NH_,
        NHEADS,
        (long long)NHEADS * S_ * S_, (long long)S_ * S_,
        (long long)S_ * NH_, (long long)H_,
        (long long)S_ * NH_, (long long)H_, 0);

    // output projection + residual LN1
    sgemm_k<<<dim3(8, 32, 1), blk>>>(attn, Wo, tmp, nullptr, M, E_, NH_, NH_, E_, E_,
                                     1, 0, 0, 0, 0, 0, 0, 0);
    ln_k<<<M, 256>>>(tmp, x, ln1g, ln1b, h1);

    // FFN
    sgemm_k<<<dim3(32, 32, 1), blk>>>(h1, Wi, inner, bi, M, F_, E_, E_, F_, F_,
                                      1, 0, 0, 0, 0, 0, 0, 1 /*relu*/);
    sgemm_k<<<dim3(8, 32, 1), blk>>>(inner, Wout, tmp, bout, M, E_, F_, F_, E_, E_,
                                     1, 0, 0, 0, 0, 0, 0, 0);
    ln_k<<<M, 256>>>(tmp, h1, ln2g, ln2b, out);
}

// round 2
// speedup vs baseline: 2.5874x; 2.5874x over previous
#include <cuda_runtime.h>
#include <math.h>
#include <stdint.h>

// Problem dims
#define B_      4
#define S_      1024
#define E_      1024
#define NHEADS  16
#define H_      64
#define NH_     1024
#define F_      4096
#define R_      2048

// ---------------- scratch (static device globals) ----------------
__device__ float g_q[4194304];        // [B,S,NH]
__device__ float g_k[4194304];        // [B,S,NH]
__device__ float g_v[4194304];        // [B,S,NH]
__device__ float g_r[8388608];        // [B,R,NH]
__device__ float g_qc[4194304];       // q + content bias
__device__ float g_qp[4194304];       // q + positional bias
__device__ float g_kt[4194304];       // [B,N,H,S]
__device__ float g_rt[8388608];       // [B,N,H,R]
__device__ float g_scores[67108864];  // [B,N,S,S]
__device__ float g_attn[4194304];
__device__ float g_h1[4194304];
__device__ float g_inner[16777216];
__device__ float g_tmp[4194304];

// ---------------- tf32 helpers ----------------
__device__ __forceinline__ uint32_t f2tf32(float f) {
    uint32_t u;
    asm("cvt.rna.tf32.f32 %0, %1;" : "=r"(u) : "f"(f));
    return u;
}

__device__ __forceinline__ void mma_tf32(float c[4], const uint32_t a[4], const uint32_t b[2]) {
    asm volatile(
        "mma.sync.aligned.m16n8k8.row.col.f32.tf32.tf32.f32 "
        "{%0,%1,%2,%3}, {%4,%5,%6,%7}, {%8,%9}, {%0,%1,%2,%3};\n"
        : "+f"(c[0]), "+f"(c[1]), "+f"(c[2]), "+f"(c[3])
        : "r"(a[0]), "r"(a[1]), "r"(a[2]), "r"(a[3]), "r"(b[0]), "r"(b[1]));
}

// ---------------- tensor-core GEMM ----------------
// C = A(MxK, lda) * B(KxN, ldb), fp32 in/out, tf32 mma, fp32 accum.
// BM=128 fixed; BN/warp-layout templated. EPI: 0 = store (+bias/relu/scale),
// 1 = rel-shift scatter-add (raw[i,g] -> C[i, i+g-S_] += val*scale).
// Batch via blockIdx.z: off = (z/zdiv)*s1 + (z%zdiv)*s2 per operand.
// Requires: M%128==0, N%BN==0, K%16==0 (true for all call sites).
template<int BN, int WRM, int WRN, int EPI>
__global__ __launch_bounds__(256) void gemm_tc(
    const float* __restrict__ A, const float* __restrict__ Bm,
    float* __restrict__ C, const float* __restrict__ bias,
    int M, int N, int K, int lda, int ldb, int ldc,
    int zdiv, long long As1, long long As2, long long Bs1, long long Bs2,
    long long Cs1, long long Cs2, int relu, float scale)
{
    constexpr int BM = 128, BK = 16;
    constexpr int MW = BM / WRM, NW = BN / WRN;
    constexpr int MT = MW / 16, NT = NW / 8;
    constexpr int LDA_S = BK + 4;   // 20
    constexpr int LDB_S = BN + 8;   // 136 / 72
    constexpr int AV = (BM * BK / 4) / 256;   // 2
    constexpr int BV = (BK * BN / 4) / 256;   // 2 / 1

    __shared__ uint32_t sA[2][BM * LDA_S];
    __shared__ uint32_t sB[2][BK * LDB_S];

    const int bm = blockIdx.y * BM, bn = blockIdx.x * BN;

    if (EPI == 1) {  // scatter tile fully outside valid j range -> skip
        int jmin = bm + bn - S_;
        int jmax = bm + BM - 1 + bn + BN - 1 - S_;
        if (jmax < 0 || jmin >= S_) return;
    }

    {
        int z = blockIdx.z;
        int zq = z / zdiv, zr = z % zdiv;
        A  += zq * As1 + zr * As2;
        Bm += zq * Bs1 + zr * Bs2;
        C  += zq * Cs1 + zr * Cs2;
    }

    const int t = threadIdx.x, lane = t & 31, wid = t >> 5;
    const int wm = (wid / WRN) * MW, wn = (wid % WRN) * NW;

    float cf[MT][NT][4];
#pragma unroll
    for (int i = 0; i < MT; i++)
#pragma unroll
        for (int j = 0; j < NT; j++)
#pragma unroll
            for (int e = 0; e < 4; e++) cf[i][j][e] = 0.f;

    float4 ra[AV], rb[BV];

    const int am = (t + 0 * 256) >> 2;          // A staging coords (iter-invariant part)
    const int akq = t & 3;

    // ---- pipeline ----
    const int nkt = K / BK;

    // global load for tile kt
#define GLOAD(kt)                                                                   \
    {                                                                               \
        _Pragma("unroll")                                                           \
        for (int i = 0; i < AV; i++) {                                              \
            int idx = t + i * 256;                                                  \
            int m = idx >> 2, kq = idx & 3;                                         \
            ra[i] = *(const float4*)(A + (long long)(bm + m) * lda + (kt) * BK + kq * 4); \
        }                                                                           \
        _Pragma("unroll")                                                           \
        for (int i = 0; i < BV; i++) {                                              \
            int idx = t + i * 256;                                                  \
            int r = idx / (BN / 4), nq = idx % (BN / 4);                            \
            rb[i] = *(const float4*)(Bm + (long long)((kt) * BK + r) * ldb + bn + nq * 4); \
        }                                                                           \
    }

#define SSTORE(buf)                                                                 \
    {                                                                               \
        _Pragma("unroll")                                                           \
        for (int i = 0; i < AV; i++) {                                              \
            int idx = t + i * 256;                                                  \
            int m = idx >> 2, kq = idx & 3;                                         \
            uint4 u;                                                                \
            u.x = f2tf32(ra[i].x); u.y = f2tf32(ra[i].y);                           \
            u.z = f2tf32(ra[i].z); u.w = f2tf32(ra[i].w);                           \
            *(uint4*)&sA[buf][m * LDA_S + kq * 4] = u;                              \
        }                                                                           \
        _Pragma("unroll")                                                           \
        for (int i = 0; i < BV; i++) {                                              \
            int idx = t + i * 256;                                                  \
            int r = idx / (BN / 4), nq = idx % (BN / 4);                            \
            uint4 u;                                                                \
            u.x = f2tf32(rb[i].x); u.y = f2tf32(rb[i].y);                           \
            u.z = f2tf32(rb[i].z); u.w = f2tf32(rb[i].w);                           \
            *(uint4*)&sB[buf][r * LDB_S + nq * 4] = u;                              \
        }                                                                           \
    }

    GLOAD(0);
    SSTORE(0);
    __syncthreads();

    for (int kt = 0; kt < nkt; kt++) {
        int buf = kt & 1;
        if (kt + 1 < nkt) GLOAD(kt + 1);

#pragma unroll
        for (int kk = 0; kk < BK; kk += 8) {
            uint32_t af[MT][4], bf[NT][2];
#pragma unroll
            for (int mt = 0; mt < MT; mt++) {
                int m0 = wm + mt * 16 + (lane >> 2);
                int c0 = kk + (lane & 3);
                af[mt][0] = sA[buf][m0 * LDA_S + c0];
                af[mt][1] = sA[buf][(m0 + 8) * LDA_S + c0];
                af[mt][2] = sA[buf][m0 * LDA_S + c0 + 4];
                af[mt][3] = sA[buf][(m0 + 8) * LDA_S + c0 + 4];
            }
#pragma unroll
            for (int nt = 0; nt < NT; nt++) {
                int n0 = wn + nt * 8 + (lane >> 2);
                int k0 = kk + (lane & 3);
                bf[nt][0] = sB[buf][k0 * LDB_S + n0];
                bf[nt][1] = sB[buf][(k0 + 4) * LDB_S + n0];
            }
#pragma unroll
            for (int mt = 0; mt < MT; mt++)
#pragma unroll
                for (int nt = 0; nt < NT; nt++)
                    mma_tf32(cf[mt][nt], af[mt], bf[nt]);
        }

        if (kt + 1 < nkt) SSTORE(buf ^ 1);
        __syncthreads();
    }
    (void)am; (void)akq;

    // ---- epilogue ----
#pragma unroll
    for (int mt = 0; mt < MT; mt++) {
#pragma unroll
        for (int nt = 0; nt < NT; nt++) {
            int r0 = bm + wm + mt * 16 + (lane >> 2);
            int c0 = bn + wn + nt * 8 + (lane & 3) * 2;
#pragma unroll
            for (int e = 0; e < 4; e++) {
                int row = r0 + (e >> 1) * 8;
                int col = c0 + (e & 1);
                float v = cf[mt][nt][e] * scale;
                if (EPI == 0) {
                    if (bias) v += bias[col];
                    if (relu) v = fmaxf(v, 0.f);
                    C[(long long)row * ldc + col] = v;
                } else {
                    int j = row + col - S_;
                    if (j >= 0 && j < S_) {
                        long long o = (long long)row * ldc + j;
                        C[o] += v;
                    }
                }
            }
        }
    }
#undef GLOAD
#undef SSTORE
}

// ---------------- per-head transpose: [B,rows,N,H] -> [B,N,H,rows] -------------
__global__ void transpose_h(const float* __restrict__ in, float* __restrict__ out, int rows)
{
    __shared__ float tile[32][33];
    int z = blockIdx.z;
    int b = z >> 4, n = z & 15;
    const float* ip = in + (long long)b * rows * NH_ + n * H_;
    float* op = out + (long long)z * H_ * rows;
    int r0 = blockIdx.x * 32, h0 = blockIdx.y * 32;
    int tx = threadIdx.x, ty = threadIdx.y;
#pragma unroll
    for (int i = 0; i < 4; i++) {
        int r = r0 + ty + i * 8;
        tile[ty + i * 8][tx] = ip[(long long)r * NH_ + h0 + tx];
    }
    __syncthreads();
#pragma unroll
    for (int i = 0; i < 4; i++) {
        int h = h0 + ty + i * 8;
        op[(long long)h * rows + r0 + tx] = tile[tx][ty + i * 8];
    }
}

// ---------------- q + biases ----------------------------------------------------
__global__ __launch_bounds__(256) void addbias_k(
    const float* __restrict__ q, const float* __restrict__ cb,
    const float* __restrict__ pb, float* __restrict__ qc, float* __restrict__ qp)
{
    long long i = (long long)blockIdx.x * 256 + threadIdx.x;  // float4 index
    float4 v = ((const float4*)q)[i];
    int col = (int)(i & (NH_ / 4 - 1));
    float4 c = ((const float4*)cb)[col];
    float4 p = ((const float4*)pb)[col];
    float4 a, b;
    a.x = v.x + c.x; a.y = v.y + c.y; a.z = v.z + c.z; a.w = v.w + c.w;
    b.x = v.x + p.x; b.y = v.y + p.y; b.z = v.z + p.z; b.w = v.w + p.w;
    ((float4*)qc)[i] = a;
    ((float4*)qp)[i] = b;
}

// ---------------- row softmax over 1024 (in place) ------------------------------
__global__ __launch_bounds__(256) void softmax_k(float* __restrict__ sc)
{
    __shared__ float red[8];
    long long row = blockIdx.x;
    float* p = sc + row * 1024;
    int t = threadIdx.x;
    float4 v = *((float4*)p + t);
    float m = fmaxf(fmaxf(v.x, v.y), fmaxf(v.z, v.w));
#pragma unroll
    for (int o = 16; o; o >>= 1) m = fmaxf(m, __shfl_xor_sync(0xffffffffu, m, o));
    if ((t & 31) == 0) red[t >> 5] = m;
    __syncthreads();
    if (t == 0) {
        float mm = red[0];
#pragma unroll
        for (int i = 1; i < 8; i++) mm = fmaxf(mm, red[i]);
        red[0] = mm;
    }
    __syncthreads();
    m = red[0];
    v.x = expf(v.x - m); v.y = expf(v.y - m);
    v.z = expf(v.z - m); v.w = expf(v.w - m);
    float s = v.x + v.y + v.z + v.w;
#pragma unroll
    for (int o = 16; o; o >>= 1) s += __shfl_xor_sync(0xffffffffu, s, o);
    __syncthreads();
    if ((t & 31) == 0) red[t >> 5] = s;
    __syncthreads();
    if (t == 0) {
        float ss = red[0];
#pragma unroll
        for (int i = 1; i < 8; i++) ss += red[i];
        red[0] = ss;
    }
    __syncthreads();
    float inv = 1.0f / red[0];
    v.x *= inv; v.y *= inv; v.z *= inv; v.w *= inv;
    *((float4*)p + t) = v;
}

// ---------------- fused residual-add + LayerNorm over E=1024 --------------------
__global__ __launch_bounds__(256) void ln_k(
    const float* __restrict__ a, const float* __restrict__ res,
    const float* __restrict__ g, const float* __restrict__ bt,
    float* __restrict__ o)
{
    __shared__ float red[16];
    long long row = blockIdx.x;
    int t = threadIdx.x;
    float4 va = *((const float4*)(a + row * 1024) + t);
    float4 vr = *((const float4*)(res + row * 1024) + t);
    float4 x;
    x.x = va.x + vr.x; x.y = va.y + vr.y; x.z = va.z + vr.z; x.w = va.w + vr.w;
    float s  = x.x + x.y + x.z + x.w;
    float q2 = x.x * x.x + x.y * x.y + x.z * x.z + x.w * x.w;
#pragma unroll
    for (int off = 16; off; off >>= 1) {
        s  += __shfl_xor_sync(0xffffffffu, s, off);
        q2 += __shfl_xor_sync(0xffffffffu, q2, off);
    }
    if ((t & 31) == 0) { red[t >> 5] = s; red[8 + (t >> 5)] = q2; }
    __syncthreads();
    if (t == 0) {
        float ss = red[0], qq = red[8];
#pragma unroll
        for (int i = 1; i < 8; i++) { ss += red[i]; qq += red[8 + i]; }
        red[0] = ss; red[8] = qq;
    }
    __syncthreads();
    float mu  = red[0] * (1.f / 1024.f);
    float var = red[8] * (1.f / 1024.f) - mu * mu;
    float rs = rsqrtf(var + 1e-12f);
    float4 gg = *((const float4*)g + t);
    float4 bb = *((const float4*)bt + t);
    float4 y;
    y.x = (x.x - mu) * rs * gg.x + bb.x;
    y.y = (x.y - mu) * rs * gg.y + bb.y;
    y.z = (x.z - mu) * rs * gg.z + bb.z;
    y.w = (x.w - mu) * rs * gg.w + bb.w;
    *((float4*)(o + row * 1024) + t) = y;
}

// ---------------- driver --------------------------------------------------------
extern "C" void kernel_launch(void* const* d_in, const int* in_sizes, int n_in,
                              void* d_out, int out_size)
{
    const float* x    = (const float*)d_in[0];
    const float* cb   = (const float*)d_in[1];
    const float* pb   = (const float*)d_in[2];
    const float* rpe  = (const float*)d_in[3];
    const float* Wq   = (const float*)d_in[4];
    const float* Wk   = (const float*)d_in[5];
    const float* Wv   = (const float*)d_in[6];
    const float* Wr   = (const float*)d_in[7];
    const float* Wo   = (const float*)d_in[8];
    const float* ln1g = (const float*)d_in[9];
    const float* ln1b = (const float*)d_in[10];
    const float* Wi   = (const float*)d_in[11];
    const float* bi   = (const float*)d_in[12];
    const float* Wout = (const float*)d_in[13];
    const float* bout = (const float*)d_in[14];
    const float* ln2g = (const float*)d_in[15];
    const float* ln2b = (const float*)d_in[16];
    float* out = (float*)d_out;

    float *q, *k, *v, *r, *qc, *qp, *kt, *rt, *sc, *attn, *h1, *inner, *tmp;
    cudaGetSymbolAddress((void**)&q,     g_q);
    cudaGetSymbolAddress((void**)&k,     g_k);
    cudaGetSymbolAddress((void**)&v,     g_v);
    cudaGetSymbolAddress((void**)&r,     g_r);
    cudaGetSymbolAddress((void**)&qc,    g_qc);
    cudaGetSymbolAddress((void**)&qp,    g_qp);
    cudaGetSymbolAddress((void**)&kt,    g_kt);
    cudaGetSymbolAddress((void**)&rt,    g_rt);
    cudaGetSymbolAddress((void**)&sc,    g_scores);
    cudaGetSymbolAddress((void**)&attn,  g_attn);
    cudaGetSymbolAddress((void**)&h1,    g_h1);
    cudaGetSymbolAddress((void**)&inner, g_inner);
    cudaGetSymbolAddress((void**)&tmp,   g_tmp);

    const int M = B_ * S_;  // 4096
    dim3 blk(256);
    const long long Z0 = 0;

    // QKV + R projections (dense GEMMs)
    gemm_tc<128,2,4,0><<<dim3(8,32,1), blk>>>(x,   Wq, q, nullptr, M,      NH_, E_, E_, NH_, NH_,
                                              1, Z0,Z0,Z0,Z0,Z0,Z0, 0, 1.f);
    gemm_tc<128,2,4,0><<<dim3(8,32,1), blk>>>(x,   Wk, k, nullptr, M,      NH_, E_, E_, NH_, NH_,
                                              1, Z0,Z0,Z0,Z0,Z0,Z0, 0, 1.f);
    gemm_tc<128,2,4,0><<<dim3(8,32,1), blk>>>(x,   Wv, v, nullptr, M,      NH_, E_, E_, NH_, NH_,
                                              1, Z0,Z0,Z0,Z0,Z0,Z0, 0, 1.f);
    gemm_tc<128,2,4,0><<<dim3(8,64,1), blk>>>(rpe, Wr, r, nullptr, B_*R_,  NH_, E_, E_, NH_, NH_,
                                              1, Z0,Z0,Z0,Z0,Z0,Z0, 0, 1.f);

    // q + biases
    addbias_k<<<(long long)M * NH_ / 4 / 256, blk>>>(q, cb, pb, qc, qp);

    // per-head transposes
    transpose_h<<<dim3(S_/32, 2, B_*NHEADS), dim3(32,8)>>>(k, kt, S_);
    transpose_h<<<dim3(R_/32, 2, B_*NHEADS), dim3(32,8)>>>(r, rt, R_);

    // content scores: per (b,n)  [S,64] x [64,S] -> scores * 0.125
    gemm_tc<128,2,4,0><<<dim3(8,8,B_*NHEADS), blk>>>(
        qc, kt, sc, nullptr, S_, S_, H_, NH_, S_, S_,
        NHEADS,
        (long long)S_*NH_, (long long)H_,
        (long long)NHEADS*H_*S_, (long long)H_*S_,
        (long long)NHEADS*S_*S_, (long long)S_*S_, 0, 0.125f);

    // position scores with folded rel-shift: raw[i,g] -> scores[i, i+g-S] +=
    gemm_tc<128,2,4,1><<<dim3(16,8,B_*NHEADS), blk>>>(
        qp, rt, sc, nullptr, S_, R_, H_, NH_, R_, S_,
        NHEADS,
        (long long)S_*NH_, (long long)H_,
        (long long)NHEADS*H_*R_, (long long)H_*R_,
        (long long)NHEADS*S_*S_, (long long)S_*S_, 0, 0.125f);

    // softmax
    softmax_k<<<B_*NHEADS*S_, 256>>>(sc);

    // attn = P @ V  (per-head, N=64)
    gemm_tc<64,4,2,0><<<dim3(1,8,B_*NHEADS), blk>>>(
        sc, v, attn, nullptr, S_, H_, S_, S_, NH_, NH_,
        NHEADS,
        (long long)NHEADS*S_*S_, (long long)S_*S_,
        (long long)S_*NH_, (long long)H_,
        (long long)S_*NH_, (long long)H_, 0, 1.f);

    // output projection + LN1
    gemm_tc<128,2,4,0><<<dim3(8,32,1), blk>>>(attn, Wo, tmp, nullptr, M, E_, NH_, NH_, E_, E_,
                                              1, Z0,Z0,Z0,Z0,Z0,Z0, 0, 1.f);
    ln_k<<<M, 256>>>(tmp, x, ln1g, ln1b, h1);

    // FFN
    gemm_tc<128,2,4,0><<<dim3(32,32,1), blk>>>(h1, Wi, inner, bi, M, F_, E_, E_, F_, F_,
                                               1, Z0,Z0,Z0,Z0,Z0,Z0, 1, 1.f);
    gemm_tc<128,2,4,0><<<dim3(8,32,1), blk>>>(inner, Wout, tmp, bout, M, E_, F_, F_, E_, E_,
                                              1, Z0,Z0,Z0,Z0,Z0,Z0, 0, 1.f);
    ln_k<<<M, 256>>>(tmp, h1, ln2g, ln2b, out);
}

// round 3
// speedup vs baseline: 2.5917x; 1.0017x over previous
#include <cuda_runtime.h>
#include <math.h>
#include <stdint.h>

// Problem dims
#define B_      4
#define S_      1024
#define E_      1024
#define NHEADS  16
#define H_      64
#define NH_     1024
#define F_      4096
#define R_      2048

// ---------------- scratch (static device globals) ----------------
__device__ float g_q[4194304];        // [B,S,NH]
__device__ float g_k[4194304];        // [B,S,NH]
__device__ float g_v[4194304];        // [B,S,NH]
__device__ float g_r[8388608];        // [B,R,NH]
__device__ float g_qc[4194304];       // q + content bias
__device__ float g_qp[4194304];       // q + positional bias
__device__ float g_kt[4194304];       // [B,N,H,S]
__device__ float g_rt[8388608];       // [B,N,H,R]
__device__ float g_scores[67108864];  // [B,N,S,S]
__device__ float g_attn[4194304];
__device__ float g_h1[4194304];
__device__ float g_inner[16777216];
__device__ float g_tmp[4194304];

// ---------------- tf32 helpers ----------------
__device__ __forceinline__ uint32_t f2tf32(float f) {
    uint32_t u;
    asm("cvt.rna.tf32.f32 %0, %1;" : "=r"(u) : "f"(f));
    return u;
}

__device__ __forceinline__ void mma_tf32(float c[4], const uint32_t a[4], const uint32_t b[2]) {
    asm volatile(
        "mma.sync.aligned.m16n8k8.row.col.f32.tf32.tf32.f32 "
        "{%0,%1,%2,%3}, {%4,%5,%6,%7}, {%8,%9}, {%0,%1,%2,%3};\n"
        : "+f"(c[0]), "+f"(c[1]), "+f"(c[2]), "+f"(c[3])
        : "r"(a[0]), "r"(a[1]), "r"(a[2]), "r"(a[3]), "r"(b[0]), "r"(b[1]));
}

// ---------------- tensor-core GEMM ----------------
// C = A(MxK, lda) * B(KxN, ldb), fp32 in/out, tf32 mma, fp32 accum.
// BM=128 fixed; BN/warp-layout templated. EPI: 0 = store (+bias/relu/scale),
// 1 = rel-shift scatter-add (raw[i,g] -> C[i, i+g-S_] += val*scale).
// Batch via blockIdx.z: off = (z/zdiv)*s1 + (z%zdiv)*s2 per operand.
// Requires: M%128==0, N%BN==0, K%16==0 (true for all call sites).
template<int BN, int WRM, int WRN, int EPI>
__global__ __launch_bounds__(256) void gemm_tc(
    const float* __restrict__ A, const float* __restrict__ Bm,
    float* __restrict__ C, const float* __restrict__ bias,
    int M, int N, int K, int lda, int ldb, int ldc,
    int zdiv, long long As1, long long As2, long long Bs1, long long Bs2,
    long long Cs1, long long Cs2, int relu, float scale)
{
    constexpr int BM = 128, BK = 16;
    constexpr int MW = BM / WRM, NW = BN / WRN;
    constexpr int MT = MW / 16, NT = NW / 8;
    constexpr int LDA_S = BK + 4;   // 20
    constexpr int LDB_S = BN + 8;   // 136 / 72
    constexpr int AV = (BM * BK / 4) / 256;   // 2
    constexpr int BV = (BK * BN / 4) / 256;   // 2 / 1

    __shared__ uint32_t sA[2][BM * LDA_S];
    __shared__ uint32_t sB[2][BK * LDB_S];

    const int bm = blockIdx.y * BM, bn = blockIdx.x * BN;

    if (EPI == 1) {  // scatter tile fully outside valid j range -> skip
        int jmin = bm + bn - S_;
        int jmax = bm + BM - 1 + bn + BN - 1 - S_;
        if (jmax < 0 || jmin >= S_) return;
    }

    {
        int z = blockIdx.z;
        int zq = z / zdiv, zr = z % zdiv;
        A  += zq * As1 + zr * As2;
        Bm += zq * Bs1 + zr * Bs2;
        C  += zq * Cs1 + zr * Cs2;
    }

    const int t = threadIdx.x, lane = t & 31, wid = t >> 5;
    const int wm = (wid / WRN) * MW, wn = (wid % WRN) * NW;

    float cf[MT][NT][4];
#pragma unroll
    for (int i = 0; i < MT; i++)
#pragma unroll
        for (int j = 0; j < NT; j++)
#pragma unroll
            for (int e = 0; e < 4; e++) cf[i][j][e] = 0.f;

    float4 ra[AV], rb[BV];

    const int am = (t + 0 * 256) >> 2;          // A staging coords (iter-invariant part)
    const int akq = t & 3;

    // ---- pipeline ----
    const int nkt = K / BK;

    // global load for tile kt
#define GLOAD(kt)                                                                   \
    {                                                                               \
        _Pragma("unroll")                                                           \
        for (int i = 0; i < AV; i++) {                                              \
            int idx = t + i * 256;                                                  \
            int m = idx >> 2, kq = idx & 3;                                         \
            ra[i] = *(const float4*)(A + (long long)(bm + m) * lda + (kt) * BK + kq * 4); \
        }                                                                           \
        _Pragma("unroll")                                                           \
        for (int i = 0; i < BV; i++) {                                              \
            int idx = t + i * 256;                                                  \
            int r = idx / (BN / 4), nq = idx % (BN / 4);                            \
            rb[i] = *(const float4*)(Bm + (long long)((kt) * BK + r) * ldb + bn + nq * 4); \
        }                                                                           \
    }

#define SSTORE(buf)                                                                 \
    {                                                                               \
        _Pragma("unroll")                                                           \
        for (int i = 0; i < AV; i++) {                                              \
            int idx = t + i * 256;                                                  \
            int m = idx >> 2, kq = idx & 3;                                         \
            uint4 u;                                                                \
            u.x = f2tf32(ra[i].x); u.y = f2tf32(ra[i].y);                           \
            u.z = f2tf32(ra[i].z); u.w = f2tf32(ra[i].w);                           \
            *(uint4*)&sA[buf][m * LDA_S + kq * 4] = u;                              \
        }                                                                           \
        _Pragma("unroll")                                                           \
        for (int i = 0; i < BV; i++) {                                              \
            int idx = t + i * 256;                                                  \
            int r = idx / (BN / 4), nq = idx % (BN / 4);                            \
            uint4 u;                                                                \
            u.x = f2tf32(rb[i].x); u.y = f2tf32(rb[i].y);                           \
            u.z = f2tf32(rb[i].z); u.w = f2tf32(rb[i].w);                           \
            *(uint4*)&sB[buf][r * LDB_S + nq * 4] = u;                              \
        }                                                                           \
    }

    GLOAD(0);
    SSTORE(0);
    __syncthreads();

    for (int kt = 0; kt < nkt; kt++) {
        int buf = kt & 1;
        if (kt + 1 < nkt) GLOAD(kt + 1);

#pragma unroll
        for (int kk = 0; kk < BK; kk += 8) {
            uint32_t af[MT][4], bf[NT][2];
#pragma unroll
            for (int mt = 0; mt < MT; mt++) {
                int m0 = wm + mt * 16 + (lane >> 2);
                int c0 = kk + (lane & 3);
                af[mt][0] = sA[buf][m0 * LDA_S + c0];
                af[mt][1] = sA[buf][(m0 + 8) * LDA_S + c0];
                af[mt][2] = sA[buf][m0 * LDA_S + c0 + 4];
                af[mt][3] = sA[buf][(m0 + 8) * LDA_S + c0 + 4];
            }
#pragma unroll
            for (int nt = 0; nt < NT; nt++) {
                int n0 = wn + nt * 8 + (lane >> 2);
                int k0 = kk + (lane & 3);
                bf[nt][0] = sB[buf][k0 * LDB_S + n0];
                bf[nt][1] = sB[buf][(k0 + 4) * LDB_S + n0];
            }
#pragma unroll
            for (int mt = 0; mt < MT; mt++)
#pragma unroll
                for (int nt = 0; nt < NT; nt++)
                    mma_tf32(cf[mt][nt], af[mt], bf[nt]);
        }

        if (kt + 1 < nkt) SSTORE(buf ^ 1);
        __syncthreads();
    }
    (void)am; (void)akq;

    // ---- epilogue ----
#pragma unroll
    for (int mt = 0; mt < MT; mt++) {
#pragma unroll
        for (int nt = 0; nt < NT; nt++) {
            int r0 = bm + wm + mt * 16 + (lane >> 2);
            int c0 = bn + wn + nt * 8 + (lane & 3) * 2;
#pragma unroll
            for (int e = 0; e < 4; e++) {
                int row = r0 + (e >> 1) * 8;
                int col = c0 + (e & 1);
                float v = cf[mt][nt][e] * scale;
                if (EPI == 0) {
                    if (bias) v += bias[col];
                    if (relu) v = fmaxf(v, 0.f);
                    C[(long long)row * ldc + col] = v;
                } else {
                    int j = row + col - S_;
                    if (j >= 0 && j < S_) {
                        long long o = (long long)row * ldc + j;
                        C[o] += v;
                    }
                }
            }
        }
    }
#undef GLOAD
#undef SSTORE
}

// ---------------- per-head transpose: [B,rows,N,H] -> [B,N,H,rows] -------------
__global__ void transpose_h(const float* __restrict__ in, float* __restrict__ out, int rows)
{
    __shared__ float tile[32][33];
    int z = blockIdx.z;
    int b = z >> 4, n = z & 15;
    const float* ip = in + (long long)b * rows * NH_ + n * H_;
    float* op = out + (long long)z * H_ * rows;
    int r0 = blockIdx.x * 32, h0 = blockIdx.y * 32;
    int tx = threadIdx.x, ty = threadIdx.y;
#pragma unroll
    for (int i = 0; i < 4; i++) {
        int r = r0 + ty + i * 8;
        tile[ty + i * 8][tx] = ip[(long long)r * NH_ + h0 + tx];
    }
    __syncthreads();
#pragma unroll
    for (int i = 0; i < 4; i++) {
        int h = h0 + ty + i * 8;
        op[(long long)h * rows + r0 + tx] = tile[tx][ty + i * 8];
    }
}

// ---------------- q + biases ----------------------------------------------------
__global__ __launch_bounds__(256) void addbias_k(
    const float* __restrict__ q, const float* __restrict__ cb,
    const float* __restrict__ pb, float* __restrict__ qc, float* __restrict__ qp)
{
    long long i = (long long)blockIdx.x * 256 + threadIdx.x;  // float4 index
    float4 v = ((const float4*)q)[i];
    int col = (int)(i & (NH_ / 4 - 1));
    float4 c = ((const float4*)cb)[col];
    float4 p = ((const float4*)pb)[col];
    float4 a, b;
    a.x = v.x + c.x; a.y = v.y + c.y; a.z = v.z + c.z; a.w = v.w + c.w;
    b.x = v.x + p.x; b.y = v.y + p.y; b.z = v.z + p.z; b.w = v.w + p.w;
    ((float4*)qc)[i] = a;
    ((float4*)qp)[i] = b;
}

// ---------------- row softmax over 1024 (in place) ------------------------------
__global__ __launch_bounds__(256) void softmax_k(float* __restrict__ sc)
{
    __shared__ float red[8];
    long long row = blockIdx.x;
    float* p = sc + row * 1024;
    int t = threadIdx.x;
    float4 v = *((float4*)p + t);
    float m = fmaxf(fmaxf(v.x, v.y), fmaxf(v.z, v.w));
#pragma unroll
    for (int o = 16; o; o >>= 1) m = fmaxf(m, __shfl_xor_sync(0xffffffffu, m, o));
    if ((t & 31) == 0) red[t >> 5] = m;
    __syncthreads();
    if (t == 0) {
        float mm = red[0];
#pragma unroll
        for (int i = 1; i < 8; i++) mm = fmaxf(mm, red[i]);
        red[0] = mm;
    }
    __syncthreads();
    m = red[0];
    v.x = expf(v.x - m); v.y = expf(v.y - m);
    v.z = expf(v.z - m); v.w = expf(v.w - m);
    float s = v.x + v.y + v.z + v.w;
#pragma unroll
    for (int o = 16; o; o >>= 1) s += __shfl_xor_sync(0xffffffffu, s, o);
    __syncthreads();
    if ((t & 31) == 0) red[t >> 5] = s;
    __syncthreads();
    if (t == 0) {
        float ss = red[0];
#pragma unroll
        for (int i = 1; i < 8; i++) ss += red[i];
        red[0] = ss;
    }
    __syncthreads();
    float inv = 1.0f / red[0];
    v.x *= inv; v.y *= inv; v.z *= inv; v.w *= inv;
    *((float4*)p + t) = v;
}

// ---------------- fused residual-add + LayerNorm over E=1024 --------------------
__global__ __launch_bounds__(256) void ln_k(
    const float* __restrict__ a, const float* __restrict__ res,
    const float* __restrict__ g, const float* __restrict__ bt,
    float* __restrict__ o)
{
    __shared__ float red[16];
    long long row = blockIdx.x;
    int t = threadIdx.x;
    float4 va = *((const float4*)(a + row * 1024) + t);
    float4 vr = *((const float4*)(res + row * 1024) + t);
    float4 x;
    x.x = va.x + vr.x; x.y = va.y + vr.y; x.z = va.z + vr.z; x.w = va.w + vr.w;
    float s  = x.x + x.y + x.z + x.w;
    float q2 = x.x * x.x + x.y * x.y + x.z * x.z + x.w * x.w;
#pragma unroll
    for (int off = 16; off; off >>= 1) {
        s  += __shfl_xor_sync(0xffffffffu, s, off);
        q2 += __shfl_xor_sync(0xffffffffu, q2, off);
    }
    if ((t & 31) == 0) { red[t >> 5] = s; red[8 + (t >> 5)] = q2; }
    __syncthreads();
    if (t == 0) {
        float ss = red[0], qq = red[8];
#pragma unroll
        for (int i = 1; i < 8; i++) { ss += red[i]; qq += red[8 + i]; }
        red[0] = ss; red[8] = qq;
    }
    __syncthreads();
    float mu  = red[0] * (1.f / 1024.f);
    float var = red[8] * (1.f / 1024.f) - mu * mu;
    float rs = rsqrtf(var + 1e-12f);
    float4 gg = *((const float4*)g + t);
    float4 bb = *((const float4*)bt + t);
    float4 y;
    y.x = (x.x - mu) * rs * gg.x + bb.x;
    y.y = (x.y - mu) * rs * gg.y + bb.y;
    y.z = (x.z - mu) * rs * gg.z + bb.z;
    y.w = (x.w - mu) * rs * gg.w + bb.w;
    *((float4*)(o + row * 1024) + t) = y;
}

// ---------------- driver --------------------------------------------------------
extern "C" void kernel_launch(void* const* d_in, const int* in_sizes, int n_in,
                              void* d_out, int out_size)
{
    const float* x    = (const float*)d_in[0];
    const float* cb   = (const float*)d_in[1];
    const float* pb   = (const float*)d_in[2];
    const float* rpe  = (const float*)d_in[3];
    const float* Wq   = (const float*)d_in[4];
    const float* Wk   = (const float*)d_in[5];
    const float* Wv   = (const float*)d_in[6];
    const float* Wr   = (const float*)d_in[7];
    const float* Wo   = (const float*)d_in[8];
    const float* ln1g = (const float*)d_in[9];
    const float* ln1b = (const float*)d_in[10];
    const float* Wi   = (const float*)d_in[11];
    const float* bi   = (const float*)d_in[12];
    const float* Wout = (const float*)d_in[13];
    const float* bout = (const float*)d_in[14];
    const float* ln2g = (const float*)d_in[15];
    const float* ln2b = (const float*)d_in[16];
    float* out = (float*)d_out;

    float *q, *k, *v, *r, *qc, *qp, *kt, *rt, *sc, *attn, *h1, *inner, *tmp;
    cudaGetSymbolAddress((void**)&q,     g_q);
    cudaGetSymbolAddress((void**)&k,     g_k);
    cudaGetSymbolAddress((void**)&v,     g_v);
    cudaGetSymbolAddress((void**)&r,     g_r);
    cudaGetSymbolAddress((void**)&qc,    g_qc);
    cudaGetSymbolAddress((void**)&qp,    g_qp);
    cudaGetSymbolAddress((void**)&kt,    g_kt);
    cudaGetSymbolAddress((void**)&rt,    g_rt);
    cudaGetSymbolAddress((void**)&sc,    g_scores);
    cudaGetSymbolAddress((void**)&attn,  g_attn);
    cudaGetSymbolAddress((void**)&h1,    g_h1);
    cudaGetSymbolAddress((void**)&inner, g_inner);
    cudaGetSymbolAddress((void**)&tmp,   g_tmp);

    const int M = B_ * S_;  // 4096
    dim3 blk(256);
    const long long Z0 = 0;

    // QKV + R projections (dense GEMMs)
    gemm_tc<128,2,4,0><<<dim3(8,32,1), blk>>>(x,   Wq, q, nullptr, M,      NH_, E_, E_, NH_, NH_,
                                              1, Z0,Z0,Z0,Z0,Z0,Z0, 0, 1.f);
    gemm_tc<128,2,4,0><<<dim3(8,32,1), blk>>>(x,   Wk, k, nullptr, M,      NH_, E_, E_, NH_, NH_,
                                              1, Z0,Z0,Z0,Z0,Z0,Z0, 0, 1.f);
    gemm_tc<128,2,4,0><<<dim3(8,32,1), blk>>>(x,   Wv, v, nullptr, M,      NH_, E_, E_, NH_, NH_,
                                              1, Z0,Z0,Z0,Z0,Z0,Z0, 0, 1.f);
    gemm_tc<128,2,4,0><<<dim3(8,64,1), blk>>>(rpe, Wr, r, nullptr, B_*R_,  NH_, E_, E_, NH_, NH_,
                                              1, Z0,Z0,Z0,Z0,Z0,Z0, 0, 1.f);

    // q + biases
    addbias_k<<<(long long)M * NH_ / 4 / 256, blk>>>(q, cb, pb, qc, qp);

    // per-head transposes
    transpose_h<<<dim3(S_/32, 2, B_*NHEADS), dim3(32,8)>>>(k, kt, S_);
    transpose_h<<<dim3(R_/32, 2, B_*NHEADS), dim3(32,8)>>>(r, rt, R_);

    // content scores: per (b,n)  [S,64] x [64,S] -> scores * 0.125
    gemm_tc<128,2,4,0><<<dim3(8,8,B_*NHEADS), blk>>>(
        qc, kt, sc, nullptr, S_, S_, H_, NH_, S_, S_,
        NHEADS,
        (long long)S_*NH_, (long long)H_,
        (long long)NHEADS*H_*S_, (long long)H_*S_,
        (long long)NHEADS*S_*S_, (long long)S_*S_, 0, 0.125f);

    // position scores with folded rel-shift: raw[i,g] -> scores[i, i+g-S] +=
    gemm_tc<128,2,4,1><<<dim3(16,8,B_*NHEADS), blk>>>(
        qp, rt, sc, nullptr, S_, R_, H_, NH_, R_, S_,
        NHEADS,
        (long long)S_*NH_, (long long)H_,
        (long long)NHEADS*H_*R_, (long long)H_*R_,
        (long long)NHEADS*S_*S_, (long long)S_*S_, 0, 0.125f);

    // softmax
    softmax_k<<<B_*NHEADS*S_, 256>>>(sc);

    // attn = P @ V  (per-head, N=64)
    gemm_tc<64,4,2,0><<<dim3(1,8,B_*NHEADS), blk>>>(
        sc, v, attn, nullptr, S_, H_, S_, S_, NH_, NH_,
        NHEADS,
        (long long)NHEADS*S_*S_, (long long)S_*S_,
        (long long)S_*NH_, (long long)H_,
        (long long)S_*NH_, (long long)H_, 0, 1.f);

    // output projection + LN1
    gemm_tc<128,2,4,0><<<dim3(8,32,1), blk>>>(attn, Wo, tmp, nullptr, M, E_, NH_, NH_, E_, E_,
                                              1, Z0,Z0,Z0,Z0,Z0,Z0, 0, 1.f);
    ln_k<<<M, 256>>>(tmp, x, ln1g, ln1b, h1);

    // FFN
    gemm_tc<128,2,4,0><<<dim3(32,32,1), blk>>>(h1, Wi, inner, bi, M, F_, E_, E_, F_, F_,
                                               1, Z0,Z0,Z0,Z0,Z0,Z0, 1, 1.f);
    gemm_tc<128,2,4,0><<<dim3(8,32,1), blk>>>(inner, Wout, tmp, bout, M, E_, F_, F_, E_, E_,
                                              1, Z0,Z0,Z0,Z0,Z0,Z0, 0, 1.f);
    ln_k<<<M, 256>>>(tmp, h1, ln2g, ln2b, out);
}

// round 5
// speedup vs baseline: 4.0082x; 1.5465x over previous
#include <cuda_runtime.h>
#include <cuda_fp16.h>
#include <math.h>
#include <stdint.h>

#define B_      4
#define S_      1024
#define E_      1024
#define NHEADS  16
#define H_      64
#define NH_     1024
#define F_      4096
#define R_      2048

// ---------------- scratch (static device globals) ----------------
__device__ __half g_xh[4194304];      // [B,S,E]
__device__ __half g_rpeh[8388608];    // [B,R,E]
__device__ __half g_q[4194304];
__device__ __half g_k[4194304];
__device__ __half g_v[4194304];
__device__ __half g_r[8388608];
__device__ __half g_qc[4194304];
__device__ __half g_qp[4194304];
__device__ __half g_vt[4194304];      // [B,N,H,S]
__device__ float  g_sc[67108864];     // [B,N,S,S] fp32 scores
__device__ __half g_sch[67108864];    // probs fp16
__device__ __half g_attn[4194304];
__device__ float  g_h1[4194304];
__device__ __half g_h1h[4194304];
__device__ __half g_inner[16777216];
__device__ float  g_tmp[4194304];
__device__ __half g_WqT[1048576];
__device__ __half g_WkT[1048576];
__device__ __half g_WvT[1048576];
__device__ __half g_WrT[1048576];
__device__ __half g_WoT[1048576];
__device__ __half g_WiT[4194304];
__device__ __half g_WoutT[4194304];

// ---------------- helpers ----------------
__device__ __forceinline__ uint32_t smem_u32(const void* p) {
    uint32_t a;
    asm("{ .reg .u64 t; cvta.to.shared.u64 t, %1; cvt.u32.u64 %0, t; }" : "=r"(a) : "l"(p));
    return a;
}
__device__ __forceinline__ void cpasync16(uint32_t s, const void* g) {
    asm volatile("cp.async.cg.shared.global [%0], [%1], 16;" :: "r"(s), "l"(g));
}
#define CP_COMMIT() asm volatile("cp.async.commit_group;" ::: "memory")
#define CP_WAIT(n)  asm volatile("cp.async.wait_group %0;" :: "n"(n) : "memory")

#define LDM4(r0, r1, r2, r3, a)                                                     \
    asm volatile("ldmatrix.sync.aligned.m8n8.x4.shared.b16 {%0,%1,%2,%3}, [%4];"    \
                 : "=r"(r0), "=r"(r1), "=r"(r2), "=r"(r3) : "r"(a))

#define MMA16816(c, a, b)                                                           \
    asm volatile("mma.sync.aligned.m16n8k16.row.col.f32.f16.f16.f32 "               \
                 "{%0,%1,%2,%3},{%4,%5,%6,%7},{%8,%9},{%0,%1,%2,%3};"               \
                 : "+f"((c)[0]), "+f"((c)[1]), "+f"((c)[2]), "+f"((c)[3])           \
                 : "r"((a)[0]), "r"((a)[1]), "r"((a)[2]), "r"((a)[3]),              \
                   "r"((b)[0]), "r"((b)[1]))

// ---------------- fp16 tensor-core GEMM -----------------------------------------
// C = A(MxK, K-major rows) * B(NxK, K-major rows)^T.  fp32 accumulate.
// EPI 0: store (+bias/relu/scale), OUTH selects half/float output.
// EPI 1: rel-shift scatter-add into fp32 C.
// Requires M%128==0, N%BN==0, K%32==0.
template<int BN, int WRM, int WRN, int EPI, int OUTH>
__global__ __launch_bounds__(256, 2) void hgemm(
    const __half* __restrict__ A, const __half* __restrict__ Bm,
    void* __restrict__ Cv, const float* __restrict__ bias,
    int K, int lda, int ldb, int ldc, int zdiv,
    long long As1, long long As2, long long Bs1, long long Bs2,
    long long Cs1, long long Cs2, int relu, float scale)
{
    constexpr int BM = 128, LDS = 40;            // 32 halves + 8 pad
    constexpr int MW = BM / WRM, NW = BN / WRN;
    constexpr int MT = MW / 16, NPAIR = NW / 16, NT = NW / 8;
    __shared__ __half sA[2][BM * LDS];
    __shared__ __half sB[2][BN * LDS];

    const int bm = blockIdx.y * BM, bn = blockIdx.x * BN;
    if (EPI == 1) {
        int jmin = bm + bn - S_;
        int jmax = bm + BM - 1 + bn + BN - 1 - S_;
        if (jmax < 0 || jmin >= S_) return;
    }
    {
        int z = blockIdx.z, zq = z / zdiv, zr = z % zdiv;
        A  += zq * As1 + zr * As2;
        Bm += zq * Bs1 + zr * Bs2;
    }
    const int tid = threadIdx.x, lane = tid & 31, wid = tid >> 5;
    const int wm = (wid / WRN) * MW, wn = (wid % WRN) * NW;

    float cf[MT][NT][4];
#pragma unroll
    for (int i = 0; i < MT; i++)
#pragma unroll
        for (int j = 0; j < NT; j++)
#pragma unroll
            for (int e = 0; e < 4; e++) cf[i][j][e] = 0.f;

    auto stage = [&](int c, int buf) {
#pragma unroll
        for (int i = 0; i < BM * 4 / 256; i++) {
            int id = tid + i * 256, row = id >> 2, ch = id & 3;
            cpasync16(smem_u32(&sA[buf][row * LDS + ch * 8]),
                      A + (long long)(bm + row) * lda + c * 32 + ch * 8);
        }
#pragma unroll
        for (int i = 0; i < BN * 4 / 256; i++) {
            int id = tid + i * 256, row = id >> 2, ch = id & 3;
            cpasync16(smem_u32(&sB[buf][row * LDS + ch * 8]),
                      Bm + (long long)(bn + row) * ldb + c * 32 + ch * 8);
        }
        CP_COMMIT();
    };

    const int nkt = K >> 5;
    stage(0, 0);
    for (int c = 0; c < nkt; c++) {
        if (c + 1 < nkt) { stage(c + 1, (c + 1) & 1); CP_WAIT(1); }
        else             { CP_WAIT(0); }
        __syncthreads();
        const int buf = c & 1;
        const uint32_t a0 = smem_u32(&sA[buf][0]);
        const uint32_t b0 = smem_u32(&sB[buf][0]);
#pragma unroll
        for (int ks = 0; ks < 2; ks++) {
            uint32_t af[MT][4], bf[NT][2];
#pragma unroll
            for (int mt = 0; mt < MT; mt++) {
                uint32_t ad = a0 + ((wm + mt * 16 + (lane & 15)) * LDS
                                    + ks * 16 + (lane >> 4) * 8) * 2;
                LDM4(af[mt][0], af[mt][1], af[mt][2], af[mt][3], ad);
            }
#pragma unroll
            for (int p = 0; p < NPAIR; p++) {
                int rn = wn + p * 16 + (lane & 7) + ((lane >> 4) << 3);
                uint32_t bd = b0 + (rn * LDS + ks * 16 + ((lane >> 3) & 1) * 8) * 2;
                uint32_t r0, r1, r2, r3;
                LDM4(r0, r1, r2, r3, bd);
                bf[2 * p][0] = r0; bf[2 * p][1] = r1;
                bf[2 * p + 1][0] = r2; bf[2 * p + 1][1] = r3;
            }
#pragma unroll
            for (int mt = 0; mt < MT; mt++)
#pragma unroll
                for (int nt = 0; nt < NT; nt++)
                    MMA16816(cf[mt][nt], af[mt], bf[nt]);
        }
        __syncthreads();
    }

    // ---- epilogue ----
    long long coff;
    {
        int z = blockIdx.z, zq = z / zdiv, zr = z % zdiv;
        coff = zq * Cs1 + zr * Cs2;
    }
#pragma unroll
    for (int mt = 0; mt < MT; mt++) {
#pragma unroll
        for (int nt = 0; nt < NT; nt++) {
            int r = bm + wm + mt * 16 + (lane >> 2);
            int col = bn + wn + nt * 8 + (lane & 3) * 2;
            float v0 = cf[mt][nt][0] * scale, v1 = cf[mt][nt][1] * scale;
            float v2 = cf[mt][nt][2] * scale, v3 = cf[mt][nt][3] * scale;
            if (EPI == 0) {
                if (bias) {
                    float b0v = bias[col], b1v = bias[col + 1];
                    v0 += b0v; v1 += b1v; v2 += b0v; v3 += b1v;
                }
                if (relu) {
                    v0 = fmaxf(v0, 0.f); v1 = fmaxf(v1, 0.f);
                    v2 = fmaxf(v2, 0.f); v3 = fmaxf(v3, 0.f);
                }
                if (OUTH) {
                    __half* Ch = (__half*)Cv + coff;
                    *(__half2*)(Ch + (long long)r * ldc + col) = __floats2half2_rn(v0, v1);
                    *(__half2*)(Ch + (long long)(r + 8) * ldc + col) = __floats2half2_rn(v2, v3);
                } else {
                    float* Cf = (float*)Cv + coff;
                    *(float2*)(Cf + (long long)r * ldc + col) = make_float2(v0, v1);
                    *(float2*)(Cf + (long long)(r + 8) * ldc + col) = make_float2(v2, v3);
                }
            } else {
                float* Cf = (float*)Cv + coff;
                int j0 = r + col - S_, j1 = j0 + 1;
                int j2 = r + 8 + col - S_, j3 = j2 + 1;
                if (j0 >= 0 && j0 < S_) Cf[(long long)r * ldc + j0] += v0;
                if (j1 >= 0 && j1 < S_) Cf[(long long)r * ldc + j1] += v1;
                if (j2 >= 0 && j2 < S_) Cf[(long long)(r + 8) * ldc + j2] += v2;
                if (j3 >= 0 && j3 < S_) Cf[(long long)(r + 8) * ldc + j3] += v3;
            }
        }
    }
}

// ---------------- fp32 -> fp16 copy ----------------
__global__ __launch_bounds__(256) void f2h_k(const float* __restrict__ in,
                                             __half* __restrict__ out)
{
    long long i = (long long)blockIdx.x * 256 + threadIdx.x;   // float4 index
    float4 v = ((const float4*)in)[i];
    ((__half2*)out)[i * 2]     = __floats2half2_rn(v.x, v.y);
    ((__half2*)out)[i * 2 + 1] = __floats2half2_rn(v.z, v.w);
}

// ---------------- fp32 transpose -> fp16: in[rows,cols] -> out[cols,rows] -------
__global__ void transpose_h16(const float* __restrict__ in, __half* __restrict__ out,
                              int rows, int cols)
{
    __shared__ float tile[32][33];
    int r0 = blockIdx.y * 32, c0 = blockIdx.x * 32;
    int tx = threadIdx.x, ty = threadIdx.y;
#pragma unroll
    for (int i = 0; i < 4; i++)
        tile[ty + i * 8][tx] = in[(long long)(r0 + ty + i * 8) * cols + c0 + tx];
    __syncthreads();
#pragma unroll
    for (int i = 0; i < 4; i++)
        out[(long long)(c0 + ty + i * 8) * rows + r0 + tx] = __float2half_rn(tile[tx][ty + i * 8]);
}

// ---------------- per-head half transpose: [B,rows,N,H] -> [B,N,H,rows] ---------
__global__ void transpose_vh(const __half* __restrict__ in, __half* __restrict__ out, int rows)
{
    __shared__ __half tile[32][34];
    int z = blockIdx.z, b = z >> 4, n = z & 15;
    const __half* ip = in + (long long)b * rows * NH_ + n * H_;
    __half* op = out + (long long)z * H_ * rows;
    int r0 = blockIdx.x * 32, h0 = blockIdx.y * 32;
    int tx = threadIdx.x, ty = threadIdx.y;
#pragma unroll
    for (int i = 0; i < 4; i++)
        tile[ty + i * 8][tx] = ip[(long long)(r0 + ty + i * 8) * NH_ + h0 + tx];
    __syncthreads();
#pragma unroll
    for (int i = 0; i < 4; i++)
        op[(long long)(h0 + ty + i * 8) * rows + r0 + tx] = tile[tx][ty + i * 8];
}

// ---------------- q(half) + biases(fp32) -> qc, qp (half) -----------------------
__global__ __launch_bounds__(256) void addbias_k(
    const __half* __restrict__ q, const float* __restrict__ cb,
    const float* __restrict__ pb, __half* __restrict__ qc, __half* __restrict__ qp)
{
    long long i = (long long)blockIdx.x * 256 + threadIdx.x;   // half2 index
    float2 v = __half22float2(((const __half2*)q)[i]);
    int cp2 = (int)(i & (NH_ / 2 - 1));
    float2 c = ((const float2*)cb)[cp2];
    float2 p = ((const float2*)pb)[cp2];
    ((__half2*)qc)[i] = __floats2half2_rn(v.x + c.x, v.y + c.y);
    ((__half2*)qp)[i] = __floats2half2_rn(v.x + p.x, v.y + p.y);
}

// ---------------- row softmax over 1024: fp32 in -> fp16 probs ------------------
__global__ __launch_bounds__(256) void softmax_k(const float* __restrict__ sc,
                                                 __half* __restrict__ sch)
{
    __shared__ float red[8];
    long long row = blockIdx.x;
    const float* p = sc + row * 1024;
    int t = threadIdx.x;
    float4 v = *((const float4*)p + t);
    float m = fmaxf(fmaxf(v.x, v.y), fmaxf(v.z, v.w));
#pragma unroll
    for (int o = 16; o; o >>= 1) m = fmaxf(m, __shfl_xor_sync(0xffffffffu, m, o));
    if ((t & 31) == 0) red[t >> 5] = m;
    __syncthreads();
    if (t == 0) {
        float mm = red[0];
#pragma unroll
        for (int i = 1; i < 8; i++) mm = fmaxf(mm, red[i]);
        red[0] = mm;
    }
    __syncthreads();
    m = red[0];
    v.x = expf(v.x - m); v.y = expf(v.y - m);
    v.z = expf(v.z - m); v.w = expf(v.w - m);
    float s = v.x + v.y + v.z + v.w;
#pragma unroll
    for (int o = 16; o; o >>= 1) s += __shfl_xor_sync(0xffffffffu, s, o);
    __syncthreads();
    if ((t & 31) == 0) red[t >> 5] = s;
    __syncthreads();
    if (t == 0) {
        float ss = red[0];
#pragma unroll
        for (int i = 1; i < 8; i++) ss += red[i];
        red[0] = ss;
    }
    __syncthreads();
    float inv = 1.0f / red[0];
    __half2* ph = (__half2*)(sch + row * 1024);
    ph[2 * t]     = __floats2half2_rn(v.x * inv, v.y * inv);
    ph[2 * t + 1] = __floats2half2_rn(v.z * inv, v.w * inv);
}

// ---------------- residual + LayerNorm (optional fp16 copy) ---------------------
__global__ __launch_bounds__(256) void ln_k(
    const float* __restrict__ a, const float* __restrict__ res,
    const float* __restrict__ g, const float* __restrict__ bt,
    float* __restrict__ o, __half* __restrict__ oh)
{
    __shared__ float red[16];
    long long row = blockIdx.x;
    int t = threadIdx.x;
    float4 va = *((const float4*)(a + row * 1024) + t);
    float4 vr = *((const float4*)(res + row * 1024) + t);
    float4 x;
    x.x = va.x + vr.x; x.y = va.y + vr.y; x.z = va.z + vr.z; x.w = va.w + vr.w;
    float s  = x.x + x.y + x.z + x.w;
    float q2 = x.x * x.x + x.y * x.y + x.z * x.z + x.w * x.w;
#pragma unroll
    for (int off = 16; off; off >>= 1) {
        s  += __shfl_xor_sync(0xffffffffu, s, off);
        q2 += __shfl_xor_sync(0xffffffffu, q2, off);
    }
    if ((t & 31) == 0) { red[t >> 5] = s; red[8 + (t >> 5)] = q2; }
    __syncthreads();
    if (t == 0) {
        float ss = red[0], qq = red[8];
#pragma unroll
        for (int i = 1; i < 8; i++) { ss += red[i]; qq += red[8 + i]; }
        red[0] = ss; red[8] = qq;
    }
    __syncthreads();
    float mu  = red[0] * (1.f / 1024.f);
    float var = red[8] * (1.f / 1024.f) - mu * mu;
    float rs = rsqrtf(var + 1e-12f);
    float4 gg = *((const float4*)g + t);
    float4 bb = *((const float4*)bt + t);
    float4 y;
    y.x = (x.x - mu) * rs * gg.x + bb.x;
    y.y = (x.y - mu) * rs * gg.y + bb.y;
    y.z = (x.z - mu) * rs * gg.z + bb.z;
    y.w = (x.w - mu) * rs * gg.w + bb.w;
    *((float4*)(o + row * 1024) + t) = y;
    if (oh) {
        __half2* ph = (__half2*)(oh + row * 1024);
        ph[2 * t]     = __floats2half2_rn(y.x, y.y);
        ph[2 * t + 1] = __floats2half2_rn(y.z, y.w);
    }
}

// ---------------- driver --------------------------------------------------------
extern "C" void kernel_launch(void* const* d_in, const int* in_sizes, int n_in,
                              void* d_out, int out_size)
{
    const float* x    = (const float*)d_in[0];
    const float* cb   = (const float*)d_in[1];
    const float* pb   = (const float*)d_in[2];
    const float* rpe  = (const float*)d_in[3];
    const float* Wq   = (const float*)d_in[4];
    const float* Wk   = (const float*)d_in[5];
    const float* Wv   = (const float*)d_in[6];
    const float* Wr   = (const float*)d_in[7];
    const float* Wo   = (const float*)d_in[8];
    const float* ln1g = (const float*)d_in[9];
    const float* ln1b = (const float*)d_in[10];
    const float* Wi   = (const float*)d_in[11];
    const float* bi   = (const float*)d_in[12];
    const float* Wout = (const float*)d_in[13];
    const float* bout = (const float*)d_in[14];
    const float* ln2g = (const float*)d_in[15];
    const float* ln2b = (const float*)d_in[16];
    float* out = (float*)d_out;

    __half *xh,*rpeh,*q,*k,*v,*r,*qc,*qp,*vt,*sch,*attn,*h1h,*inner;
    __half *WqT,*WkT,*WvT,*WrT,*WoT,*WiT,*WoutT;
    float *sc,*h1,*tmp;
    cudaGetSymbolAddress((void**)&xh, g_xh);      cudaGetSymbolAddress((void**)&rpeh, g_rpeh);
    cudaGetSymbolAddress((void**)&q, g_q);        cudaGetSymbolAddress((void**)&k, g_k);
    cudaGetSymbolAddress((void**)&v, g_v);        cudaGetSymbolAddress((void**)&r, g_r);
    cudaGetSymbolAddress((void**)&qc, g_qc);      cudaGetSymbolAddress((void**)&qp, g_qp);
    cudaGetSymbolAddress((void**)&vt, g_vt);      cudaGetSymbolAddress((void**)&sc, g_sc);
    cudaGetSymbolAddress((void**)&sch, g_sch);    cudaGetSymbolAddress((void**)&attn, g_attn);
    cudaGetSymbolAddress((void**)&h1, g_h1);      cudaGetSymbolAddress((void**)&h1h, g_h1h);
    cudaGetSymbolAddress((void**)&inner, g_inner);cudaGetSymbolAddress((void**)&tmp, g_tmp);
    cudaGetSymbolAddress((void**)&WqT, g_WqT);    cudaGetSymbolAddress((void**)&WkT, g_WkT);
    cudaGetSymbolAddress((void**)&WvT, g_WvT);    cudaGetSymbolAddress((void**)&WrT, g_WrT);
    cudaGetSymbolAddress((void**)&WoT, g_WoT);    cudaGetSymbolAddress((void**)&WiT, g_WiT);
    cudaGetSymbolAddress((void**)&WoutT, g_WoutT);

    const int M = B_ * S_;
    dim3 blk(256);
    const long long Z0 = 0;

    // fp16 conversions + weight transposes
    f2h_k<<<M * E_ / 1024, blk>>>(x, xh);
    f2h_k<<<B_ * R_ * E_ / 1024, blk>>>(rpe, rpeh);
    transpose_h16<<<dim3(32, 32),  dim3(32, 8)>>>(Wq,   WqT,   E_, NH_);
    transpose_h16<<<dim3(32, 32),  dim3(32, 8)>>>(Wk,   WkT,   E_, NH_);
    transpose_h16<<<dim3(32, 32),  dim3(32, 8)>>>(Wv,   WvT,   E_, NH_);
    transpose_h16<<<dim3(32, 32),  dim3(32, 8)>>>(Wr,   WrT,   E_, NH_);
    transpose_h16<<<dim3(32, 32),  dim3(32, 8)>>>(Wo,   WoT,   NH_, E_);
    transpose_h16<<<dim3(128, 32), dim3(32, 8)>>>(Wi,   WiT,   E_, F_);
    transpose_h16<<<dim3(32, 128), dim3(32, 8)>>>(Wout, WoutT, F_, E_);

    // projections (fp16 out)
    hgemm<128,2,4,0,1><<<dim3(8,32,1), blk>>>(xh, WqT, q, nullptr, E_, E_, E_, NH_,
        1, Z0,Z0,Z0,Z0,Z0,Z0, 0, 1.f);
    hgemm<128,2,4,0,1><<<dim3(8,32,1), blk>>>(xh, WkT, k, nullptr, E_, E_, E_, NH_,
        1, Z0,Z0,Z0,Z0,Z0,Z0, 0, 1.f);
    hgemm<128,2,4,0,1><<<dim3(8,32,1), blk>>>(xh, WvT, v, nullptr, E_, E_, E_, NH_,
        1, Z0,Z0,Z0,Z0,Z0,Z0, 0, 1.f);
    hgemm<128,2,4,0,1><<<dim3(8,64,1), blk>>>(rpeh, WrT, r, nullptr, E_, E_, E_, NH_,
        1, Z0,Z0,Z0,Z0,Z0,Z0, 0, 1.f);

    addbias_k<<<M * NH_ / 2 / 256, blk>>>(q, cb, pb, qc, qp);
    transpose_vh<<<dim3(S_/32, 2, B_*NHEADS), dim3(32,8)>>>(v, vt, S_);

    // content scores: A=qc[S,64], B=k[S,64] per head -> fp32 * 0.125
    hgemm<128,2,4,0,0><<<dim3(8,8,B_*NHEADS), blk>>>(
        qc, k, sc, nullptr, H_, NH_, NH_, S_, NHEADS,
        (long long)S_*NH_, (long long)H_,
        (long long)S_*NH_, (long long)H_,
        (long long)NHEADS*S_*S_, (long long)S_*S_, 0, 0.125f);

    // position scores (rel-shift scatter-add): A=qp[S,64], B=r[R,64]
    hgemm<128,2,4,1,0><<<dim3(16,8,B_*NHEADS), blk>>>(
        qp, r, sc, nullptr, H_, NH_, NH_, S_, NHEADS,
        (long long)S_*NH_, (long long)H_,
        (long long)R_*NH_, (long long)H_,
        (long long)NHEADS*S_*S_, (long long)S_*S_, 0, 0.125f);

    softmax_k<<<B_*NHEADS*S_, 256>>>(sc, sch);

    // attn = P @ V : A=probs[S,S] fp16, B=vt[H,S] fp16 -> attn fp16
    hgemm<64,4,2,0,1><<<dim3(1,8,B_*NHEADS), blk>>>(
        sch, vt, attn, nullptr, S_, S_, S_, NH_, NHEADS,
        (long long)NHEADS*S_*S_, (long long)S_*S_,
        (long long)NHEADS*H_*S_, (long long)H_*S_,
        (long long)S_*NH_, (long long)H_, 0, 1.f);

    // O projection + LN1
    hgemm<128,2,4,0,0><<<dim3(8,32,1), blk>>>(attn, WoT, tmp, nullptr, NH_, NH_, NH_, E_,
        1, Z0,Z0,Z0,Z0,Z0,Z0, 0, 1.f);
    ln_k<<<M, 256>>>(tmp, x, ln1g, ln1b, h1, h1h);

    // FFN
    hgemm<128,2,4,0,1><<<dim3(32,32,1), blk>>>(h1h, WiT, inner, bi, E_, E_, E_, F_,
        1, Z0,Z0,Z0,Z0,Z0,Z0, 1, 1.f);
    hgemm<128,2,4,0,0><<<dim3(8,32,1), blk>>>(inner, WoutT, tmp, bout, F_, F_, F_, E_,
        1, Z0,Z0,Z0,Z0,Z0,Z0, 0, 1.f);
    ln_k<<<M, 256>>>(tmp, h1, ln2g, ln2b, out, nullptr);
}

// round 6
// speedup vs baseline: 6.7652x; 1.6879x over previous
#include <cuda_runtime.h>
#include <cuda_fp16.h>
#include <math.h>
#include <stdint.h>

#define B_      4
#define S_      1024
#define E_      1024
#define NHEADS  16
#define H_      64
#define NH_     1024
#define F_      4096
#define R_      2048

// ---------------- scratch (static device globals) ----------------
__device__ __half g_xh[4194304];      // [B,S,E]
__device__ __half g_rpeh[8388608];    // [B,R,E]
__device__ __half g_q[4194304];
__device__ __half g_k[4194304];
__device__ __half g_v[4194304];
__device__ __half g_r[8388608];
__device__ __half g_qc[4194304];
__device__ __half g_qp[4194304];
__device__ __half g_vt[4194304];      // [B,N,H,S]
__device__ __half g_attn[4194304];
__device__ float  g_h1[4194304];
__device__ __half g_h1h[4194304];
__device__ __half g_inner[16777216];
__device__ float  g_tmp[4194304];
__device__ __half g_WqT[1048576];
__device__ __half g_WkT[1048576];
__device__ __half g_WvT[1048576];
__device__ __half g_WrT[1048576];
__device__ __half g_WoT[1048576];
__device__ __half g_WiT[4194304];
__device__ __half g_WoutT[4194304];

// ---------------- helpers ----------------
__device__ __forceinline__ uint32_t smem_u32(const void* p) {
    uint32_t a;
    asm("{ .reg .u64 t; cvta.to.shared.u64 t, %1; cvt.u32.u64 %0, t; }" : "=r"(a) : "l"(p));
    return a;
}
__device__ __forceinline__ void cpasync16(uint32_t s, const void* g) {
    asm volatile("cp.async.cg.shared.global [%0], [%1], 16;" :: "r"(s), "l"(g));
}
#define CP_COMMIT() asm volatile("cp.async.commit_group;" ::: "memory")
#define CP_WAIT(n)  asm volatile("cp.async.wait_group %0;" :: "n"(n) : "memory")

#define LDM4(r0, r1, r2, r3, a)                                                     \
    asm volatile("ldmatrix.sync.aligned.m8n8.x4.shared.b16 {%0,%1,%2,%3}, [%4];"    \
                 : "=r"(r0), "=r"(r1), "=r"(r2), "=r"(r3) : "r"(a))

#define MMA16816(c, a, b)                                                           \
    asm volatile("mma.sync.aligned.m16n8k16.row.col.f32.f16.f16.f32 "               \
                 "{%0,%1,%2,%3},{%4,%5,%6,%7},{%8,%9},{%0,%1,%2,%3};"               \
                 : "+f"((c)[0]), "+f"((c)[1]), "+f"((c)[2]), "+f"((c)[3])           \
                 : "r"((a)[0]), "r"((a)[1]), "r"((a)[2]), "r"((a)[3]),              \
                   "r"((b)[0]), "r"((b)[1]))

// ---------------- fp16 tensor-core GEMM (unchanged from R5) ---------------------
// C = A(MxK, K-major rows) * B(NxK, K-major rows)^T.  fp32 accumulate.
template<int BN, int WRM, int WRN, int OUTH>
__global__ __launch_bounds__(256, 2) void hgemm(
    const __half* __restrict__ A, const __half* __restrict__ Bm,
    void* __restrict__ Cv, const float* __restrict__ bias,
    int K, int lda, int ldb, int ldc, int zdiv,
    long long As1, long long As2, long long Bs1, long long Bs2,
    long long Cs1, long long Cs2, int relu, float scale)
{
    constexpr int BM = 128, LDS = 40;
    constexpr int MW = BM / WRM, NW = BN / WRN;
    constexpr int MT = MW / 16, NPAIR = NW / 16, NT = NW / 8;
    __shared__ __half sA[2][BM * LDS];
    __shared__ __half sB[2][BN * LDS];

    const int bm = blockIdx.y * BM, bn = blockIdx.x * BN;
    {
        int z = blockIdx.z, zq = z / zdiv, zr = z % zdiv;
        A  += zq * As1 + zr * As2;
        Bm += zq * Bs1 + zr * Bs2;
    }
    const int tid = threadIdx.x, lane = tid & 31, wid = tid >> 5;
    const int wm = (wid / WRN) * MW, wn = (wid % WRN) * NW;

    float cf[MT][NT][4];
#pragma unroll
    for (int i = 0; i < MT; i++)
#pragma unroll
        for (int j = 0; j < NT; j++)
#pragma unroll
            for (int e = 0; e < 4; e++) cf[i][j][e] = 0.f;

    auto stage = [&](int c, int buf) {
#pragma unroll
        for (int i = 0; i < BM * 4 / 256; i++) {
            int id = tid + i * 256, row = id >> 2, ch = id & 3;
            cpasync16(smem_u32(&sA[buf][row * LDS + ch * 8]),
                      A + (long long)(bm + row) * lda + c * 32 + ch * 8);
        }
#pragma unroll
        for (int i = 0; i < BN * 4 / 256; i++) {
            int id = tid + i * 256, row = id >> 2, ch = id & 3;
            cpasync16(smem_u32(&sB[buf][row * LDS + ch * 8]),
                      Bm + (long long)(bn + row) * ldb + c * 32 + ch * 8);
        }
        CP_COMMIT();
    };

    const int nkt = K >> 5;
    stage(0, 0);
    for (int c = 0; c < nkt; c++) {
        if (c + 1 < nkt) { stage(c + 1, (c + 1) & 1); CP_WAIT(1); }
        else             { CP_WAIT(0); }
        __syncthreads();
        const int buf = c & 1;
        const uint32_t a0 = smem_u32(&sA[buf][0]);
        const uint32_t b0 = smem_u32(&sB[buf][0]);
#pragma unroll
        for (int ks = 0; ks < 2; ks++) {
            uint32_t af[MT][4], bf[NT][2];
#pragma unroll
            for (int mt = 0; mt < MT; mt++) {
                uint32_t ad = a0 + ((wm + mt * 16 + (lane & 15)) * LDS
                                    + ks * 16 + (lane >> 4) * 8) * 2;
                LDM4(af[mt][0], af[mt][1], af[mt][2], af[mt][3], ad);
            }
#pragma unroll
            for (int p = 0; p < NPAIR; p++) {
                int rn = wn + p * 16 + (lane & 7) + ((lane >> 4) << 3);
                uint32_t bd = b0 + (rn * LDS + ks * 16 + ((lane >> 3) & 1) * 8) * 2;
                uint32_t r0, r1, r2, r3;
                LDM4(r0, r1, r2, r3, bd);
                bf[2 * p][0] = r0; bf[2 * p][1] = r1;
                bf[2 * p + 1][0] = r2; bf[2 * p + 1][1] = r3;
            }
#pragma unroll
            for (int mt = 0; mt < MT; mt++)
#pragma unroll
                for (int nt = 0; nt < NT; nt++)
                    MMA16816(cf[mt][nt], af[mt], bf[nt]);
        }
        __syncthreads();
    }

    long long coff;
    {
        int z = blockIdx.z, zq = z / zdiv, zr = z % zdiv;
        coff = zq * Cs1 + zr * Cs2;
    }
#pragma unroll
    for (int mt = 0; mt < MT; mt++) {
#pragma unroll
        for (int nt = 0; nt < NT; nt++) {
            int r = bm + wm + mt * 16 + (lane >> 2);
            int col = bn + wn + nt * 8 + (lane & 3) * 2;
            float v0 = cf[mt][nt][0] * scale, v1 = cf[mt][nt][1] * scale;
            float v2 = cf[mt][nt][2] * scale, v3 = cf[mt][nt][3] * scale;
            if (bias) {
                float b0v = bias[col], b1v = bias[col + 1];
                v0 += b0v; v1 += b1v; v2 += b0v; v3 += b1v;
            }
            if (relu) {
                v0 = fmaxf(v0, 0.f); v1 = fmaxf(v1, 0.f);
                v2 = fmaxf(v2, 0.f); v3 = fmaxf(v3, 0.f);
            }
            if (OUTH) {
                __half* Ch = (__half*)Cv + coff;
                *(__half2*)(Ch + (long long)r * ldc + col) = __floats2half2_rn(v0, v1);
                *(__half2*)(Ch + (long long)(r + 8) * ldc + col) = __floats2half2_rn(v2, v3);
            } else {
                float* Cf = (float*)Cv + coff;
                *(float2*)(Cf + (long long)r * ldc + col) = make_float2(v0, v1);
                *(float2*)(Cf + (long long)(r + 8) * ldc + col) = make_float2(v2, v3);
            }
        }
    }
}

// ---------------- flash attention with folded Transformer-XL rel-shift ----------
// One block = (i-tile of 128 rows, head z). Streams 8 j-tiles: content mma +
// banded position mma (shift folded as register->smem scatter-add), online
// softmax, PV mma. Writes attn [B,S,NH] fp16. No scores in DRAM.
#define LDQ_  72
#define LDV_  136
#define LDS_S 132
#define LDP_  136
#define FL_SMEM (3*128*LDQ_*2 + 64*LDV_*2 + 256*LDQ_*2 + 128*LDS_S*4 + 128*LDP_*2 + 3*128*4)

__global__ __launch_bounds__(256, 1) void flash_k(
    const __half* __restrict__ qc, const __half* __restrict__ qp,
    const __half* __restrict__ kk, const __half* __restrict__ vt,
    const __half* __restrict__ rr, __half* __restrict__ attn)
{
    extern __shared__ char smraw[];
    __half* sQc = (__half*)smraw;
    __half* sQp = sQc + 128 * LDQ_;
    __half* sK  = sQp + 128 * LDQ_;
    __half* sV  = sK  + 128 * LDQ_;
    __half* sR  = sV  + 64 * LDV_;
    float*  sS  = (float*)(sR + 256 * LDQ_);
    __half* sP  = (__half*)(sS + 128 * LDS_S);
    float*  sM  = (float*)(sP + 128 * LDP_);
    float*  sL  = sM + 128;
    float*  sAl = sL + 128;

    const int it = blockIdx.x, z = blockIdx.y;
    const int b = z >> 4, n = z & 15;
    const int i0 = it * 128;
    const int tid = threadIdx.x, lane = tid & 31, wid = tid >> 5;
    const int wm = wid * 16;

    const __half* qcb = qc + (long long)b * S_ * NH_ + n * H_;
    const __half* qpb = qp + (long long)b * S_ * NH_ + n * H_;
    const __half* kb  = kk + (long long)b * S_ * NH_ + n * H_;
    const __half* vtb = vt + (long long)z * H_ * S_;
    const __half* rb  = rr + (long long)b * R_ * NH_ + n * H_;

    // stage Q tiles once
#pragma unroll
    for (int i = 0; i < 4; i++) {
        int id = tid + i * 256, row = id >> 3, ch = id & 7;
        cpasync16(smem_u32(sQc + row * LDQ_ + ch * 8),
                  qcb + (long long)(i0 + row) * NH_ + ch * 8);
        cpasync16(smem_u32(sQp + row * LDQ_ + ch * 8),
                  qpb + (long long)(i0 + row) * NH_ + ch * 8);
    }
    CP_COMMIT();
    if (tid < 128) { sM[tid] = -1e30f; sL[tid] = 0.f; }
    CP_WAIT(0);
    __syncthreads();

    float of[8][4];
#pragma unroll
    for (int nt = 0; nt < 8; nt++)
#pragma unroll
        for (int e = 0; e < 4; e++) of[nt][e] = 0.f;

    const uint32_t aQc = smem_u32(sQc), aQp = smem_u32(sQp);
    const uint32_t aK = smem_u32(sK), aV = smem_u32(sV);
    const uint32_t aR = smem_u32(sR), aP = smem_u32(sP);

    for (int jt = 0; jt < 8; jt++) {
        const int j0 = jt * 128;
        const int base = S_ + j0 - i0 - 127;

        // stage K, V, R for this j-tile
#pragma unroll
        for (int i = 0; i < 4; i++) {
            int id = tid + i * 256, row = id >> 3, ch = id & 7;
            cpasync16(smem_u32(sK + row * LDQ_ + ch * 8),
                      kb + (long long)(j0 + row) * NH_ + ch * 8);
        }
#pragma unroll
        for (int i = 0; i < 4; i++) {
            int id = tid + i * 256, row = id >> 4, ch = id & 15;
            cpasync16(smem_u32(sV + row * LDV_ + ch * 8),
                      vtb + (long long)row * S_ + j0 + ch * 8);
        }
#pragma unroll
        for (int i = 0; i < 8; i++) {
            int id = tid + i * 256, row = id >> 3, ch = id & 7;
            int grow = base + row; grow = grow < R_ ? grow : R_ - 1;
            cpasync16(smem_u32(sR + row * LDQ_ + ch * 8),
                      rb + (long long)grow * NH_ + ch * 8);
        }
        CP_COMMIT();
        CP_WAIT(0);
        __syncthreads();

        // ---- content scores -> sS (store) ----
        float cf[16][4];
#pragma unroll
        for (int nt = 0; nt < 16; nt++)
#pragma unroll
            for (int e = 0; e < 4; e++) cf[nt][e] = 0.f;
#pragma unroll
        for (int ks = 0; ks < 4; ks++) {
            uint32_t af[4], bf[16][2];
            LDM4(af[0], af[1], af[2], af[3],
                 aQc + ((wm + (lane & 15)) * LDQ_ + ks * 16 + (lane >> 4) * 8) * 2);
#pragma unroll
            for (int p = 0; p < 8; p++) {
                int rn = p * 16 + (lane & 7) + ((lane >> 4) << 3);
                uint32_t r0, r1, r2, r3;
                LDM4(r0, r1, r2, r3, aK + (rn * LDQ_ + ks * 16 + ((lane >> 3) & 1) * 8) * 2);
                bf[2 * p][0] = r0; bf[2 * p][1] = r1;
                bf[2 * p + 1][0] = r2; bf[2 * p + 1][1] = r3;
            }
#pragma unroll
            for (int nt = 0; nt < 16; nt++) MMA16816(cf[nt], af, bf[nt]);
        }
#pragma unroll
        for (int nt = 0; nt < 16; nt++) {
            int c0 = nt * 8 + (lane & 3) * 2;
#pragma unroll
            for (int e2 = 0; e2 < 2; e2++) {
                int row = wm + (lane >> 2) + 8 * e2;
                *(float2*)&sS[row * LDS_S + c0] = make_float2(cf[nt][e2 * 2], cf[nt][e2 * 2 + 1]);
            }
        }
        __syncwarp();

        // ---- position scores, shift folded: sS[li][g-127+li] += raw[li][g] ----
#pragma unroll
        for (int halfg = 0; halfg < 2; halfg++) {
            int g0 = halfg * 128;
#pragma unroll
            for (int nt = 0; nt < 16; nt++)
#pragma unroll
                for (int e = 0; e < 4; e++) cf[nt][e] = 0.f;
#pragma unroll
            for (int ks = 0; ks < 4; ks++) {
                uint32_t af[4], bf[16][2];
                LDM4(af[0], af[1], af[2], af[3],
                     aQp + ((wm + (lane & 15)) * LDQ_ + ks * 16 + (lane >> 4) * 8) * 2);
#pragma unroll
                for (int p = 0; p < 8; p++) {
                    int rn = g0 + p * 16 + (lane & 7) + ((lane >> 4) << 3);
                    uint32_t r0, r1, r2, r3;
                    LDM4(r0, r1, r2, r3, aR + (rn * LDQ_ + ks * 16 + ((lane >> 3) & 1) * 8) * 2);
                    bf[2 * p][0] = r0; bf[2 * p][1] = r1;
                    bf[2 * p + 1][0] = r2; bf[2 * p + 1][1] = r3;
                }
#pragma unroll
                for (int nt = 0; nt < 16; nt++) MMA16816(cf[nt], af, bf[nt]);
            }
#pragma unroll
            for (int nt = 0; nt < 16; nt++) {
#pragma unroll
                for (int e = 0; e < 4; e++) {
                    int li = wm + (lane >> 2) + 8 * (e >> 1);
                    int g  = g0 + nt * 8 + (lane & 3) * 2 + (e & 1);
                    int lj = g - 127 + li;
                    if (lj >= 0 && lj < 128) sS[li * LDS_S + lj] += cf[nt][e];
                }
            }
            __syncwarp();
        }

        // ---- online softmax over this 128-col slab (warp-local rows) ----
        {
            int rloc = wm + (lane >> 1), hf = lane & 1;
            float* srow = &sS[rloc * LDS_S + hf * 64];
            float mx = -1e30f;
#pragma unroll
            for (int c = 0; c < 64; c++) mx = fmaxf(mx, srow[c]);
            mx = fmaxf(mx, __shfl_xor_sync(0xffffffffu, mx, 1));
            mx *= 0.125f;
            float mold = sM[rloc];
            float mnew = fmaxf(mold, mx);
            float alpha = __expf(mold - mnew);
            float sum = 0.f;
            __half* prow = &sP[rloc * LDP_ + hf * 64];
#pragma unroll
            for (int c = 0; c < 64; c += 2) {
                float p0 = __expf(srow[c] * 0.125f - mnew);
                float p1 = __expf(srow[c + 1] * 0.125f - mnew);
                sum += p0 + p1;
                *(__half2*)&prow[c] = __floats2half2_rn(p0, p1);
            }
            sum += __shfl_xor_sync(0xffffffffu, sum, 1);
            if (hf == 0) {
                sL[rloc] = sL[rloc] * alpha + sum;
                sM[rloc] = mnew;
                sAl[rloc] = alpha;
            }
        }
        __syncwarp();

        // ---- rescale O, then PV mma ----
#pragma unroll
        for (int e2 = 0; e2 < 2; e2++) {
            float al = sAl[wm + (lane >> 2) + 8 * e2];
#pragma unroll
            for (int nt = 0; nt < 8; nt++) {
                of[nt][e2 * 2]     *= al;
                of[nt][e2 * 2 + 1] *= al;
            }
        }
#pragma unroll
        for (int ks = 0; ks < 8; ks++) {
            uint32_t af[4], bfv[8][2];
            LDM4(af[0], af[1], af[2], af[3],
                 aP + ((wm + (lane & 15)) * LDP_ + ks * 16 + (lane >> 4) * 8) * 2);
#pragma unroll
            for (int p = 0; p < 4; p++) {
                int rn = p * 16 + (lane & 7) + ((lane >> 4) << 3);
                uint32_t r0, r1, r2, r3;
                LDM4(r0, r1, r2, r3, aV + (rn * LDV_ + ks * 16 + ((lane >> 3) & 1) * 8) * 2);
                bfv[2 * p][0] = r0; bfv[2 * p][1] = r1;
                bfv[2 * p + 1][0] = r2; bfv[2 * p + 1][1] = r3;
            }
#pragma unroll
            for (int nt = 0; nt < 8; nt++) MMA16816(of[nt], af, bfv[nt]);
        }
        __syncthreads();   // protect staging buffers before next j-tile
    }

    // ---- final: O / l -> attn fp16 ----
#pragma unroll
    for (int e2 = 0; e2 < 2; e2++) {
        int li = wm + (lane >> 2) + 8 * e2;
        float inv = 1.0f / sL[li];
        long long rowg = (long long)(b * S_ + i0 + li) * NH_ + n * H_;
#pragma unroll
        for (int nt = 0; nt < 8; nt++) {
            int col = nt * 8 + (lane & 3) * 2;
            *(__half2*)(attn + rowg + col) =
                __floats2half2_rn(of[nt][e2 * 2] * inv, of[nt][e2 * 2 + 1] * inv);
        }
    }
}

// ---------------- fp32 -> fp16 copy ----------------
__global__ __launch_bounds__(256) void f2h_k(const float* __restrict__ in,
                                             __half* __restrict__ out)
{
    long long i = (long long)blockIdx.x * 256 + threadIdx.x;
    float4 v = ((const float4*)in)[i];
    ((__half2*)out)[i * 2]     = __floats2half2_rn(v.x, v.y);
    ((__half2*)out)[i * 2 + 1] = __floats2half2_rn(v.z, v.w);
}

// ---------------- fp32 transpose -> fp16 ----------------
__global__ void transpose_h16(const float* __restrict__ in, __half* __restrict__ out,
                              int rows, int cols)
{
    __shared__ float tile[32][33];
    int r0 = blockIdx.y * 32, c0 = blockIdx.x * 32;
    int tx = threadIdx.x, ty = threadIdx.y;
#pragma unroll
    for (int i = 0; i < 4; i++)
        tile[ty + i * 8][tx] = in[(long long)(r0 + ty + i * 8) * cols + c0 + tx];
    __syncthreads();
#pragma unroll
    for (int i = 0; i < 4; i++)
        out[(long long)(c0 + ty + i * 8) * rows + r0 + tx] = __float2half_rn(tile[tx][ty + i * 8]);
}

// ---------------- per-head half transpose: [B,rows,N,H] -> [B,N,H,rows] ---------
__global__ void transpose_vh(const __half* __restrict__ in, __half* __restrict__ out, int rows)
{
    __shared__ __half tile[32][34];
    int z = blockIdx.z, b = z >> 4, n = z & 15;
    const __half* ip = in + (long long)b * rows * NH_ + n * H_;
    __half* op = out + (long long)z * H_ * rows;
    int r0 = blockIdx.x * 32, h0 = blockIdx.y * 32;
    int tx = threadIdx.x, ty = threadIdx.y;
#pragma unroll
    for (int i = 0; i < 4; i++)
        tile[ty + i * 8][tx] = ip[(long long)(r0 + ty + i * 8) * NH_ + h0 + tx];
    __syncthreads();
#pragma unroll
    for (int i = 0; i < 4; i++)
        op[(long long)(h0 + ty + i * 8) * rows + r0 + tx] = tile[tx][ty + i * 8];
}

// ---------------- q(half) + biases(fp32) -> qc, qp (half) -----------------------
__global__ __launch_bounds__(256) void addbias_k(
    const __half* __restrict__ q, const float* __restrict__ cb,
    const float* __restrict__ pb, __half* __restrict__ qc, __half* __restrict__ qp)
{
    long long i = (long long)blockIdx.x * 256 + threadIdx.x;
    float2 v = __half22float2(((const __half2*)q)[i]);
    int cp2 = (int)(i & (NH_ / 2 - 1));
    float2 c = ((const float2*)cb)[cp2];
    float2 p = ((const float2*)pb)[cp2];
    ((__half2*)qc)[i] = __floats2half2_rn(v.x + c.x, v.y + c.y);
    ((__half2*)qp)[i] = __floats2half2_rn(v.x + p.x, v.y + p.y);
}

// ---------------- residual + LayerNorm (optional fp16 copy) ---------------------
__global__ __launch_bounds__(256) void ln_k(
    const float* __restrict__ a, const float* __restrict__ res,
    const float* __restrict__ g, const float* __restrict__ bt,
    float* __restrict__ o, __half* __restrict__ oh)
{
    __shared__ float red[16];
    long long row = blockIdx.x;
    int t = threadIdx.x;
    float4 va = *((const float4*)(a + row * 1024) + t);
    float4 vr = *((const float4*)(res + row * 1024) + t);
    float4 x;
    x.x = va.x + vr.x; x.y = va.y + vr.y; x.z = va.z + vr.z; x.w = va.w + vr.w;
    float s  = x.x + x.y + x.z + x.w;
    float q2 = x.x * x.x + x.y * x.y + x.z * x.z + x.w * x.w;
#pragma unroll
    for (int off = 16; off; off >>= 1) {
        s  += __shfl_xor_sync(0xffffffffu, s, off);
        q2 += __shfl_xor_sync(0xffffffffu, q2, off);
    }
    if ((t & 31) == 0) { red[t >> 5] = s; red[8 + (t >> 5)] = q2; }
    __syncthreads();
    if (t == 0) {
        float ss = red[0], qq = red[8];
#pragma unroll
        for (int i = 1; i < 8; i++) { ss += red[i]; qq += red[8 + i]; }
        red[0] = ss; red[8] = qq;
    }
    __syncthreads();
    float mu  = red[0] * (1.f / 1024.f);
    float var = red[8] * (1.f / 1024.f) - mu * mu;
    float rs = rsqrtf(var + 1e-12f);
    float4 gg = *((const float4*)g + t);
    float4 bb = *((const float4*)bt + t);
    float4 y;
    y.x = (x.x - mu) * rs * gg.x + bb.x;
    y.y = (x.y - mu) * rs * gg.y + bb.y;
    y.z = (x.z - mu) * rs * gg.z + bb.z;
    y.w = (x.w - mu) * rs * gg.w + bb.w;
    *((float4*)(o + row * 1024) + t) = y;
    if (oh) {
        __half2* ph = (__half2*)(oh + row * 1024);
        ph[2 * t]     = __floats2half2_rn(y.x, y.y);
        ph[2 * t + 1] = __floats2half2_rn(y.z, y.w);
    }
}

// ---------------- driver --------------------------------------------------------
extern "C" void kernel_launch(void* const* d_in, const int* in_sizes, int n_in,
                              void* d_out, int out_size)
{
    const float* x    = (const float*)d_in[0];
    const float* cb   = (const float*)d_in[1];
    const float* pb   = (const float*)d_in[2];
    const float* rpe  = (const float*)d_in[3];
    const float* Wq   = (const float*)d_in[4];
    const float* Wk   = (const float*)d_in[5];
    const float* Wv   = (const float*)d_in[6];
    const float* Wr   = (const float*)d_in[7];
    const float* Wo   = (const float*)d_in[8];
    const float* ln1g = (const float*)d_in[9];
    const float* ln1b = (const float*)d_in[10];
    const float* Wi   = (const float*)d_in[11];
    const float* bi   = (const float*)d_in[12];
    const float* Wout = (const float*)d_in[13];
    const float* bout = (const float*)d_in[14];
    const float* ln2g = (const float*)d_in[15];
    const float* ln2b = (const float*)d_in[16];
    float* out = (float*)d_out;

    __half *xh,*rpeh,*q,*k,*v,*r,*qc,*qp,*vt,*attn,*h1h,*inner;
    __half *WqT,*WkT,*WvT,*WrT,*WoT,*WiT,*WoutT;
    float *h1,*tmp;
    cudaGetSymbolAddress((void**)&xh, g_xh);      cudaGetSymbolAddress((void**)&rpeh, g_rpeh);
    cudaGetSymbolAddress((void**)&q, g_q);        cudaGetSymbolAddress((void**)&k, g_k);
    cudaGetSymbolAddress((void**)&v, g_v);        cudaGetSymbolAddress((void**)&r, g_r);
    cudaGetSymbolAddress((void**)&qc, g_qc);      cudaGetSymbolAddress((void**)&qp, g_qp);
    cudaGetSymbolAddress((void**)&vt, g_vt);      cudaGetSymbolAddress((void**)&attn, g_attn);
    cudaGetSymbolAddress((void**)&h1, g_h1);      cudaGetSymbolAddress((void**)&h1h, g_h1h);
    cudaGetSymbolAddress((void**)&inner, g_inner);cudaGetSymbolAddress((void**)&tmp, g_tmp);
    cudaGetSymbolAddress((void**)&WqT, g_WqT);    cudaGetSymbolAddress((void**)&WkT, g_WkT);
    cudaGetSymbolAddress((void**)&WvT, g_WvT);    cudaGetSymbolAddress((void**)&WrT, g_WrT);
    cudaGetSymbolAddress((void**)&WoT, g_WoT);    cudaGetSymbolAddress((void**)&WiT, g_WiT);
    cudaGetSymbolAddress((void**)&WoutT, g_WoutT);

    cudaFuncSetAttribute(flash_k, cudaFuncAttributeMaxDynamicSharedMemorySize, FL_SMEM);

    const int M = B_ * S_;
    dim3 blk(256);
    const long long Z0 = 0;

    f2h_k<<<M * E_ / 1024, blk>>>(x, xh);
    f2h_k<<<B_ * R_ * E_ / 1024, blk>>>(rpe, rpeh);
    transpose_h16<<<dim3(32, 32),  dim3(32, 8)>>>(Wq,   WqT,   E_, NH_);
    transpose_h16<<<dim3(32, 32),  dim3(32, 8)>>>(Wk,   WkT,   E_, NH_);
    transpose_h16<<<dim3(32, 32),  dim3(32, 8)>>>(Wv,   WvT,   E_, NH_);
    transpose_h16<<<dim3(32, 32),  dim3(32, 8)>>>(Wr,   WrT,   E_, NH_);
    transpose_h16<<<dim3(32, 32),  dim3(32, 8)>>>(Wo,   WoT,   NH_, E_);
    transpose_h16<<<dim3(128, 32), dim3(32, 8)>>>(Wi,   WiT,   E_, F_);
    transpose_h16<<<dim3(32, 128), dim3(32, 8)>>>(Wout, WoutT, F_, E_);

    // projections (fp16 out)
    hgemm<128,2,4,1><<<dim3(8,32,1), blk>>>(xh, WqT, q, nullptr, E_, E_, E_, NH_,
        1, Z0,Z0,Z0,Z0,Z0,Z0, 0, 1.f);
    hgemm<128,2,4,1><<<dim3(8,32,1), blk>>>(xh, WkT, k, nullptr, E_, E_, E_, NH_,
        1, Z0,Z0,Z0,Z0,Z0,Z0, 0, 1.f);
    hgemm<128,2,4,1><<<dim3(8,32,1), blk>>>(xh, WvT, v, nullptr, E_, E_, E_, NH_,
        1, Z0,Z0,Z0,Z0,Z0,Z0, 0, 1.f);
    hgemm<128,2,4,1><<<dim3(8,64,1), blk>>>(rpeh, WrT, r, nullptr, E_, E_, E_, NH_,
        1, Z0,Z0,Z0,Z0,Z0,Z0, 0, 1.f);

    addbias_k<<<M * NH_ / 2 / 256, blk>>>(q, cb, pb, qc, qp);
    transpose_vh<<<dim3(S_/32, 2, B_*NHEADS), dim3(32,8)>>>(v, vt, S_);

    // fused attention (content + rel-shifted position + softmax + PV)
    flash_k<<<dim3(8, B_ * NHEADS), blk, FL_SMEM>>>(qc, qp, k, vt, r, attn);

    // O projection + LN1
    hgemm<128,2,4,0><<<dim3(8,32,1), blk>>>(attn, WoT, tmp, nullptr, NH_, NH_, NH_, E_,
        1, Z0,Z0,Z0,Z0,Z0,Z0, 0, 1.f);
    ln_k<<<M, 256>>>(tmp, x, ln1g, ln1b, h1, h1h);

    // FFN
    hgemm<128,2,4,1><<<dim3(32,32,1), blk>>>(h1h, WiT, inner, bi, E_, E_, E_, F_,
        1, Z0,Z0,Z0,Z0,Z0,Z0, 1, 1.f);
    hgemm<128,2,4,0><<<dim3(8,32,1), blk>>>(inner, WoutT, tmp, bout, F_, F_, F_, E_,
        1, Z0,Z0,Z0,Z0,Z0,Z0, 0, 1.f);
    ln_k<<<M, 256>>>(tmp, h1, ln2g, ln2b, out, nullptr);
}

// round 7
// speedup vs baseline: 7.1608x; 1.0585x over previous
#include <cuda_runtime.h>
#include <cuda_fp16.h>
#include <math.h>
#include <stdint.h>

#define B_      4
#define S_      1024
#define E_      1024
#define NHEADS  16
#define H_      64
#define NH_     1024
#define F_      4096
#define R_      2048

// ---------------- scratch (static device globals) ----------------
__device__ __half g_xh[4194304];       // [B,S,E]
__device__ __half g_rpeh[8388608];     // [B,R,E]
__device__ __half g_qkv[12582912];     // [B,S,3NH]: cols 1024..2047=K, 2048..3071=V
__device__ __half g_qc[4194304];
__device__ __half g_qp[4194304];
__device__ __half g_r[8388608];
__device__ __half g_vt[4194304];       // [B,N,H,S]
__device__ __half g_attn[4194304];
__device__ float  g_h1[4194304];
__device__ __half g_h1h[4194304];
__device__ __half g_inner[16777216];
__device__ float  g_tmp[4194304];
__device__ __half g_WqkvT[3145728];    // [3NH, E]
__device__ __half g_WrT[1048576];
__device__ __half g_WoT[1048576];
__device__ __half g_WiT[4194304];
__device__ __half g_WoutT[4194304];

// ---------------- helpers ----------------
__device__ __forceinline__ uint32_t smem_u32(const void* p) {
    uint32_t a;
    asm("{ .reg .u64 t; cvta.to.shared.u64 t, %1; cvt.u32.u64 %0, t; }" : "=r"(a) : "l"(p));
    return a;
}
__device__ __forceinline__ void cpasync16(uint32_t s, const void* g) {
    asm volatile("cp.async.cg.shared.global [%0], [%1], 16;" :: "r"(s), "l"(g));
}
#define CP_COMMIT() asm volatile("cp.async.commit_group;" ::: "memory")
#define CP_WAIT(n)  asm volatile("cp.async.wait_group %0;" :: "n"(n) : "memory")

#define LDM4(r0, r1, r2, r3, a)                                                     \
    asm volatile("ldmatrix.sync.aligned.m8n8.x4.shared.b16 {%0,%1,%2,%3}, [%4];"    \
                 : "=r"(r0), "=r"(r1), "=r"(r2), "=r"(r3) : "r"(a))

#define MMA16816(c, a, b)                                                           \
    asm volatile("mma.sync.aligned.m16n8k16.row.col.f32.f16.f16.f32 "               \
                 "{%0,%1,%2,%3},{%4,%5,%6,%7},{%8,%9},{%0,%1,%2,%3};"               \
                 : "+f"((c)[0]), "+f"((c)[1]), "+f"((c)[2]), "+f"((c)[3])           \
                 : "r"((a)[0]), "r"((a)[1]), "r"((a)[2]), "r"((a)[3]),              \
                   "r"((b)[0]), "r"((b)[1]))

// ---------------- fp16 tensor-core GEMM, 3-stage pipeline -----------------------
// C = A(MxK, K-major rows) * B(NxK, K-major rows)^T.  fp32 accumulate.
// EPI 0: store (+bias/relu/scale), OUTH picks half/float.
// EPI 2: QKV epilogue — col<NH_: qc=v+cb, qp=v+pb (half); else store half to C.
#define HG_SMEM (3 * (128 + 128) * 40 * 2)
template<int BN, int WRM, int WRN, int EPI, int OUTH>
__global__ __launch_bounds__(256, 2) void hgemm(
    const __half* __restrict__ A, const __half* __restrict__ Bm,
    void* __restrict__ Cv, const float* __restrict__ bias,
    const float* __restrict__ pb, __half* __restrict__ qcp, __half* __restrict__ qpp,
    int K, int lda, int ldb, int ldc, int zdiv,
    long long As1, long long As2, long long Bs1, long long Bs2,
    long long Cs1, long long Cs2, int relu, float scale)
{
    constexpr int BM = 128, LDS = 40;
    constexpr int MW = BM / WRM, NW = BN / WRN;
    constexpr int MT = MW / 16, NPAIR = NW / 16, NT = NW / 8;
    extern __shared__ __half hsm[];
    __half* sA = hsm;                       // [3][BM*LDS]
    __half* sB = hsm + 3 * BM * LDS;        // [3][BN*LDS]

    const int bm = blockIdx.y * BM, bn = blockIdx.x * BN;
    {
        int z = blockIdx.z, zq = z / zdiv, zr = z % zdiv;
        A  += zq * As1 + zr * As2;
        Bm += zq * Bs1 + zr * Bs2;
    }
    const int tid = threadIdx.x, lane = tid & 31, wid = tid >> 5;
    const int wm = (wid / WRN) * MW, wn = (wid % WRN) * NW;

    float cf[MT][NT][4];
#pragma unroll
    for (int i = 0; i < MT; i++)
#pragma unroll
        for (int j = 0; j < NT; j++)
#pragma unroll
            for (int e = 0; e < 4; e++) cf[i][j][e] = 0.f;

    auto stage = [&](int c, int sx) {
        __half* dA = sA + sx * BM * LDS;
        __half* dB = sB + sx * BN * LDS;
#pragma unroll
        for (int i = 0; i < BM * 4 / 256; i++) {
            int id = tid + i * 256, row = id >> 2, ch = id & 3;
            cpasync16(smem_u32(dA + row * LDS + ch * 8),
                      A + (long long)(bm + row) * lda + c * 32 + ch * 8);
        }
#pragma unroll
        for (int i = 0; i < BN * 4 / 256; i++) {
            int id = tid + i * 256, row = id >> 2, ch = id & 3;
            cpasync16(smem_u32(dB + row * LDS + ch * 8),
                      Bm + (long long)(bn + row) * ldb + c * 32 + ch * 8);
        }
        CP_COMMIT();
    };

    const int nkt = K >> 5;                 // always >= 32 at our call sites
    stage(0, 0);
    stage(1, 1);
    int cbuf = 0, pbuf = 2;                 // compute buf, prefetch buf
    for (int c = 0; c < nkt; c++) {
        CP_WAIT(1);                          // chunk c staged
        __syncthreads();                     // all warps finished chunk c-1
        if (c + 2 < nkt) stage(c + 2, pbuf);
        else CP_COMMIT();
        const uint32_t a0 = smem_u32(sA + cbuf * BM * LDS);
        const uint32_t b0 = smem_u32(sB + cbuf * BN * LDS);
#pragma unroll
        for (int ks = 0; ks < 2; ks++) {
            uint32_t af[MT][4], bf[NT][2];
#pragma unroll
            for (int mt = 0; mt < MT; mt++) {
                uint32_t ad = a0 + ((wm + mt * 16 + (lane & 15)) * LDS
                                    + ks * 16 + (lane >> 4) * 8) * 2;
                LDM4(af[mt][0], af[mt][1], af[mt][2], af[mt][3], ad);
            }
#pragma unroll
            for (int p = 0; p < NPAIR; p++) {
                int rn = wn + p * 16 + (lane & 7) + ((lane >> 4) << 3);
                uint32_t bd = b0 + (rn * LDS + ks * 16 + ((lane >> 3) & 1) * 8) * 2;
                uint32_t r0, r1, r2, r3;
                LDM4(r0, r1, r2, r3, bd);
                bf[2 * p][0] = r0; bf[2 * p][1] = r1;
                bf[2 * p + 1][0] = r2; bf[2 * p + 1][1] = r3;
            }
#pragma unroll
            for (int mt = 0; mt < MT; mt++)
#pragma unroll
                for (int nt = 0; nt < NT; nt++)
                    MMA16816(cf[mt][nt], af[mt], bf[nt]);
        }
        cbuf = cbuf == 2 ? 0 : cbuf + 1;
        pbuf = pbuf == 2 ? 0 : pbuf + 1;
    }

    long long coff;
    {
        int z = blockIdx.z, zq = z / zdiv, zr = z % zdiv;
        coff = zq * Cs1 + zr * Cs2;
    }
#pragma unroll
    for (int mt = 0; mt < MT; mt++) {
#pragma unroll
        for (int nt = 0; nt < NT; nt++) {
            int r = bm + wm + mt * 16 + (lane >> 2);
            int col = bn + wn + nt * 8 + (lane & 3) * 2;
#pragma unroll
            for (int e2 = 0; e2 < 2; e2++) {
                int row = r + 8 * e2;
                float v0 = cf[mt][nt][e2 * 2] * scale;
                float v1 = cf[mt][nt][e2 * 2 + 1] * scale;
                if (EPI == 2) {
                    if (col < NH_) {
                        float c0 = bias[col], c1 = bias[col + 1];
                        float p0 = pb[col],  p1 = pb[col + 1];
                        *(__half2*)(qcp + (long long)row * NH_ + col) =
                            __floats2half2_rn(v0 + c0, v1 + c1);
                        *(__half2*)(qpp + (long long)row * NH_ + col) =
                            __floats2half2_rn(v0 + p0, v1 + p1);
                    } else {
                        __half* Ch = (__half*)Cv;
                        *(__half2*)(Ch + (long long)row * ldc + col) =
                            __floats2half2_rn(v0, v1);
                    }
                } else {
                    if (bias) { v0 += bias[col]; v1 += bias[col + 1]; }
                    if (relu) { v0 = fmaxf(v0, 0.f); v1 = fmaxf(v1, 0.f); }
                    if (OUTH) {
                        __half* Ch = (__half*)Cv + coff;
                        *(__half2*)(Ch + (long long)row * ldc + col) =
                            __floats2half2_rn(v0, v1);
                    } else {
                        float* Cf = (float*)Cv + coff;
                        *(float2*)(Cf + (long long)row * ldc + col) = make_float2(v0, v1);
                    }
                }
            }
        }
    }
}

// ---------------- flash attention with folded rel-shift + band tile-skip --------
#define LDQ_  72
#define LDV_  136
#define LDS_S 132
#define LDP_  136
#define FL_SMEM (3*128*LDQ_*2 + 64*LDV_*2 + 256*LDQ_*2 + 128*LDS_S*4 + 128*LDP_*2 + 3*128*4)

__global__ __launch_bounds__(256, 1) void flash_k(
    const __half* __restrict__ qc, const __half* __restrict__ qp,
    const __half* __restrict__ kk, const __half* __restrict__ vt,
    const __half* __restrict__ rr, __half* __restrict__ attn, int kstr)
{
    extern __shared__ char smraw[];
    __half* sQc = (__half*)smraw;
    __half* sQp = sQc + 128 * LDQ_;
    __half* sK  = sQp + 128 * LDQ_;
    __half* sV  = sK  + 128 * LDQ_;
    __half* sR  = sV  + 64 * LDV_;
    float*  sS  = (float*)(sR + 256 * LDQ_);
    __half* sP  = (__half*)(sS + 128 * LDS_S);
    float*  sM  = (float*)(sP + 128 * LDP_);
    float*  sL  = sM + 128;
    float*  sAl = sL + 128;

    const int it = blockIdx.x, z = blockIdx.y;
    const int b = z >> 4, n = z & 15;
    const int i0 = it * 128;
    const int tid = threadIdx.x, lane = tid & 31, wid = tid >> 5;
    const int wm = wid * 16;

    // band-valid pos n-tiles for this warp: g in [112-wm, 254-wm]
    int ntlo0 = (105 - wm + 7) >> 3; if (ntlo0 < 0) ntlo0 = 0;   // half0: nt in [ntlo0,15]
    int nthi1 = (126 - wm) >> 3;                                  // half1: nt in [0,nthi1]

    const __half* qcb = qc + (long long)b * S_ * NH_ + n * H_;
    const __half* qpb = qp + (long long)b * S_ * NH_ + n * H_;
    const __half* kb  = kk + (long long)b * S_ * kstr + n * H_;
    const __half* vtb = vt + (long long)z * H_ * S_;
    const __half* rb  = rr + (long long)b * R_ * NH_ + n * H_;

#pragma unroll
    for (int i = 0; i < 4; i++) {
        int id = tid + i * 256, row = id >> 3, ch = id & 7;
        cpasync16(smem_u32(sQc + row * LDQ_ + ch * 8),
                  qcb + (long long)(i0 + row) * NH_ + ch * 8);
        cpasync16(smem_u32(sQp + row * LDQ_ + ch * 8),
                  qpb + (long long)(i0 + row) * NH_ + ch * 8);
    }
    CP_COMMIT();
    if (tid < 128) { sM[tid] = -1e30f; sL[tid] = 0.f; }
    CP_WAIT(0);
    __syncthreads();

    float of[8][4];
#pragma unroll
    for (int nt = 0; nt < 8; nt++)
#pragma unroll
        for (int e = 0; e < 4; e++) of[nt][e] = 0.f;

    const uint32_t aQc = smem_u32(sQc), aQp = smem_u32(sQp);
    const uint32_t aK = smem_u32(sK), aV = smem_u32(sV);
    const uint32_t aR = smem_u32(sR), aP = smem_u32(sP);

    for (int jt = 0; jt < 8; jt++) {
        const int j0 = jt * 128;
        const int base = S_ + j0 - i0 - 127;

        // group 1: K only (needed first)
#pragma unroll
        for (int i = 0; i < 4; i++) {
            int id = tid + i * 256, row = id >> 3, ch = id & 7;
            cpasync16(smem_u32(sK + row * LDQ_ + ch * 8),
                      kb + (long long)(j0 + row) * kstr + ch * 8);
        }
        CP_COMMIT();
        // group 2: V + R (consumed after content phase)
#pragma unroll
        for (int i = 0; i < 4; i++) {
            int id = tid + i * 256, row = id >> 4, ch = id & 15;
            cpasync16(smem_u32(sV + row * LDV_ + ch * 8),
                      vtb + (long long)row * S_ + j0 + ch * 8);
        }
#pragma unroll
        for (int i = 0; i < 8; i++) {
            int id = tid + i * 256, row = id >> 3, ch = id & 7;
            int grow = base + row; grow = grow < R_ ? grow : R_ - 1;
            cpasync16(smem_u32(sR + row * LDQ_ + ch * 8),
                      rb + (long long)grow * NH_ + ch * 8);
        }
        CP_COMMIT();
        CP_WAIT(1);          // K ready; V/R still inbound
        __syncthreads();

        // ---- content scores -> sS ----
        float cf[16][4];
#pragma unroll
        for (int nt = 0; nt < 16; nt++)
#pragma unroll
            for (int e = 0; e < 4; e++) cf[nt][e] = 0.f;
#pragma unroll
        for (int ks = 0; ks < 4; ks++) {
            uint32_t af[4], bf[16][2];
            LDM4(af[0], af[1], af[2], af[3],
                 aQc + ((wm + (lane & 15)) * LDQ_ + ks * 16 + (lane >> 4) * 8) * 2);
#pragma unroll
            for (int p = 0; p < 8; p++) {
                int rn = p * 16 + (lane & 7) + ((lane >> 4) << 3);
                uint32_t r0, r1, r2, r3;
                LDM4(r0, r1, r2, r3, aK + (rn * LDQ_ + ks * 16 + ((lane >> 3) & 1) * 8) * 2);
                bf[2 * p][0] = r0; bf[2 * p][1] = r1;
                bf[2 * p + 1][0] = r2; bf[2 * p + 1][1] = r3;
            }
#pragma unroll
            for (int nt = 0; nt < 16; nt++) MMA16816(cf[nt], af, bf[nt]);
        }
#pragma unroll
        for (int nt = 0; nt < 16; nt++) {
            int c0 = nt * 8 + (lane & 3) * 2;
#pragma unroll
            for (int e2 = 0; e2 < 2; e2++) {
                int row = wm + (lane >> 2) + 8 * e2;
                *(float2*)&sS[row * LDS_S + c0] = make_float2(cf[nt][e2 * 2], cf[nt][e2 * 2 + 1]);
            }
        }
        CP_WAIT(0);          // V + R landed (overlapped with content MMAs)
        __syncthreads();

        // ---- position scores, band tiles only; shift folded into scatter ----
#pragma unroll
        for (int halfg = 0; halfg < 2; halfg++) {
            int g0 = halfg * 128;
            int lo = halfg == 0 ? ntlo0 : 0;
            int hi = halfg == 0 ? 15 : nthi1;
#pragma unroll
            for (int nt = 0; nt < 16; nt++)
#pragma unroll
                for (int e = 0; e < 4; e++) cf[nt][e] = 0.f;
#pragma unroll
            for (int ks = 0; ks < 4; ks++) {
                uint32_t af[4], bf[16][2];
                LDM4(af[0], af[1], af[2], af[3],
                     aQp + ((wm + (lane & 15)) * LDQ_ + ks * 16 + (lane >> 4) * 8) * 2);
#pragma unroll
                for (int p = 0; p < 8; p++) {
                    if (2 * p + 1 < lo || 2 * p > hi) continue;
                    int rn = g0 + p * 16 + (lane & 7) + ((lane >> 4) << 3);
                    uint32_t r0, r1, r2, r3;
                    LDM4(r0, r1, r2, r3, aR + (rn * LDQ_ + ks * 16 + ((lane >> 3) & 1) * 8) * 2);
                    bf[2 * p][0] = r0; bf[2 * p][1] = r1;
                    bf[2 * p + 1][0] = r2; bf[2 * p + 1][1] = r3;
                }
#pragma unroll
                for (int nt = 0; nt < 16; nt++) {
                    if (nt < lo || nt > hi) continue;
                    MMA16816(cf[nt], af, bf[nt]);
                }
            }
#pragma unroll
            for (int nt = 0; nt < 16; nt++) {
                if (nt < lo || nt > hi) continue;
#pragma unroll
                for (int e = 0; e < 4; e++) {
                    int li = wm + (lane >> 2) + 8 * (e >> 1);
                    int g  = g0 + nt * 8 + (lane & 3) * 2 + (e & 1);
                    int lj = g - 127 + li;
                    if (lj >= 0 && lj < 128) sS[li * LDS_S + lj] += cf[nt][e];
                }
            }
            __syncwarp();
        }

        // ---- online softmax (warp-local rows) ----
        {
            int rloc = wm + (lane >> 1), hf = lane & 1;
            float* srow = &sS[rloc * LDS_S + hf * 64];
            float mx = -1e30f;
#pragma unroll
            for (int c = 0; c < 64; c++) mx = fmaxf(mx, srow[c]);
            mx = fmaxf(mx, __shfl_xor_sync(0xffffffffu, mx, 1));
            mx *= 0.125f;
            float mold = sM[rloc];
            float mnew = fmaxf(mold, mx);
            float alpha = __expf(mold - mnew);
            float sum = 0.f;
            __half* prow = &sP[rloc * LDP_ + hf * 64];
#pragma unroll
            for (int c = 0; c < 64; c += 2) {
                float p0 = __expf(srow[c] * 0.125f - mnew);
                float p1 = __expf(srow[c + 1] * 0.125f - mnew);
                sum += p0 + p1;
                *(__half2*)&prow[c] = __floats2half2_rn(p0, p1);
            }
            sum += __shfl_xor_sync(0xffffffffu, sum, 1);
            if (hf == 0) {
                sL[rloc] = sL[rloc] * alpha + sum;
                sM[rloc] = mnew;
                sAl[rloc] = alpha;
            }
        }
        __syncwarp();

        // ---- rescale O, PV mma ----
#pragma unroll
        for (int e2 = 0; e2 < 2; e2++) {
            float al = sAl[wm + (lane >> 2) + 8 * e2];
#pragma unroll
            for (int nt = 0; nt < 8; nt++) {
                of[nt][e2 * 2]     *= al;
                of[nt][e2 * 2 + 1] *= al;
            }
        }
#pragma unroll
        for (int ks = 0; ks < 8; ks++) {
            uint32_t af[4], bfv[8][2];
            LDM4(af[0], af[1], af[2], af[3],
                 aP + ((wm + (lane & 15)) * LDP_ + ks * 16 + (lane >> 4) * 8) * 2);
#pragma unroll
            for (int p = 0; p < 4; p++) {
                int rn = p * 16 + (lane & 7) + ((lane >> 4) << 3);
                uint32_t r0, r1, r2, r3;
                LDM4(r0, r1, r2, r3, aV + (rn * LDV_ + ks * 16 + ((lane >> 3) & 1) * 8) * 2);
                bfv[2 * p][0] = r0; bfv[2 * p][1] = r1;
                bfv[2 * p + 1][0] = r2; bfv[2 * p + 1][1] = r3;
            }
#pragma unroll
            for (int nt = 0; nt < 8; nt++) MMA16816(of[nt], af, bfv[nt]);
        }
        __syncthreads();
    }

#pragma unroll
    for (int e2 = 0; e2 < 2; e2++) {
        int li = wm + (lane >> 2) + 8 * e2;
        float inv = 1.0f / sL[li];
        long long rowg = (long long)(b * S_ + i0 + li) * NH_ + n * H_;
#pragma unroll
        for (int nt = 0; nt < 8; nt++) {
            int col = nt * 8 + (lane & 3) * 2;
            *(__half2*)(attn + rowg + col) =
                __floats2half2_rn(of[nt][e2 * 2] * inv, of[nt][e2 * 2 + 1] * inv);
        }
    }
}

// ---------------- fp32 -> fp16 copy ----------------
__global__ __launch_bounds__(256) void f2h_k(const float* __restrict__ in,
                                             __half* __restrict__ out)
{
    long long i = (long long)blockIdx.x * 256 + threadIdx.x;
    float4 v = ((const float4*)in)[i];
    ((__half2*)out)[i * 2]     = __floats2half2_rn(v.x, v.y);
    ((__half2*)out)[i * 2 + 1] = __floats2half2_rn(v.z, v.w);
}

// ---------------- fp32 transpose -> fp16 ----------------
__global__ void transpose_h16(const float* __restrict__ in, __half* __restrict__ out,
                              int rows, int cols)
{
    __shared__ float tile[32][33];
    int r0 = blockIdx.y * 32, c0 = blockIdx.x * 32;
    int tx = threadIdx.x, ty = threadIdx.y;
#pragma unroll
    for (int i = 0; i < 4; i++)
        tile[ty + i * 8][tx] = in[(long long)(r0 + ty + i * 8) * cols + c0 + tx];
    __syncthreads();
#pragma unroll
    for (int i = 0; i < 4; i++)
        out[(long long)(c0 + ty + i * 8) * rows + r0 + tx] = __float2half_rn(tile[tx][ty + i * 8]);
}

// ---------------- per-head half transpose: [B,rows,(str)] -> [B,N,H,rows] -------
__global__ void transpose_vh(const __half* __restrict__ in, __half* __restrict__ out,
                             int rows, int instr)
{
    __shared__ __half tile[32][34];
    int z = blockIdx.z, b = z >> 4, n = z & 15;
    const __half* ip = in + (long long)b * rows * instr + n * H_;
    __half* op = out + (long long)z * H_ * rows;
    int r0 = blockIdx.x * 32, h0 = blockIdx.y * 32;
    int tx = threadIdx.x, ty = threadIdx.y;
#pragma unroll
    for (int i = 0; i < 4; i++)
        tile[ty + i * 8][tx] = ip[(long long)(r0 + ty + i * 8) * instr + h0 + tx];
    __syncthreads();
#pragma unroll
    for (int i = 0; i < 4; i++)
        op[(long long)(h0 + ty + i * 8) * rows + r0 + tx] = tile[tx][ty + i * 8];
}

// ---------------- residual + LayerNorm (optional fp16 copy) ---------------------
__global__ __launch_bounds__(256) void ln_k(
    const float* __restrict__ a, const float* __restrict__ res,
    const float* __restrict__ g, const float* __restrict__ bt,
    float* __restrict__ o, __half* __restrict__ oh)
{
    __shared__ float red[16];
    long long row = blockIdx.x;
    int t = threadIdx.x;
    float4 va = *((const float4*)(a + row * 1024) + t);
    float4 vr = *((const float4*)(res + row * 1024) + t);
    float4 x;
    x.x = va.x + vr.x; x.y = va.y + vr.y; x.z = va.z + vr.z; x.w = va.w + vr.w;
    float s  = x.x + x.y + x.z + x.w;
    float q2 = x.x * x.x + x.y * x.y + x.z * x.z + x.w * x.w;
#pragma unroll
    for (int off = 16; off; off >>= 1) {
        s  += __shfl_xor_sync(0xffffffffu, s, off);
        q2 += __shfl_xor_sync(0xffffffffu, q2, off);
    }
    if ((t & 31) == 0) { red[t >> 5] = s; red[8 + (t >> 5)] = q2; }
    __syncthreads();
    if (t == 0) {
        float ss = red[0], qq = red[8];
#pragma unroll
        for (int i = 1; i < 8; i++) { ss += red[i]; qq += red[8 + i]; }
        red[0] = ss; red[8] = qq;
    }
    __syncthreads();
    float mu  = red[0] * (1.f / 1024.f);
    float var = red[8] * (1.f / 1024.f) - mu * mu;
    float rs = rsqrtf(var + 1e-12f);
    float4 gg = *((const float4*)g + t);
    float4 bb = *((const float4*)bt + t);
    float4 y;
    y.x = (x.x - mu) * rs * gg.x + bb.x;
    y.y = (x.y - mu) * rs * gg.y + bb.y;
    y.z = (x.z - mu) * rs * gg.z + bb.z;
    y.w = (x.w - mu) * rs * gg.w + bb.w;
    *((float4*)(o + row * 1024) + t) = y;
    if (oh) {
        __half2* ph = (__half2*)(oh + row * 1024);
        ph[2 * t]     = __floats2half2_rn(y.x, y.y);
        ph[2 * t + 1] = __floats2half2_rn(y.z, y.w);
    }
}

// ---------------- driver --------------------------------------------------------
extern "C" void kernel_launch(void* const* d_in, const int* in_sizes, int n_in,
                              void* d_out, int out_size)
{
    const float* x    = (const float*)d_in[0];
    const float* cb   = (const float*)d_in[1];
    const float* pb   = (const float*)d_in[2];
    const float* rpe  = (const float*)d_in[3];
    const float* Wq   = (const float*)d_in[4];
    const float* Wk   = (const float*)d_in[5];
    const float* Wv   = (const float*)d_in[6];
    const float* Wr   = (const float*)d_in[7];
    const float* Wo   = (const float*)d_in[8];
    const float* ln1g = (const float*)d_in[9];
    const float* ln1b = (const float*)d_in[10];
    const float* Wi   = (const float*)d_in[11];
    const float* bi   = (const float*)d_in[12];
    const float* Wout = (const float*)d_in[13];
    const float* bout = (const float*)d_in[14];
    const float* ln2g = (const float*)d_in[15];
    const float* ln2b = (const float*)d_in[16];
    float* out = (float*)d_out;

    __half *xh,*rpeh,*qkv,*qc,*qp,*r,*vt,*attn,*h1h,*inner;
    __half *WqkvT,*WrT,*WoT,*WiT,*WoutT;
    float *h1,*tmp;
    cudaGetSymbolAddress((void**)&xh, g_xh);      cudaGetSymbolAddress((void**)&rpeh, g_rpeh);
    cudaGetSymbolAddress((void**)&qkv, g_qkv);    cudaGetSymbolAddress((void**)&qc, g_qc);
    cudaGetSymbolAddress((void**)&qp, g_qp);      cudaGetSymbolAddress((void**)&r, g_r);
    cudaGetSymbolAddress((void**)&vt, g_vt);      cudaGetSymbolAddress((void**)&attn, g_attn);
    cudaGetSymbolAddress((void**)&h1, g_h1);      cudaGetSymbolAddress((void**)&h1h, g_h1h);
    cudaGetSymbolAddress((void**)&inner, g_inner);cudaGetSymbolAddress((void**)&tmp, g_tmp);
    cudaGetSymbolAddress((void**)&WqkvT, g_WqkvT);cudaGetSymbolAddress((void**)&WrT, g_WrT);
    cudaGetSymbolAddress((void**)&WoT, g_WoT);    cudaGetSymbolAddress((void**)&WiT, g_WiT);
    cudaGetSymbolAddress((void**)&WoutT, g_WoutT);

    cudaFuncSetAttribute((const void*)hgemm<128,2,4,0,1>,
                         cudaFuncAttributeMaxDynamicSharedMemorySize, HG_SMEM);
    cudaFuncSetAttribute((const void*)hgemm<128,2,4,0,0>,
                         cudaFuncAttributeMaxDynamicSharedMemorySize, HG_SMEM);
    cudaFuncSetAttribute((const void*)hgemm<128,2,4,2,1>,
                         cudaFuncAttributeMaxDynamicSharedMemorySize, HG_SMEM);
    cudaFuncSetAttribute(flash_k, cudaFuncAttributeMaxDynamicSharedMemorySize, FL_SMEM);

    const int M = B_ * S_;
    dim3 blk(256);
    const long long Z0 = 0;

    f2h_k<<<M * E_ / 1024, blk>>>(x, xh);
    f2h_k<<<B_ * R_ * E_ / 1024, blk>>>(rpe, rpeh);
    transpose_h16<<<dim3(32, 32),  dim3(32, 8)>>>(Wq,   WqkvT,                 E_, NH_);
    transpose_h16<<<dim3(32, 32),  dim3(32, 8)>>>(Wk,   WqkvT + 1024 * 1024,   E_, NH_);
    transpose_h16<<<dim3(32, 32),  dim3(32, 8)>>>(Wv,   WqkvT + 2048 * 1024,   E_, NH_);
    transpose_h16<<<dim3(32, 32),  dim3(32, 8)>>>(Wr,   WrT,   E_, NH_);
    transpose_h16<<<dim3(32, 32),  dim3(32, 8)>>>(Wo,   WoT,   NH_, E_);
    transpose_h16<<<dim3(128, 32), dim3(32, 8)>>>(Wi,   WiT,   E_, F_);
    transpose_h16<<<dim3(32, 128), dim3(32, 8)>>>(Wout, WoutT, F_, E_);

    // fused QKV projection: qc/qp written directly with biases; K,V into qkv
    hgemm<128,2,4,2,1><<<dim3(24,32,1), blk, HG_SMEM>>>(
        xh, WqkvT, qkv, cb, pb, qc, qp, E_, E_, E_, 3*NH_,
        1, Z0,Z0,Z0,Z0,Z0,Z0, 0, 1.f);

    // R projection
    hgemm<128,2,4,0,1><<<dim3(8,64,1), blk, HG_SMEM>>>(
        rpeh, WrT, r, nullptr, nullptr, nullptr, nullptr, E_, E_, E_, NH_,
        1, Z0,Z0,Z0,Z0,Z0,Z0, 0, 1.f);

    transpose_vh<<<dim3(S_/32, 2, B_*NHEADS), dim3(32,8)>>>(qkv + 2*NH_, vt, S_, 3*NH_);

    // fused attention
    flash_k<<<dim3(8, B_ * NHEADS), blk, FL_SMEM>>>(qc, qp, qkv + NH_, vt, r, attn, 3*NH_);

    // O projection + LN1
    hgemm<128,2,4,0,0><<<dim3(8,32,1), blk, HG_SMEM>>>(
        attn, WoT, tmp, nullptr, nullptr, nullptr, nullptr, NH_, NH_, NH_, E_,
        1, Z0,Z0,Z0,Z0,Z0,Z0, 0, 1.f);
    ln_k<<<M, 256>>>(tmp, x, ln1g, ln1b, h1, h1h);

    // FFN
    hgemm<128,2,4,0,1><<<dim3(32,32,1), blk, HG_SMEM>>>(
        h1h, WiT, inner, bi, nullptr, nullptr, nullptr, E_, E_, E_, F_,
        1, Z0,Z0,Z0,Z0,Z0,Z0, 1, 1.f);
    hgemm<128,2,4,0,0><<<dim3(8,32,1), blk, HG_SMEM>>>(
        inner, WoutT, tmp, bout, nullptr, nullptr, nullptr, F_, F_, F_, E_,
        1, Z0,Z0,Z0,Z0,Z0,Z0, 0, 1.f);
    ln_k<<<M, 256>>>(tmp, h1, ln2g, ln2b, out, nullptr);
}

// round 8
// speedup vs baseline: 7.4062x; 1.0343x over previous
#include <cuda_runtime.h>
#include <cuda_fp16.h>
#include <math.h>
#include <stdint.h>

#define B_      4
#define S_      1024
#define E_      1024
#define NHEADS  16
#define H_      64
#define NH_     1024
#define F_      4096
#define R_      2048

// ---------------- scratch (static device globals) ----------------
__device__ __half g_xh[4194304];       // [B,S,E]
__device__ __half g_rpeh[8388608];     // [B,R,E]
__device__ __half g_qkv[12582912];     // [B,S,3NH]: cols 1024..2047=K, 2048..3071=V
__device__ __half g_qc[4194304];
__device__ __half g_qp[4194304];
__device__ __half g_r[8388608];
__device__ __half g_vt[4194304];       // [B,N,H,S]
__device__ __half g_attn[4194304];
__device__ float  g_h1[4194304];
__device__ __half g_h1h[4194304];
__device__ __half g_inner[16777216];
__device__ float  g_tmp[4194304];
__device__ __half g_WqkvT[3145728];    // [3NH, E]
__device__ __half g_WrT[1048576];
__device__ __half g_WoT[1048576];
__device__ __half g_WiT[4194304];
__device__ __half g_WoutT[4194304];

// ---------------- helpers ----------------
__device__ __forceinline__ uint32_t smem_u32(const void* p) {
    uint32_t a;
    asm("{ .reg .u64 t; cvta.to.shared.u64 t, %1; cvt.u32.u64 %0, t; }" : "=r"(a) : "l"(p));
    return a;
}
__device__ __forceinline__ void cpasync16(uint32_t s, const void* g) {
    asm volatile("cp.async.cg.shared.global [%0], [%1], 16;" :: "r"(s), "l"(g));
}
#define CP_COMMIT() asm volatile("cp.async.commit_group;" ::: "memory")
#define CP_WAIT(n)  asm volatile("cp.async.wait_group %0;" :: "n"(n) : "memory")

#define LDM4(r0, r1, r2, r3, a)                                                     \
    asm volatile("ldmatrix.sync.aligned.m8n8.x4.shared.b16 {%0,%1,%2,%3}, [%4];"    \
                 : "=r"(r0), "=r"(r1), "=r"(r2), "=r"(r3) : "r"(a))

#define MMA16816(c, a, b)                                                           \
    asm volatile("mma.sync.aligned.m16n8k16.row.col.f32.f16.f16.f32 "               \
                 "{%0,%1,%2,%3},{%4,%5,%6,%7},{%8,%9},{%0,%1,%2,%3};"               \
                 : "+f"((c)[0]), "+f"((c)[1]), "+f"((c)[2]), "+f"((c)[3])           \
                 : "r"((a)[0]), "r"((a)[1]), "r"((a)[2]), "r"((a)[3]),              \
                   "r"((b)[0]), "r"((b)[1]))

// ---------------- fp16 tensor-core GEMM, 3-stage pipeline -----------------------
// C = A(MxK, K-major rows) * B(NxK, K-major rows)^T.  fp32 accumulate.
// EPI 0: store (+bias/relu/scale), OUTH picks half/float.
// EPI 2: QKV epilogue — col<NH_: qc=(v+cb)/8, qp=(v+pb)/8 (half); else store half.
#define HG_SMEM (3 * (128 + 128) * 40 * 2)
template<int BN, int WRM, int WRN, int EPI, int OUTH>
__global__ __launch_bounds__(256, 2) void hgemm(
    const __half* __restrict__ A, const __half* __restrict__ Bm,
    void* __restrict__ Cv, const float* __restrict__ bias,
    const float* __restrict__ pb, __half* __restrict__ qcp, __half* __restrict__ qpp,
    int K, int lda, int ldb, int ldc, int zdiv,
    long long As1, long long As2, long long Bs1, long long Bs2,
    long long Cs1, long long Cs2, int relu, float scale)
{
    constexpr int BM = 128, LDS = 40;
    constexpr int MW = BM / WRM, NW = BN / WRN;
    constexpr int MT = MW / 16, NPAIR = NW / 16, NT = NW / 8;
    extern __shared__ __half hsm[];
    __half* sA = hsm;                       // [3][BM*LDS]
    __half* sB = hsm + 3 * BM * LDS;        // [3][BN*LDS]

    const int bm = blockIdx.y * BM, bn = blockIdx.x * BN;
    {
        int z = blockIdx.z, zq = z / zdiv, zr = z % zdiv;
        A  += zq * As1 + zr * As2;
        Bm += zq * Bs1 + zr * Bs2;
    }
    const int tid = threadIdx.x, lane = tid & 31, wid = tid >> 5;
    const int wm = (wid / WRN) * MW, wn = (wid % WRN) * NW;

    float cf[MT][NT][4];
#pragma unroll
    for (int i = 0; i < MT; i++)
#pragma unroll
        for (int j = 0; j < NT; j++)
#pragma unroll
            for (int e = 0; e < 4; e++) cf[i][j][e] = 0.f;

    auto stage = [&](int c, int sx) {
        __half* dA = sA + sx * BM * LDS;
        __half* dB = sB + sx * BN * LDS;
#pragma unroll
        for (int i = 0; i < BM * 4 / 256; i++) {
            int id = tid + i * 256, row = id >> 2, ch = id & 3;
            cpasync16(smem_u32(dA + row * LDS + ch * 8),
                      A + (long long)(bm + row) * lda + c * 32 + ch * 8);
        }
#pragma unroll
        for (int i = 0; i < BN * 4 / 256; i++) {
            int id = tid + i * 256, row = id >> 2, ch = id & 3;
            cpasync16(smem_u32(dB + row * LDS + ch * 8),
                      Bm + (long long)(bn + row) * ldb + c * 32 + ch * 8);
        }
        CP_COMMIT();
    };

    const int nkt = K >> 5;
    stage(0, 0);
    stage(1, 1);
    int cbuf = 0, pbuf = 2;
    for (int c = 0; c < nkt; c++) {
        CP_WAIT(1);
        __syncthreads();
        if (c + 2 < nkt) stage(c + 2, pbuf);
        else CP_COMMIT();
        const uint32_t a0 = smem_u32(sA + cbuf * BM * LDS);
        const uint32_t b0 = smem_u32(sB + cbuf * BN * LDS);
#pragma unroll
        for (int ks = 0; ks < 2; ks++) {
            uint32_t af[MT][4], bf[NT][2];
#pragma unroll
            for (int mt = 0; mt < MT; mt++) {
                uint32_t ad = a0 + ((wm + mt * 16 + (lane & 15)) * LDS
                                    + ks * 16 + (lane >> 4) * 8) * 2;
                LDM4(af[mt][0], af[mt][1], af[mt][2], af[mt][3], ad);
            }
#pragma unroll
            for (int p = 0; p < NPAIR; p++) {
                int rn = wn + p * 16 + (lane & 7) + ((lane >> 4) << 3);
                uint32_t bd = b0 + (rn * LDS + ks * 16 + ((lane >> 3) & 1) * 8) * 2;
                uint32_t r0, r1, r2, r3;
                LDM4(r0, r1, r2, r3, bd);
                bf[2 * p][0] = r0; bf[2 * p][1] = r1;
                bf[2 * p + 1][0] = r2; bf[2 * p + 1][1] = r3;
            }
#pragma unroll
            for (int mt = 0; mt < MT; mt++)
#pragma unroll
                for (int nt = 0; nt < NT; nt++)
                    MMA16816(cf[mt][nt], af[mt], bf[nt]);
        }
        cbuf = cbuf == 2 ? 0 : cbuf + 1;
        pbuf = pbuf == 2 ? 0 : pbuf + 1;
    }

    long long coff;
    {
        int z = blockIdx.z, zq = z / zdiv, zr = z % zdiv;
        coff = zq * Cs1 + zr * Cs2;
    }
#pragma unroll
    for (int mt = 0; mt < MT; mt++) {
#pragma unroll
        for (int nt = 0; nt < NT; nt++) {
            int r = bm + wm + mt * 16 + (lane >> 2);
            int col = bn + wn + nt * 8 + (lane & 3) * 2;
#pragma unroll
            for (int e2 = 0; e2 < 2; e2++) {
                int row = r + 8 * e2;
                float v0 = cf[mt][nt][e2 * 2] * scale;
                float v1 = cf[mt][nt][e2 * 2 + 1] * scale;
                if (EPI == 2) {
                    if (col < NH_) {
                        // fold 1/sqrt(H)=0.125 into the stored query tensors
                        float c0 = bias[col], c1 = bias[col + 1];
                        float p0 = pb[col],  p1 = pb[col + 1];
                        *(__half2*)(qcp + (long long)row * NH_ + col) =
                            __floats2half2_rn((v0 + c0) * 0.125f, (v1 + c1) * 0.125f);
                        *(__half2*)(qpp + (long long)row * NH_ + col) =
                            __floats2half2_rn((v0 + p0) * 0.125f, (v1 + p1) * 0.125f);
                    } else {
                        __half* Ch = (__half*)Cv;
                        *(__half2*)(Ch + (long long)row * ldc + col) =
                            __floats2half2_rn(v0, v1);
                    }
                } else {
                    if (bias) { v0 += bias[col]; v1 += bias[col + 1]; }
                    if (relu) { v0 = fmaxf(v0, 0.f); v1 = fmaxf(v1, 0.f); }
                    if (OUTH) {
                        __half* Ch = (__half*)Cv + coff;
                        *(__half2*)(Ch + (long long)row * ldc + col) =
                            __floats2half2_rn(v0, v1);
                    } else {
                        float* Cf = (float*)Cv + coff;
                        *(float2*)(Cf + (long long)row * ldc + col) = make_float2(v0, v1);
                    }
                }
            }
        }
    }
}

// ---------------- flash attention with folded rel-shift + band tile-skip --------
#define LDQ_  72
#define LDV_  136
#define LDS_S 132
#define LDP_  136
#define FL_SMEM (3*128*LDQ_*2 + 64*LDV_*2 + 256*LDQ_*2 + 128*LDS_S*4 + 128*LDP_*2 + 3*128*4)

__global__ __launch_bounds__(256, 1) void flash_k(
    const __half* __restrict__ qc, const __half* __restrict__ qp,
    const __half* __restrict__ kk, const __half* __restrict__ vt,
    const __half* __restrict__ rr, __half* __restrict__ attn, int kstr)
{
    extern __shared__ char smraw[];
    __half* sQc = (__half*)smraw;
    __half* sQp = sQc + 128 * LDQ_;
    __half* sK  = sQp + 128 * LDQ_;
    __half* sV  = sK  + 128 * LDQ_;
    __half* sR  = sV  + 64 * LDV_;
    float*  sS  = (float*)(sR + 256 * LDQ_);
    __half* sP  = (__half*)(sS + 128 * LDS_S);
    float*  sM  = (float*)(sP + 128 * LDP_);
    float*  sL  = sM + 128;
    float*  sAl = sL + 128;

    const int it = blockIdx.x, z = blockIdx.y;
    const int b = z >> 4, n = z & 15;
    const int i0 = it * 128;
    const int tid = threadIdx.x, lane = tid & 31, wid = tid >> 5;
    const int wm = wid * 16;

    int ntlo0 = (105 - wm + 7) >> 3; if (ntlo0 < 0) ntlo0 = 0;
    int nthi1 = (126 - wm) >> 3;

    const __half* qcb = qc + (long long)b * S_ * NH_ + n * H_;
    const __half* qpb = qp + (long long)b * S_ * NH_ + n * H_;
    const __half* kb  = kk + (long long)b * S_ * kstr + n * H_;
    const __half* vtb = vt + (long long)z * H_ * S_;
    const __half* rb  = rr + (long long)b * R_ * NH_ + n * H_;

#pragma unroll
    for (int i = 0; i < 4; i++) {
        int id = tid + i * 256, row = id >> 3, ch = id & 7;
        cpasync16(smem_u32(sQc + row * LDQ_ + ch * 8),
                  qcb + (long long)(i0 + row) * NH_ + ch * 8);
        cpasync16(smem_u32(sQp + row * LDQ_ + ch * 8),
                  qpb + (long long)(i0 + row) * NH_ + ch * 8);
    }
    CP_COMMIT();
    if (tid < 128) { sM[tid] = -1e30f; sL[tid] = 0.f; }
    CP_WAIT(0);
    __syncthreads();

    float of[8][4];
#pragma unroll
    for (int nt = 0; nt < 8; nt++)
#pragma unroll
        for (int e = 0; e < 4; e++) of[nt][e] = 0.f;

    const uint32_t aQc = smem_u32(sQc), aQp = smem_u32(sQp);
    const uint32_t aK = smem_u32(sK), aV = smem_u32(sV);
    const uint32_t aR = smem_u32(sR), aP = smem_u32(sP);

    for (int jt = 0; jt < 8; jt++) {
        const int j0 = jt * 128;
        const int base = S_ + j0 - i0 - 127;

#pragma unroll
        for (int i = 0; i < 4; i++) {
            int id = tid + i * 256, row = id >> 3, ch = id & 7;
            cpasync16(smem_u32(sK + row * LDQ_ + ch * 8),
                      kb + (long long)(j0 + row) * kstr + ch * 8);
        }
        CP_COMMIT();
#pragma unroll
        for (int i = 0; i < 4; i++) {
            int id = tid + i * 256, row = id >> 4, ch = id & 15;
            cpasync16(smem_u32(sV + row * LDV_ + ch * 8),
                      vtb + (long long)row * S_ + j0 + ch * 8);
        }
#pragma unroll
        for (int i = 0; i < 8; i++) {
            int id = tid + i * 256, row = id >> 3, ch = id & 7;
            int grow = base + row; grow = grow < R_ ? grow : R_ - 1;
            cpasync16(smem_u32(sR + row * LDQ_ + ch * 8),
                      rb + (long long)grow * NH_ + ch * 8);
        }
        CP_COMMIT();
        CP_WAIT(1);
        __syncthreads();

        // ---- content scores -> sS ----
        float cf[16][4];
#pragma unroll
        for (int nt = 0; nt < 16; nt++)
#pragma unroll
            for (int e = 0; e < 4; e++) cf[nt][e] = 0.f;
#pragma unroll
        for (int ks = 0; ks < 4; ks++) {
            uint32_t af[4], bf[16][2];
            LDM4(af[0], af[1], af[2], af[3],
                 aQc + ((wm + (lane & 15)) * LDQ_ + ks * 16 + (lane >> 4) * 8) * 2);
#pragma unroll
            for (int p = 0; p < 8; p++) {
                int rn = p * 16 + (lane & 7) + ((lane >> 4) << 3);
                uint32_t r0, r1, r2, r3;
                LDM4(r0, r1, r2, r3, aK + (rn * LDQ_ + ks * 16 + ((lane >> 3) & 1) * 8) * 2);
                bf[2 * p][0] = r0; bf[2 * p][1] = r1;
                bf[2 * p + 1][0] = r2; bf[2 * p + 1][1] = r3;
            }
#pragma unroll
            for (int nt = 0; nt < 16; nt++) MMA16816(cf[nt], af, bf[nt]);
        }
#pragma unroll
        for (int nt = 0; nt < 16; nt++) {
            int c0 = nt * 8 + (lane & 3) * 2;
#pragma unroll
            for (int e2 = 0; e2 < 2; e2++) {
                int row = wm + (lane >> 2) + 8 * e2;
                *(float2*)&sS[row * LDS_S + c0] = make_float2(cf[nt][e2 * 2], cf[nt][e2 * 2 + 1]);
            }
        }
        CP_WAIT(0);
        __syncthreads();

        // ---- position scores, band tiles only ----
#pragma unroll
        for (int halfg = 0; halfg < 2; halfg++) {
            int g0 = halfg * 128;
            int lo = halfg == 0 ? ntlo0 : 0;
            int hi = halfg == 0 ? 15 : nthi1;
#pragma unroll
            for (int nt = 0; nt < 16; nt++)
#pragma unroll
                for (int e = 0; e < 4; e++) cf[nt][e] = 0.f;
#pragma unroll
            for (int ks = 0; ks < 4; ks++) {
                uint32_t af[4], bf[16][2];
                LDM4(af[0], af[1], af[2], af[3],
                     aQp + ((wm + (lane & 15)) * LDQ_ + ks * 16 + (lane >> 4) * 8) * 2);
#pragma unroll
                for (int p = 0; p < 8; p++) {
                    if (2 * p + 1 < lo || 2 * p > hi) continue;
                    int rn = g0 + p * 16 + (lane & 7) + ((lane >> 4) << 3);
                    uint32_t r0, r1, r2, r3;
                    LDM4(r0, r1, r2, r3, aR + (rn * LDQ_ + ks * 16 + ((lane >> 3) & 1) * 8) * 2);
                    bf[2 * p][0] = r0; bf[2 * p][1] = r1;
                    bf[2 * p + 1][0] = r2; bf[2 * p + 1][1] = r3;
                }
#pragma unroll
                for (int nt = 0; nt < 16; nt++) {
                    if (nt < lo || nt > hi) continue;
                    MMA16816(cf[nt], af, bf[nt]);
                }
            }
#pragma unroll
            for (int nt = 0; nt < 16; nt++) {
                if (nt < lo || nt > hi) continue;
#pragma unroll
                for (int e = 0; e < 4; e++) {
                    int li = wm + (lane >> 2) + 8 * (e >> 1);
                    int g  = g0 + nt * 8 + (lane & 3) * 2 + (e & 1);
                    int lj = g - 127 + li;
                    if (lj >= 0 && lj < 128) sS[li * LDS_S + lj] += cf[nt][e];
                }
            }
            __syncwarp();
        }

        // ---- online softmax (scores pre-scaled by 1/8 via qc/qp) ----
        {
            int rloc = wm + (lane >> 1), hf = lane & 1;
            float* srow = &sS[rloc * LDS_S + hf * 64];
            float mx = -1e30f;
#pragma unroll
            for (int c = 0; c < 64; c++) mx = fmaxf(mx, srow[c]);
            mx = fmaxf(mx, __shfl_xor_sync(0xffffffffu, mx, 1));
            float mold = sM[rloc];
            float mnew = fmaxf(mold, mx);
            float alpha = __expf(mold - mnew);
            float sum = 0.f;
            __half* prow = &sP[rloc * LDP_ + hf * 64];
#pragma unroll
            for (int c = 0; c < 64; c += 2) {
                float p0 = __expf(srow[c] - mnew);
                float p1 = __expf(srow[c + 1] - mnew);
                sum += p0 + p1;
                *(__half2*)&prow[c] = __floats2half2_rn(p0, p1);
            }
            sum += __shfl_xor_sync(0xffffffffu, sum, 1);
            if (hf == 0) {
                sL[rloc] = sL[rloc] * alpha + sum;
                sM[rloc] = mnew;
                sAl[rloc] = alpha;
            }
        }
        __syncwarp();

        // ---- rescale O, PV mma ----
#pragma unroll
        for (int e2 = 0; e2 < 2; e2++) {
            float al = sAl[wm + (lane >> 2) + 8 * e2];
#pragma unroll
            for (int nt = 0; nt < 8; nt++) {
                of[nt][e2 * 2]     *= al;
                of[nt][e2 * 2 + 1] *= al;
            }
        }
#pragma unroll
        for (int ks = 0; ks < 8; ks++) {
            uint32_t af[4], bfv[8][2];
            LDM4(af[0], af[1], af[2], af[3],
                 aP + ((wm + (lane & 15)) * LDP_ + ks * 16 + (lane >> 4) * 8) * 2);
#pragma unroll
            for (int p = 0; p < 4; p++) {
                int rn = p * 16 + (lane & 7) + ((lane >> 4) << 3);
                uint32_t r0, r1, r2, r3;
                LDM4(r0, r1, r2, r3, aV + (rn * LDV_ + ks * 16 + ((lane >> 3) & 1) * 8) * 2);
                bfv[2 * p][0] = r0; bfv[2 * p][1] = r1;
                bfv[2 * p + 1][0] = r2; bfv[2 * p + 1][1] = r3;
            }
#pragma unroll
            for (int nt = 0; nt < 8; nt++) MMA16816(of[nt], af, bfv[nt]);
        }
        __syncthreads();
    }

#pragma unroll
    for (int e2 = 0; e2 < 2; e2++) {
        int li = wm + (lane >> 2) + 8 * e2;
        float inv = 1.0f / sL[li];
        long long rowg = (long long)(b * S_ + i0 + li) * NH_ + n * H_;
#pragma unroll
        for (int nt = 0; nt < 8; nt++) {
            int col = nt * 8 + (lane & 3) * 2;
            *(__half2*)(attn + rowg + col) =
                __floats2half2_rn(of[nt][e2 * 2] * inv, of[nt][e2 * 2 + 1] * inv);
        }
    }
}

// ---------------- fp32 -> fp16 copy ----------------
__global__ __launch_bounds__(256) void f2h_k(const float* __restrict__ in,
                                             __half* __restrict__ out)
{
    long long i = (long long)blockIdx.x * 256 + threadIdx.x;
    float4 v = ((const float4*)in)[i];
    ((__half2*)out)[i * 2]     = __floats2half2_rn(v.x, v.y);
    ((__half2*)out)[i * 2 + 1] = __floats2half2_rn(v.z, v.w);
}

// ---------------- fp32 transpose -> fp16 ----------------
__global__ void transpose_h16(const float* __restrict__ in, __half* __restrict__ out,
                              int rows, int cols)
{
    __shared__ float tile[32][33];
    int r0 = blockIdx.y * 32, c0 = blockIdx.x * 32;
    int tx = threadIdx.x, ty = threadIdx.y;
#pragma unroll
    for (int i = 0; i < 4; i++)
        tile[ty + i * 8][tx] = in[(long long)(r0 + ty + i * 8) * cols + c0 + tx];
    __syncthreads();
#pragma unroll
    for (int i = 0; i < 4; i++)
        out[(long long)(c0 + ty + i * 8) * rows + r0 + tx] = __float2half_rn(tile[tx][ty + i * 8]);
}

// ---------------- per-head half transpose ----------------
__global__ void transpose_vh(const __half* __restrict__ in, __half* __restrict__ out,
                             int rows, int instr)
{
    __shared__ __half tile[32][34];
    int z = blockIdx.z, b = z >> 4, n = z & 15;
    const __half* ip = in + (long long)b * rows * instr + n * H_;
    __half* op = out + (long long)z * H_ * rows;
    int r0 = blockIdx.x * 32, h0 = blockIdx.y * 32;
    int tx = threadIdx.x, ty = threadIdx.y;
#pragma unroll
    for (int i = 0; i < 4; i++)
        tile[ty + i * 8][tx] = ip[(long long)(r0 + ty + i * 8) * instr + h0 + tx];
    __syncthreads();
#pragma unroll
    for (int i = 0; i < 4; i++)
        op[(long long)(h0 + ty + i * 8) * rows + r0 + tx] = tile[tx][ty + i * 8];
}

// ---------------- residual + LayerNorm (optional fp16 copy) ---------------------
__global__ __launch_bounds__(256) void ln_k(
    const float* __restrict__ a, const float* __restrict__ res,
    const float* __restrict__ g, const float* __restrict__ bt,
    float* __restrict__ o, __half* __restrict__ oh)
{
    __shared__ float red[16];
    long long row = blockIdx.x;
    int t = threadIdx.x;
    float4 va = *((const float4*)(a + row * 1024) + t);
    float4 vr = *((const float4*)(res + row * 1024) + t);
    float4 x;
    x.x = va.x + vr.x; x.y = va.y + vr.y; x.z = va.z + vr.z; x.w = va.w + vr.w;
    float s  = x.x + x.y + x.z + x.w;
    float q2 = x.x * x.x + x.y * x.y + x.z * x.z + x.w * x.w;
#pragma unroll
    for (int off = 16; off; off >>= 1) {
        s  += __shfl_xor_sync(0xffffffffu, s, off);
        q2 += __shfl_xor_sync(0xffffffffu, q2, off);
    }
    if ((t & 31) == 0) { red[t >> 5] = s; red[8 + (t >> 5)] = q2; }
    __syncthreads();
    if (t == 0) {
        float ss = red[0], qq = red[8];
#pragma unroll
        for (int i = 1; i < 8; i++) { ss += red[i]; qq += red[8 + i]; }
        red[0] = ss; red[8] = qq;
    }
    __syncthreads();
    float mu  = red[0] * (1.f / 1024.f);
    float var = red[8] * (1.f / 1024.f) - mu * mu;
    float rs = rsqrtf(var + 1e-12f);
    float4 gg = *((const float4*)g + t);
    float4 bb = *((const float4*)bt + t);
    float4 y;
    y.x = (x.x - mu) * rs * gg.x + bb.x;
    y.y = (x.y - mu) * rs * gg.y + bb.y;
    y.z = (x.z - mu) * rs * gg.z + bb.z;
    y.w = (x.w - mu) * rs * gg.w + bb.w;
    *((float4*)(o + row * 1024) + t) = y;
    if (oh) {
        __half2* ph = (__half2*)(oh + row * 1024);
        ph[2 * t]     = __floats2half2_rn(y.x, y.y);
        ph[2 * t + 1] = __floats2half2_rn(y.z, y.w);
    }
}

// ---------------- driver --------------------------------------------------------
extern "C" void kernel_launch(void* const* d_in, const int* in_sizes, int n_in,
                              void* d_out, int out_size)
{
    const float* x    = (const float*)d_in[0];
    const float* cb   = (const float*)d_in[1];
    const float* pb   = (const float*)d_in[2];
    const float* rpe  = (const float*)d_in[3];
    const float* Wq   = (const float*)d_in[4];
    const float* Wk   = (const float*)d_in[5];
    const float* Wv   = (const float*)d_in[6];
    const float* Wr   = (const float*)d_in[7];
    const float* Wo   = (const float*)d_in[8];
    const float* ln1g = (const float*)d_in[9];
    const float* ln1b = (const float*)d_in[10];
    const float* Wi   = (const float*)d_in[11];
    const float* bi   = (const float*)d_in[12];
    const float* Wout = (const float*)d_in[13];
    const float* bout = (const float*)d_in[14];
    const float* ln2g = (const float*)d_in[15];
    const float* ln2b = (const float*)d_in[16];
    float* out = (float*)d_out;

    __half *xh,*rpeh,*qkv,*qc,*qp,*r,*vt,*attn,*h1h,*inner;
    __half *WqkvT,*WrT,*WoT,*WiT,*WoutT;
    float *h1,*tmp;
    cudaGetSymbolAddress((void**)&xh, g_xh);      cudaGetSymbolAddress((void**)&rpeh, g_rpeh);
    cudaGetSymbolAddress((void**)&qkv, g_qkv);    cudaGetSymbolAddress((void**)&qc, g_qc);
    cudaGetSymbolAddress((void**)&qp, g_qp);      cudaGetSymbolAddress((void**)&r, g_r);
    cudaGetSymbolAddress((void**)&vt, g_vt);      cudaGetSymbolAddress((void**)&attn, g_attn);
    cudaGetSymbolAddress((void**)&h1, g_h1);      cudaGetSymbolAddress((void**)&h1h, g_h1h);
    cudaGetSymbolAddress((void**)&inner, g_inner);cudaGetSymbolAddress((void**)&tmp, g_tmp);
    cudaGetSymbolAddress((void**)&WqkvT, g_WqkvT);cudaGetSymbolAddress((void**)&WrT, g_WrT);
    cudaGetSymbolAddress((void**)&WoT, g_WoT);    cudaGetSymbolAddress((void**)&WiT, g_WiT);
    cudaGetSymbolAddress((void**)&WoutT, g_WoutT);

    cudaFuncSetAttribute((const void*)hgemm<128,2,4,0,1>,
                         cudaFuncAttributeMaxDynamicSharedMemorySize, HG_SMEM);
    cudaFuncSetAttribute((const void*)hgemm<128,2,4,0,0>,
                         cudaFuncAttributeMaxDynamicSharedMemorySize, HG_SMEM);
    cudaFuncSetAttribute((const void*)hgemm<128,2,4,2,1>,
                         cudaFuncAttributeMaxDynamicSharedMemorySize, HG_SMEM);
    cudaFuncSetAttribute(flash_k, cudaFuncAttributeMaxDynamicSharedMemorySize, FL_SMEM);

    // side streams + fork/join events (created once; capture-compatible)
    static cudaStream_t s1 = nullptr, s2 = nullptr, s3 = nullptr;
    static cudaEvent_t  eF = nullptr, e1 = nullptr, e2 = nullptr, e3 = nullptr;
    if (s1 == nullptr) {
        cudaStreamCreateWithFlags(&s1, cudaStreamNonBlocking);
        cudaStreamCreateWithFlags(&s2, cudaStreamNonBlocking);
        cudaStreamCreateWithFlags(&s3, cudaStreamNonBlocking);
        cudaEventCreateWithFlags(&eF, cudaEventDisableTiming);
        cudaEventCreateWithFlags(&e1, cudaEventDisableTiming);
        cudaEventCreateWithFlags(&e2, cudaEventDisableTiming);
        cudaEventCreateWithFlags(&e3, cudaEventDisableTiming);
    }

    const int M = B_ * S_;
    dim3 blk(256);
    const long long Z0 = 0;

    // ---- fork ----
    cudaEventRecord(eF, 0);
    cudaStreamWaitEvent(s1, eF, 0);
    cudaStreamWaitEvent(s2, eF, 0);
    cudaStreamWaitEvent(s3, eF, 0);

    // main: x -> fp16 (needed by QKV)
    f2h_k<<<M * E_ / 1024, blk>>>(x, xh);

    // s1: QKV weight transposes
    transpose_h16<<<dim3(32, 32), dim3(32, 8), 0, s1>>>(Wq, WqkvT,               E_, NH_);
    transpose_h16<<<dim3(32, 32), dim3(32, 8), 0, s1>>>(Wk, WqkvT + 1024 * 1024, E_, NH_);
    transpose_h16<<<dim3(32, 32), dim3(32, 8), 0, s1>>>(Wv, WqkvT + 2048 * 1024, E_, NH_);
    cudaEventRecord(e1, s1);

    // s2: full R chain (hidden under QKV GEMM)
    f2h_k<<<B_ * R_ * E_ / 1024, blk, 0, s2>>>(rpe, rpeh);
    transpose_h16<<<dim3(32, 32), dim3(32, 8), 0, s2>>>(Wr, WrT, E_, NH_);
    hgemm<128,2,4,0,1><<<dim3(8,64,1), blk, HG_SMEM, s2>>>(
        rpeh, WrT, r, nullptr, nullptr, nullptr, nullptr, E_, E_, E_, NH_,
        1, Z0,Z0,Z0,Z0,Z0,Z0, 0, 1.f);
    cudaEventRecord(e2, s2);

    // s3: remaining weight transposes (hidden under QKV+flash)
    transpose_h16<<<dim3(32, 32),  dim3(32, 8), 0, s3>>>(Wo,   WoT,   NH_, E_);
    transpose_h16<<<dim3(128, 32), dim3(32, 8), 0, s3>>>(Wi,   WiT,   E_, F_);
    transpose_h16<<<dim3(32, 128), dim3(32, 8), 0, s3>>>(Wout, WoutT, F_, E_);
    cudaEventRecord(e3, s3);

    // main: QKV mega-GEMM (waits weight transposes), then V transpose
    cudaStreamWaitEvent(0, e1, 0);
    hgemm<128,2,4,2,1><<<dim3(24,32,1), blk, HG_SMEM>>>(
        xh, WqkvT, qkv, cb, pb, qc, qp, E_, E_, E_, 3*NH_,
        1, Z0,Z0,Z0,Z0,Z0,Z0, 0, 1.f);
    transpose_vh<<<dim3(S_/32, 2, B_*NHEADS), dim3(32,8)>>>(qkv + 2*NH_, vt, S_, 3*NH_);

    // join R chain, run fused attention
    cudaStreamWaitEvent(0, e2, 0);
    flash_k<<<dim3(8, B_ * NHEADS), blk, FL_SMEM>>>(qc, qp, qkv + NH_, vt, r, attn, 3*NH_);

    // join s3, O projection + LN1
    cudaStreamWaitEvent(0, e3, 0);
    hgemm<128,2,4,0,0><<<dim3(8,32,1), blk, HG_SMEM>>>(
        attn, WoT, tmp, nullptr, nullptr, nullptr, nullptr, NH_, NH_, NH_, E_,
        1, Z0,Z0,Z0,Z0,Z0,Z0, 0, 1.f);
    ln_k<<<M, 256>>>(tmp, x, ln1g, ln1b, h1, h1h);

    // FFN
    hgemm<128,2,4,0,1><<<dim3(32,32,1), blk, HG_SMEM>>>(
        h1h, WiT, inner, bi, nullptr, nullptr, nullptr, E_, E_, E_, F_,
        1, Z0,Z0,Z0,Z0,Z0,Z0, 1, 1.f);
    hgemm<128,2,4,0,0><<<dim3(8,32,1), blk, HG_SMEM>>>(
        inner, WoutT, tmp, bout, nullptr, nullptr, nullptr, F_, F_, F_, E_,
        1, Z0,Z0,Z0,Z0,Z0,Z0, 0, 1.f);
    ln_k<<<M, 256>>>(tmp, h1, ln2g, ln2b, out, nullptr);
}

// round 9
// speedup vs baseline: 7.7856x; 1.0512x over previous
#include <cuda_runtime.h>
#include <cuda_fp16.h>
#include <math.h>
#include <stdint.h>

#define B_      4
#define S_      1024
#define E_      1024
#define NHEADS  16
#define H_      64
#define NH_     1024
#define F_      4096
#define R_      2048

// ---------------- scratch (static device globals) ----------------
__device__ __half g_xh[4194304];       // [B,S,E]
__device__ __half g_rpeh[8388608];     // [B,R,E]
__device__ __half g_qkv[12582912];     // [B,S,3NH]: cols 1024..2047=K, 2048..3071=V
__device__ __half g_qc[4194304];
__device__ __half g_qp[4194304];
__device__ __half g_r[8388608];
__device__ __half g_vt[4194304];       // [B,N,H,S]
__device__ __half g_attn[4194304];
__device__ float  g_h1[4194304];
__device__ __half g_h1h[4194304];
__device__ __half g_inner[16777216];
__device__ float  g_tmp[4194304];
__device__ __half g_WqkvT[3145728];    // [3NH, E]
__device__ __half g_WrT[1048576];
__device__ __half g_WoT[1048576];
__device__ __half g_WiT[4194304];
__device__ __half g_WoutT[4194304];

// ---------------- helpers ----------------
__device__ __forceinline__ uint32_t smem_u32(const void* p) {
    uint32_t a;
    asm("{ .reg .u64 t; cvta.to.shared.u64 t, %1; cvt.u32.u64 %0, t; }" : "=r"(a) : "l"(p));
    return a;
}
__device__ __forceinline__ void cpasync16(uint32_t s, const void* g) {
    asm volatile("cp.async.cg.shared.global [%0], [%1], 16;" :: "r"(s), "l"(g));
}
#define CP_COMMIT() asm volatile("cp.async.commit_group;" ::: "memory")
#define CP_WAIT(n)  asm volatile("cp.async.wait_group %0;" :: "n"(n) : "memory")

#define LDM4(r0, r1, r2, r3, a)                                                     \
    asm volatile("ldmatrix.sync.aligned.m8n8.x4.shared.b16 {%0,%1,%2,%3}, [%4];"    \
                 : "=r"(r0), "=r"(r1), "=r"(r2), "=r"(r3) : "r"(a))

#define MMA16816(c, a, b)                                                           \
    asm volatile("mma.sync.aligned.m16n8k16.row.col.f32.f16.f16.f32 "               \
                 "{%0,%1,%2,%3},{%4,%5,%6,%7},{%8,%9},{%0,%1,%2,%3};"               \
                 : "+f"((c)[0]), "+f"((c)[1]), "+f"((c)[2]), "+f"((c)[3])           \
                 : "r"((a)[0]), "r"((a)[1]), "r"((a)[2]), "r"((a)[3]),              \
                   "r"((b)[0]), "r"((b)[1]))

// ---------------- fp16 tensor-core GEMM, K-chunk 64, 3-stage ring ---------------
// C = A(MxK, K-major rows) * B(NxK, K-major rows)^T.  fp32 accumulate.
// EPI 0: store (+bias/relu/scale), OUTH picks half/float.
// EPI 2: QKV epilogue — col<NH_: qc=(v+cb)/8, qp=(v+pb)/8 (half); else store half.
// Requires K % 64 == 0 (all call sites satisfy this).
#define LDSG 72
#define HG_SMEM (3 * (128 + 128) * LDSG * 2)
template<int BN, int WRM, int WRN, int EPI, int OUTH>
__global__ __launch_bounds__(256, 2) void hgemm(
    const __half* __restrict__ A, const __half* __restrict__ Bm,
    void* __restrict__ Cv, const float* __restrict__ bias,
    const float* __restrict__ pb, __half* __restrict__ qcp, __half* __restrict__ qpp,
    int K, int lda, int ldb, int ldc, int zdiv,
    long long As1, long long As2, long long Bs1, long long Bs2,
    long long Cs1, long long Cs2, int relu, float scale)
{
    constexpr int BM = 128;
    constexpr int MW = BM / WRM, NW = BN / WRN;
    constexpr int MT = MW / 16, NPAIR = NW / 16, NT = NW / 8;
    extern __shared__ __half hsm[];
    __half* sA = hsm;                       // [3][BM*LDSG]
    __half* sB = hsm + 3 * BM * LDSG;       // [3][BN*LDSG]

    const int bm = blockIdx.y * BM, bn = blockIdx.x * BN;
    {
        int z = blockIdx.z, zq = z / zdiv, zr = z % zdiv;
        A  += zq * As1 + zr * As2;
        Bm += zq * Bs1 + zr * Bs2;
    }
    const int tid = threadIdx.x, lane = tid & 31, wid = tid >> 5;
    const int wm = (wid / WRN) * MW, wn = (wid % WRN) * NW;

    float cf[MT][NT][4];
#pragma unroll
    for (int i = 0; i < MT; i++)
#pragma unroll
        for (int j = 0; j < NT; j++)
#pragma unroll
            for (int e = 0; e < 4; e++) cf[i][j][e] = 0.f;

    // one chunk = 64 K-columns = 128B per row = 8 x 16B copies per row
    auto stage = [&](int c, int sx) {
        __half* dA = sA + sx * BM * LDSG;
        __half* dB = sB + sx * BN * LDSG;
#pragma unroll
        for (int i = 0; i < BM * 8 / 256; i++) {          // 4
            int id = tid + i * 256, row = id >> 3, ch = id & 7;
            cpasync16(smem_u32(dA + row * LDSG + ch * 8),
                      A + (long long)(bm + row) * lda + c * 64 + ch * 8);
        }
#pragma unroll
        for (int i = 0; i < BN * 8 / 256; i++) {          // 4 (BN=128)
            int id = tid + i * 256, row = id >> 3, ch = id & 7;
            cpasync16(smem_u32(dB + row * LDSG + ch * 8),
                      Bm + (long long)(bn + row) * ldb + c * 64 + ch * 8);
        }
        CP_COMMIT();
    };

    const int nkt = K >> 6;
    stage(0, 0);
    stage(1, 1);
    int cbuf = 0, pbuf = 2;
    for (int c = 0; c < nkt; c++) {
        CP_WAIT(1);                      // chunk c resident
        __syncthreads();                 // all warps finished chunk c-1's buffer
        if (c + 2 < nkt) stage(c + 2, pbuf);
        else CP_COMMIT();
        const uint32_t a0 = smem_u32(sA + cbuf * BM * LDSG);
        const uint32_t b0 = smem_u32(sB + cbuf * BN * LDSG);
#pragma unroll
        for (int ks = 0; ks < 4; ks++) {
            uint32_t af[MT][4], bf[NT][2];
#pragma unroll
            for (int mt = 0; mt < MT; mt++) {
                uint32_t ad = a0 + ((wm + mt * 16 + (lane & 15)) * LDSG
                                    + ks * 16 + (lane >> 4) * 8) * 2;
                LDM4(af[mt][0], af[mt][1], af[mt][2], af[mt][3], ad);
            }
#pragma unroll
            for (int p = 0; p < NPAIR; p++) {
                int rn = wn + p * 16 + (lane & 7) + ((lane >> 4) << 3);
                uint32_t bd = b0 + (rn * LDSG + ks * 16 + ((lane >> 3) & 1) * 8) * 2;
                uint32_t r0, r1, r2, r3;
                LDM4(r0, r1, r2, r3, bd);
                bf[2 * p][0] = r0; bf[2 * p][1] = r1;
                bf[2 * p + 1][0] = r2; bf[2 * p + 1][1] = r3;
            }
#pragma unroll
            for (int mt = 0; mt < MT; mt++)
#pragma unroll
                for (int nt = 0; nt < NT; nt++)
                    MMA16816(cf[mt][nt], af[mt], bf[nt]);
        }
        cbuf = cbuf == 2 ? 0 : cbuf + 1;
        pbuf = pbuf == 2 ? 0 : pbuf + 1;
    }

    long long coff;
    {
        int z = blockIdx.z, zq = z / zdiv, zr = z % zdiv;
        coff = zq * Cs1 + zr * Cs2;
    }
#pragma unroll
    for (int mt = 0; mt < MT; mt++) {
#pragma unroll
        for (int nt = 0; nt < NT; nt++) {
            int r = bm + wm + mt * 16 + (lane >> 2);
            int col = bn + wn + nt * 8 + (lane & 3) * 2;
#pragma unroll
            for (int e2 = 0; e2 < 2; e2++) {
                int row = r + 8 * e2;
                float v0 = cf[mt][nt][e2 * 2] * scale;
                float v1 = cf[mt][nt][e2 * 2 + 1] * scale;
                if (EPI == 2) {
                    if (col < NH_) {
                        float c0 = bias[col], c1 = bias[col + 1];
                        float p0 = pb[col],  p1 = pb[col + 1];
                        *(__half2*)(qcp + (long long)row * NH_ + col) =
                            __floats2half2_rn((v0 + c0) * 0.125f, (v1 + c1) * 0.125f);
                        *(__half2*)(qpp + (long long)row * NH_ + col) =
                            __floats2half2_rn((v0 + p0) * 0.125f, (v1 + p1) * 0.125f);
                    } else {
                        __half* Ch = (__half*)Cv;
                        *(__half2*)(Ch + (long long)row * ldc + col) =
                            __floats2half2_rn(v0, v1);
                    }
                } else {
                    if (bias) { v0 += bias[col]; v1 += bias[col + 1]; }
                    if (relu) { v0 = fmaxf(v0, 0.f); v1 = fmaxf(v1, 0.f); }
                    if (OUTH) {
                        __half* Ch = (__half*)Cv + coff;
                        *(__half2*)(Ch + (long long)row * ldc + col) =
                            __floats2half2_rn(v0, v1);
                    } else {
                        float* Cf = (float*)Cv + coff;
                        *(float2*)(Cf + (long long)row * ldc + col) = make_float2(v0, v1);
                    }
                }
            }
        }
    }
}

// ---------------- flash attention with folded rel-shift + band tile-skip --------
#define LDQ_  72
#define LDV_  136
#define LDS_S 132
#define LDP_  136
#define FL_SMEM (3*128*LDQ_*2 + 64*LDV_*2 + 256*LDQ_*2 + 128*LDS_S*4 + 128*LDP_*2 + 3*128*4)

__global__ __launch_bounds__(256, 1) void flash_k(
    const __half* __restrict__ qc, const __half* __restrict__ qp,
    const __half* __restrict__ kk, const __half* __restrict__ vt,
    const __half* __restrict__ rr, __half* __restrict__ attn, int kstr)
{
    extern __shared__ char smraw[];
    __half* sQc = (__half*)smraw;
    __half* sQp = sQc + 128 * LDQ_;
    __half* sK  = sQp + 128 * LDQ_;
    __half* sV  = sK  + 128 * LDQ_;
    __half* sR  = sV  + 64 * LDV_;
    float*  sS  = (float*)(sR + 256 * LDQ_);
    __half* sP  = (__half*)(sS + 128 * LDS_S);
    float*  sM  = (float*)(sP + 128 * LDP_);
    float*  sL  = sM + 128;
    float*  sAl = sL + 128;

    const int it = blockIdx.x, z = blockIdx.y;
    const int b = z >> 4, n = z & 15;
    const int i0 = it * 128;
    const int tid = threadIdx.x, lane = tid & 31, wid = tid >> 5;
    const int wm = wid * 16;

    int ntlo0 = (105 - wm + 7) >> 3; if (ntlo0 < 0) ntlo0 = 0;
    int nthi1 = (126 - wm) >> 3;

    const __half* qcb = qc + (long long)b * S_ * NH_ + n * H_;
    const __half* qpb = qp + (long long)b * S_ * NH_ + n * H_;
    const __half* kb  = kk + (long long)b * S_ * kstr + n * H_;
    const __half* vtb = vt + (long long)z * H_ * S_;
    const __half* rb  = rr + (long long)b * R_ * NH_ + n * H_;

#pragma unroll
    for (int i = 0; i < 4; i++) {
        int id = tid + i * 256, row = id >> 3, ch = id & 7;
        cpasync16(smem_u32(sQc + row * LDQ_ + ch * 8),
                  qcb + (long long)(i0 + row) * NH_ + ch * 8);
        cpasync16(smem_u32(sQp + row * LDQ_ + ch * 8),
                  qpb + (long long)(i0 + row) * NH_ + ch * 8);
    }
    CP_COMMIT();
    if (tid < 128) { sM[tid] = -1e30f; sL[tid] = 0.f; }
    CP_WAIT(0);
    __syncthreads();

    float of[8][4];
#pragma unroll
    for (int nt = 0; nt < 8; nt++)
#pragma unroll
        for (int e = 0; e < 4; e++) of[nt][e] = 0.f;

    const uint32_t aQc = smem_u32(sQc), aQp = smem_u32(sQp);
    const uint32_t aK = smem_u32(sK), aV = smem_u32(sV);
    const uint32_t aR = smem_u32(sR), aP = smem_u32(sP);

    for (int jt = 0; jt < 8; jt++) {
        const int j0 = jt * 128;
        const int base = S_ + j0 - i0 - 127;

#pragma unroll
        for (int i = 0; i < 4; i++) {
            int id = tid + i * 256, row = id >> 3, ch = id & 7;
            cpasync16(smem_u32(sK + row * LDQ_ + ch * 8),
                      kb + (long long)(j0 + row) * kstr + ch * 8);
        }
        CP_COMMIT();
#pragma unroll
        for (int i = 0; i < 4; i++) {
            int id = tid + i * 256, row = id >> 4, ch = id & 15;
            cpasync16(smem_u32(sV + row * LDV_ + ch * 8),
                      vtb + (long long)row * S_ + j0 + ch * 8);
        }
#pragma unroll
        for (int i = 0; i < 8; i++) {
            int id = tid + i * 256, row = id >> 3, ch = id & 7;
            int grow = base + row; grow = grow < R_ ? grow : R_ - 1;
            cpasync16(smem_u32(sR + row * LDQ_ + ch * 8),
                      rb + (long long)grow * NH_ + ch * 8);
        }
        CP_COMMIT();
        CP_WAIT(1);
        __syncthreads();

        // ---- content scores -> sS ----
        float cf[16][4];
#pragma unroll
        for (int nt = 0; nt < 16; nt++)
#pragma unroll
            for (int e = 0; e < 4; e++) cf[nt][e] = 0.f;
#pragma unroll
        for (int ks = 0; ks < 4; ks++) {
            uint32_t af[4], bf[16][2];
            LDM4(af[0], af[1], af[2], af[3],
                 aQc + ((wm + (lane & 15)) * LDQ_ + ks * 16 + (lane >> 4) * 8) * 2);
#pragma unroll
            for (int p = 0; p < 8; p++) {
                int rn = p * 16 + (lane & 7) + ((lane >> 4) << 3);
                uint32_t r0, r1, r2, r3;
                LDM4(r0, r1, r2, r3, aK + (rn * LDQ_ + ks * 16 + ((lane >> 3) & 1) * 8) * 2);
                bf[2 * p][0] = r0; bf[2 * p][1] = r1;
                bf[2 * p + 1][0] = r2; bf[2 * p + 1][1] = r3;
            }
#pragma unroll
            for (int nt = 0; nt < 16; nt++) MMA16816(cf[nt], af, bf[nt]);
        }
#pragma unroll
        for (int nt = 0; nt < 16; nt++) {
            int c0 = nt * 8 + (lane & 3) * 2;
#pragma unroll
            for (int e2 = 0; e2 < 2; e2++) {
                int row = wm + (lane >> 2) + 8 * e2;
                *(float2*)&sS[row * LDS_S + c0] = make_float2(cf[nt][e2 * 2], cf[nt][e2 * 2 + 1]);
            }
        }
        CP_WAIT(0);
        __syncthreads();

        // ---- position scores, band tiles only ----
#pragma unroll
        for (int halfg = 0; halfg < 2; halfg++) {
            int g0 = halfg * 128;
            int lo = halfg == 0 ? ntlo0 : 0;
            int hi = halfg == 0 ? 15 : nthi1;
#pragma unroll
            for (int nt = 0; nt < 16; nt++)
#pragma unroll
                for (int e = 0; e < 4; e++) cf[nt][e] = 0.f;
#pragma unroll
            for (int ks = 0; ks < 4; ks++) {
                uint32_t af[4], bf[16][2];
                LDM4(af[0], af[1], af[2], af[3],
                     aQp + ((wm + (lane & 15)) * LDQ_ + ks * 16 + (lane >> 4) * 8) * 2);
#pragma unroll
                for (int p = 0; p < 8; p++) {
                    if (2 * p + 1 < lo || 2 * p > hi) continue;
                    int rn = g0 + p * 16 + (lane & 7) + ((lane >> 4) << 3);
                    uint32_t r0, r1, r2, r3;
                    LDM4(r0, r1, r2, r3, aR + (rn * LDQ_ + ks * 16 + ((lane >> 3) & 1) * 8) * 2);
                    bf[2 * p][0] = r0; bf[2 * p][1] = r1;
                    bf[2 * p + 1][0] = r2; bf[2 * p + 1][1] = r3;
                }
#pragma unroll
                for (int nt = 0; nt < 16; nt++) {
                    if (nt < lo || nt > hi) continue;
                    MMA16816(cf[nt], af, bf[nt]);
                }
            }
#pragma unroll
            for (int nt = 0; nt < 16; nt++) {
                if (nt < lo || nt > hi) continue;
#pragma unroll
                for (int e = 0; e < 4; e++) {
                    int li = wm + (lane >> 2) + 8 * (e >> 1);
                    int g  = g0 + nt * 8 + (lane & 3) * 2 + (e & 1);
                    int lj = g - 127 + li;
                    if (lj >= 0 && lj < 128) sS[li * LDS_S + lj] += cf[nt][e];
                }
            }
            __syncwarp();
        }

        // ---- online softmax (scores pre-scaled by 1/8 via qc/qp) ----
        {
            int rloc = wm + (lane >> 1), hf = lane & 1;
            float* srow = &sS[rloc * LDS_S + hf * 64];
            float mx = -1e30f;
#pragma unroll
            for (int c = 0; c < 64; c++) mx = fmaxf(mx, srow[c]);
            mx = fmaxf(mx, __shfl_xor_sync(0xffffffffu, mx, 1));
            float mold = sM[rloc];
            float mnew = fmaxf(mold, mx);
            float alpha = __expf(mold - mnew);
            float sum = 0.f;
            __half* prow = &sP[rloc * LDP_ + hf * 64];
#pragma unroll
            for (int c = 0; c < 64; c += 2) {
                float p0 = __expf(srow[c] - mnew);
                float p1 = __expf(srow[c + 1] - mnew);
                sum += p0 + p1;
                *(__half2*)&prow[c] = __floats2half2_rn(p0, p1);
            }
            sum += __shfl_xor_sync(0xffffffffu, sum, 1);
            if (hf == 0) {
                sL[rloc] = sL[rloc] * alpha + sum;
                sM[rloc] = mnew;
                sAl[rloc] = alpha;
            }
        }
        __syncwarp();

        // ---- rescale O, PV mma ----
#pragma unroll
        for (int e2 = 0; e2 < 2; e2++) {
            float al = sAl[wm + (lane >> 2) + 8 * e2];
#pragma unroll
            for (int nt = 0; nt < 8; nt++) {
                of[nt][e2 * 2]     *= al;
                of[nt][e2 * 2 + 1] *= al;
            }
        }
#pragma unroll
        for (int ks = 0; ks < 8; ks++) {
            uint32_t af[4], bfv[8][2];
            LDM4(af[0], af[1], af[2], af[3],
                 aP + ((wm + (lane & 15)) * LDP_ + ks * 16 + (lane >> 4) * 8) * 2);
#pragma unroll
            for (int p = 0; p < 4; p++) {
                int rn = p * 16 + (lane & 7) + ((lane >> 4) << 3);
                uint32_t r0, r1, r2, r3;
                LDM4(r0, r1, r2, r3, aV + (rn * LDV_ + ks * 16 + ((lane >> 3) & 1) * 8) * 2);
                bfv[2 * p][0] = r0; bfv[2 * p][1] = r1;
                bfv[2 * p + 1][0] = r2; bfv[2 * p + 1][1] = r3;
            }
#pragma unroll
            for (int nt = 0; nt < 8; nt++) MMA16816(of[nt], af, bfv[nt]);
        }
        __syncthreads();
    }

#pragma unroll
    for (int e2 = 0; e2 < 2; e2++) {
        int li = wm + (lane >> 2) + 8 * e2;
        float inv = 1.0f / sL[li];
        long long rowg = (long long)(b * S_ + i0 + li) * NH_ + n * H_;
#pragma unroll
        for (int nt = 0; nt < 8; nt++) {
            int col = nt * 8 + (lane & 3) * 2;
            *(__half2*)(attn + rowg + col) =
                __floats2half2_rn(of[nt][e2 * 2] * inv, of[nt][e2 * 2 + 1] * inv);
        }
    }
}

// ---------------- fp32 -> fp16 copy ----------------
__global__ __launch_bounds__(256) void f2h_k(const float* __restrict__ in,
                                             __half* __restrict__ out)
{
    long long i = (long long)blockIdx.x * 256 + threadIdx.x;
    float4 v = ((const float4*)in)[i];
    ((__half2*)out)[i * 2]     = __floats2half2_rn(v.x, v.y);
    ((__half2*)out)[i * 2 + 1] = __floats2half2_rn(v.z, v.w);
}

// ---------------- fp32 transpose -> fp16 ----------------
__global__ void transpose_h16(const float* __restrict__ in, __half* __restrict__ out,
                              int rows, int cols)
{
    __shared__ float tile[32][33];
    int r0 = blockIdx.y * 32, c0 = blockIdx.x * 32;
    int tx = threadIdx.x, ty = threadIdx.y;
#pragma unroll
    for (int i = 0; i < 4; i++)
        tile[ty + i * 8][tx] = in[(long long)(r0 + ty + i * 8) * cols + c0 + tx];
    __syncthreads();
#pragma unroll
    for (int i = 0; i < 4; i++)
        out[(long long)(c0 + ty + i * 8) * rows + r0 + tx] = __float2half_rn(tile[tx][ty + i * 8]);
}

// ---------------- per-head half transpose ----------------
__global__ void transpose_vh(const __half* __restrict__ in, __half* __restrict__ out,
                             int rows, int instr)
{
    __shared__ __half tile[32][34];
    int z = blockIdx.z, b = z >> 4, n = z & 15;
    const __half* ip = in + (long long)b * rows * instr + n * H_;
    __half* op = out + (long long)z * H_ * rows;
    int r0 = blockIdx.x * 32, h0 = blockIdx.y * 32;
    int tx = threadIdx.x, ty = threadIdx.y;
#pragma unroll
    for (int i = 0; i < 4; i++)
        tile[ty + i * 8][tx] = ip[(long long)(r0 + ty + i * 8) * instr + h0 + tx];
    __syncthreads();
#pragma unroll
    for (int i = 0; i < 4; i++)
        op[(long long)(h0 + ty + i * 8) * rows + r0 + tx] = tile[tx][ty + i * 8];
}

// ---------------- residual + LayerNorm (optional fp16 copy) ---------------------
__global__ __launch_bounds__(256) void ln_k(
    const float* __restrict__ a, const float* __restrict__ res,
    const float* __restrict__ g, const float* __restrict__ bt,
    float* __restrict__ o, __half* __restrict__ oh)
{
    __shared__ float red[16];
    long long row = blockIdx.x;
    int t = threadIdx.x;
    float4 va = *((const float4*)(a + row * 1024) + t);
    float4 vr = *((const float4*)(res + row * 1024) + t);
    float4 x;
    x.x = va.x + vr.x; x.y = va.y + vr.y; x.z = va.z + vr.z; x.w = va.w + vr.w;
    float s  = x.x + x.y + x.z + x.w;
    float q2 = x.x * x.x + x.y * x.y + x.z * x.z + x.w * x.w;
#pragma unroll
    for (int off = 16; off; off >>= 1) {
        s  += __shfl_xor_sync(0xffffffffu, s, off);
        q2 += __shfl_xor_sync(0xffffffffu, q2, off);
    }
    if ((t & 31) == 0) { red[t >> 5] = s; red[8 + (t >> 5)] = q2; }
    __syncthreads();
    if (t == 0) {
        float ss = red[0], qq = red[8];
#pragma unroll
        for (int i = 1; i < 8; i++) { ss += red[i]; qq += red[8 + i]; }
        red[0] = ss; red[8] = qq;
    }
    __syncthreads();
    float mu  = red[0] * (1.f / 1024.f);
    float var = red[8] * (1.f / 1024.f) - mu * mu;
    float rs = rsqrtf(var + 1e-12f);
    float4 gg = *((const float4*)g + t);
    float4 bb = *((const float4*)bt + t);
    float4 y;
    y.x = (x.x - mu) * rs * gg.x + bb.x;
    y.y = (x.y - mu) * rs * gg.y + bb.y;
    y.z = (x.z - mu) * rs * gg.z + bb.z;
    y.w = (x.w - mu) * rs * gg.w + bb.w;
    *((float4*)(o + row * 1024) + t) = y;
    if (oh) {
        __half2* ph = (__half2*)(oh + row * 1024);
        ph[2 * t]     = __floats2half2_rn(y.x, y.y);
        ph[2 * t + 1] = __floats2half2_rn(y.z, y.w);
    }
}

// ---------------- driver --------------------------------------------------------
extern "C" void kernel_launch(void* const* d_in, const int* in_sizes, int n_in,
                              void* d_out, int out_size)
{
    const float* x    = (const float*)d_in[0];
    const float* cb   = (const float*)d_in[1];
    const float* pb   = (const float*)d_in[2];
    const float* rpe  = (const float*)d_in[3];
    const float* Wq   = (const float*)d_in[4];
    const float* Wk   = (const float*)d_in[5];
    const float* Wv   = (const float*)d_in[6];
    const float* Wr   = (const float*)d_in[7];
    const float* Wo   = (const float*)d_in[8];
    const float* ln1g = (const float*)d_in[9];
    const float* ln1b = (const float*)d_in[10];
    const float* Wi   = (const float*)d_in[11];
    const float* bi   = (const float*)d_in[12];
    const float* Wout = (const float*)d_in[13];
    const float* bout = (const float*)d_in[14];
    const float* ln2g = (const float*)d_in[15];
    const float* ln2b = (const float*)d_in[16];
    float* out = (float*)d_out;

    __half *xh,*rpeh,*qkv,*qc,*qp,*r,*vt,*attn,*h1h,*inner;
    __half *WqkvT,*WrT,*WoT,*WiT,*WoutT;
    float *h1,*tmp;
    cudaGetSymbolAddress((void**)&xh, g_xh);      cudaGetSymbolAddress((void**)&rpeh, g_rpeh);
    cudaGetSymbolAddress((void**)&qkv, g_qkv);    cudaGetSymbolAddress((void**)&qc, g_qc);
    cudaGetSymbolAddress((void**)&qp, g_qp);      cudaGetSymbolAddress((void**)&r, g_r);
    cudaGetSymbolAddress((void**)&vt, g_vt);      cudaGetSymbolAddress((void**)&attn, g_attn);
    cudaGetSymbolAddress((void**)&h1, g_h1);      cudaGetSymbolAddress((void**)&h1h, g_h1h);
    cudaGetSymbolAddress((void**)&inner, g_inner);cudaGetSymbolAddress((void**)&tmp, g_tmp);
    cudaGetSymbolAddress((void**)&WqkvT, g_WqkvT);cudaGetSymbolAddress((void**)&WrT, g_WrT);
    cudaGetSymbolAddress((void**)&WoT, g_WoT);    cudaGetSymbolAddress((void**)&WiT, g_WiT);
    cudaGetSymbolAddress((void**)&WoutT, g_WoutT);

    cudaFuncSetAttribute((const void*)hgemm<128,2,4,0,1>,
                         cudaFuncAttributeMaxDynamicSharedMemorySize, HG_SMEM);
    cudaFuncSetAttribute((const void*)hgemm<128,2,4,0,0>,
                         cudaFuncAttributeMaxDynamicSharedMemorySize, HG_SMEM);
    cudaFuncSetAttribute((const void*)hgemm<128,2,4,2,1>,
                         cudaFuncAttributeMaxDynamicSharedMemorySize, HG_SMEM);
    cudaFuncSetAttribute(flash_k, cudaFuncAttributeMaxDynamicSharedMemorySize, FL_SMEM);

    static cudaStream_t s1 = nullptr, s2 = nullptr, s3 = nullptr;
    static cudaEvent_t  eF = nullptr, e1 = nullptr, e2 = nullptr, e3 = nullptr;
    if (s1 == nullptr) {
        cudaStreamCreateWithFlags(&s1, cudaStreamNonBlocking);
        cudaStreamCreateWithFlags(&s2, cudaStreamNonBlocking);
        cudaStreamCreateWithFlags(&s3, cudaStreamNonBlocking);
        cudaEventCreateWithFlags(&eF, cudaEventDisableTiming);
        cudaEventCreateWithFlags(&e1, cudaEventDisableTiming);
        cudaEventCreateWithFlags(&e2, cudaEventDisableTiming);
        cudaEventCreateWithFlags(&e3, cudaEventDisableTiming);
    }

    const int M = B_ * S_;
    dim3 blk(256);
    const long long Z0 = 0;

    // ---- fork ----
    cudaEventRecord(eF, 0);
    cudaStreamWaitEvent(s1, eF, 0);
    cudaStreamWaitEvent(s2, eF, 0);
    cudaStreamWaitEvent(s3, eF, 0);

    f2h_k<<<M * E_ / 1024, blk>>>(x, xh);

    transpose_h16<<<dim3(32, 32), dim3(32, 8), 0, s1>>>(Wq, WqkvT,               E_, NH_);
    transpose_h16<<<dim3(32, 32), dim3(32, 8), 0, s1>>>(Wk, WqkvT + 1024 * 1024, E_, NH_);
    transpose_h16<<<dim3(32, 32), dim3(32, 8), 0, s1>>>(Wv, WqkvT + 2048 * 1024, E_, NH_);
    cudaEventRecord(e1, s1);

    f2h_k<<<B_ * R_ * E_ / 1024, blk, 0, s2>>>(rpe, rpeh);
    transpose_h16<<<dim3(32, 32), dim3(32, 8), 0, s2>>>(Wr, WrT, E_, NH_);
    hgemm<128,2,4,0,1><<<dim3(8,64,1), blk, HG_SMEM, s2>>>(
        rpeh, WrT, r, nullptr, nullptr, nullptr, nullptr, E_, E_, E_, NH_,
        1, Z0,Z0,Z0,Z0,Z0,Z0, 0, 1.f);
    cudaEventRecord(e2, s2);

    transpose_h16<<<dim3(32, 32),  dim3(32, 8), 0, s3>>>(Wo,   WoT,   NH_, E_);
    transpose_h16<<<dim3(128, 32), dim3(32, 8), 0, s3>>>(Wi,   WiT,   E_, F_);
    transpose_h16<<<dim3(32, 128), dim3(32, 8), 0, s3>>>(Wout, WoutT, F_, E_);
    cudaEventRecord(e3, s3);

    cudaStreamWaitEvent(0, e1, 0);
    hgemm<128,2,4,2,1><<<dim3(24,32,1), blk, HG_SMEM>>>(
        xh, WqkvT, qkv, cb, pb, qc, qp, E_, E_, E_, 3*NH_,
        1, Z0,Z0,Z0,Z0,Z0,Z0, 0, 1.f);
    transpose_vh<<<dim3(S_/32, 2, B_*NHEADS), dim3(32,8)>>>(qkv + 2*NH_, vt, S_, 3*NH_);

    cudaStreamWaitEvent(0, e2, 0);
    flash_k<<<dim3(8, B_ * NHEADS), blk, FL_SMEM>>>(qc, qp, qkv + NH_, vt, r, attn, 3*NH_);

    cudaStreamWaitEvent(0, e3, 0);
    hgemm<128,2,4,0,0><<<dim3(8,32,1), blk, HG_SMEM>>>(
        attn, WoT, tmp, nullptr, nullptr, nullptr, nullptr, NH_, NH_, NH_, E_,
        1, Z0,Z0,Z0,Z0,Z0,Z0, 0, 1.f);
    ln_k<<<M, 256>>>(tmp, x, ln1g, ln1b, h1, h1h);

    hgemm<128,2,4,0,1><<<dim3(32,32,1), blk, HG_SMEM>>>(
        h1h, WiT, inner, bi, nullptr, nullptr, nullptr, E_, E_, E_, F_,
        1, Z0,Z0,Z0,Z0,Z0,Z0, 1, 1.f);
    hgemm<128,2,4,0,0><<<dim3(8,32,1), blk, HG_SMEM>>>(
        inner, WoutT, tmp, bout, nullptr, nullptr, nullptr, F_, F_, F_, E_,
        1, Z0,Z0,Z0,Z0,Z0,Z0, 0, 1.f);
    ln_k<<<M, 256>>>(tmp, h1, ln2g, ln2b, out, nullptr);
}